// round 5
// baseline (speedup 1.0000x reference)
#include <cuda_runtime.h>
#include <cuda_bf16.h>
#include <math.h>
#include <stdint.h>

#define NB 8
#define NT 8192
#define ND 128
#define NH 8
#define TILE 128
#define NTILES 64              // NT / TILE
#define NGRP 4                 // partial groups per block

// ---------------- scratch (device globals; no allocs allowed) ---------------
static __device__ float g_q[NB * NT * ND];                  // rope+elu'd q
static __device__ float g_part[NB * NTILES * NGRP * 2048];  // ctx partials
static __device__ float g_partk[NB * NTILES * NGRP * 128];  // ksum partials
static __device__ float g_ctx[NB * 2048];                   // [b][h][d][e]
static __device__ float g_ksum[NB * 128];                   // [b][h*16+d]

// ---------------------------------------------------------------------------
__device__ __forceinline__ void mma16816(float c[4], const uint32_t a[4],
                                         uint32_t b0, uint32_t b1) {
    asm volatile(
        "mma.sync.aligned.m16n8k16.row.col.f32.bf16.bf16.f32 "
        "{%0,%1,%2,%3}, {%4,%5,%6,%7}, {%8,%9}, {%0,%1,%2,%3};"
        : "+f"(c[0]), "+f"(c[1]), "+f"(c[2]), "+f"(c[3])
        : "r"(a[0]), "r"(a[1]), "r"(a[2]), "r"(a[3]), "r"(b0), "r"(b1));
}
__device__ __forceinline__ void ldsm4(uint32_t r[4], uint32_t addr) {
    asm volatile("ldmatrix.sync.aligned.m8n8.x4.shared.b16 {%0,%1,%2,%3}, [%4];"
                 : "=r"(r[0]), "=r"(r[1]), "=r"(r[2]), "=r"(r[3]) : "r"(addr));
}
__device__ __forceinline__ uint32_t smem_u32(const void* p) {
    return (uint32_t)__cvta_generic_to_shared(p);
}

// bf16 tile layout (A and W identical): [128 rows][128 bf16 = 256B], 16B-granule
// XOR swizzle: phys = row*256 + (((k>>3) ^ (row&7))<<4) + (k&7)*2.

__device__ __forceinline__ void a_store4(char* hi, char* lo, int row, int k4, float4 v) {
    uint32_t off = (uint32_t)(row * 256 + ((((k4 >> 1) ^ (row & 7)) << 4) | ((k4 & 1) << 3)));
    __nv_bfloat16 h0 = __float2bfloat16(v.x), h1 = __float2bfloat16(v.y);
    __nv_bfloat16 h2 = __float2bfloat16(v.z), h3 = __float2bfloat16(v.w);
    *(__nv_bfloat162*)(hi + off)     = __halves2bfloat162(h0, h1);
    *(__nv_bfloat162*)(hi + off + 4) = __halves2bfloat162(h2, h3);
    __nv_bfloat16 l0 = __float2bfloat16(v.x - __bfloat162float(h0));
    __nv_bfloat16 l1 = __float2bfloat16(v.y - __bfloat162float(h1));
    __nv_bfloat16 l2 = __float2bfloat16(v.z - __bfloat162float(h2));
    __nv_bfloat16 l3 = __float2bfloat16(v.w - __bfloat162float(h3));
    *(__nv_bfloat162*)(lo + off)     = __halves2bfloat162(l0, l1);
    *(__nv_bfloat162*)(lo + off + 4) = __halves2bfloat162(l2, l3);
}

// Convert W fp32 [k][n] row-major -> Wt_hi / Wt_lo [n][k] bf16 swizzled.
__device__ __forceinline__ void convert_w2(const float* __restrict__ W,
                                           char* wh, char* wl, int tid, int nthr) {
    const float4* Wp = (const float4*)W;
    for (int i = tid; i < 4096; i += nthr) {
        int k = i >> 5, n4 = i & 31;
        float4 w = Wp[i];
        float vv[4] = {w.x, w.y, w.z, w.w};
        #pragma unroll
        for (int u = 0; u < 4; u++) {
            int n = n4 * 4 + u;
            uint32_t off = (uint32_t)(n * 256 + ((((k >> 3) ^ (n & 7)) << 4) | ((k & 7) * 2)));
            __nv_bfloat16 bh = __float2bfloat16(vv[u]);
            __nv_bfloat16 bl = __float2bfloat16(vv[u] - __bfloat162float(bh));
            *(__nv_bfloat16*)(wh + off) = bh;
            *(__nv_bfloat16*)(wl + off) = bl;
        }
    }
}

// Fused 3-product GEMM via ldmatrix: acc = Ah@Wh + Al@Wh + Ah@Wl.
// Warp tile 32x32: mt in 0..1 (m16), nt in 0..3 (n8).
__device__ __forceinline__ void gemm3(uint32_t aHi, uint32_t aLo,
                                      uint32_t wH, uint32_t wL,
                                      float acc[2][4][4],
                                      int r0, int c0, int lane) {
    #pragma unroll
    for (int mt = 0; mt < 2; mt++)
        #pragma unroll
        for (int nt = 0; nt < 4; nt++)
            #pragma unroll
            for (int i = 0; i < 4; i++) acc[mt][nt][i] = 0.f;

    const int l7 = lane & 7;
    const int am8 = ((lane >> 3) & 1) << 3;   // A: lanes 8-15/24-31 -> rows +8
    const int akh = lane >> 4;                // A: lanes 16-31 -> odd k-granule
    const int bm8 = ((lane >> 4) & 1) << 3;   // B: lanes 16-31 -> rows +8
    const int bpar = (lane >> 3) & 1;         // B: lanes 8-15/24-31 -> odd granule
    uint32_t arow[2], brow[2];
    int arow7[2], brow7[2];
    #pragma unroll
    for (int mt = 0; mt < 2; mt++) {
        int r = r0 + mt * 16 + am8 + l7;
        arow[mt] = (uint32_t)(r * 256); arow7[mt] = r & 7;
    }
    #pragma unroll
    for (int n2 = 0; n2 < 2; n2++) {
        int r = c0 + n2 * 16 + bm8 + l7;
        brow[n2] = (uint32_t)(r * 256); brow7[n2] = r & 7;
    }

    #pragma unroll
    for (int ks = 0; ks < 8; ks++) {
        uint32_t Ah[2][4], Al[2][4], Bh[2][4], Bl[2][4];
        #pragma unroll
        for (int mt = 0; mt < 2; mt++) {
            uint32_t g = (uint32_t)(((2 * ks + akh) ^ arow7[mt]) << 4);
            ldsm4(Ah[mt], aHi + arow[mt] + g);
            ldsm4(Al[mt], aLo + arow[mt] + g);
        }
        #pragma unroll
        for (int n2 = 0; n2 < 2; n2++) {
            uint32_t g = (uint32_t)(((2 * ks + bpar) ^ brow7[n2]) << 4);
            ldsm4(Bh[n2], wH + brow[n2] + g);
            ldsm4(Bl[n2], wL + brow[n2] + g);
        }
        #pragma unroll
        for (int n2 = 0; n2 < 2; n2++)
            #pragma unroll
            for (int j = 0; j < 2; j++) {
                int nt = n2 * 2 + j;
                uint32_t bh0 = Bh[n2][j * 2], bh1 = Bh[n2][j * 2 + 1];
                uint32_t bl0 = Bl[n2][j * 2], bl1 = Bl[n2][j * 2 + 1];
                #pragma unroll
                for (int mt = 0; mt < 2; mt++) {
                    mma16816(acc[mt][nt], Ah[mt], bh0, bh1);
                    mma16816(acc[mt][nt], Al[mt], bh0, bh1);
                    mma16816(acc[mt][nt], Ah[mt], bl0, bl1);
                }
            }
    }
}

// bias + RoPE + elu+1 on accumulators (warp covers cols c0..c0+31 = 2 heads).
__device__ __forceinline__ void rope_elu_acc(float acc[2][4][4],
                                             const float* bias_s, int c0, int tg,
                                             const float sn[4][2], const float cs[4][2]) {
    #pragma unroll
    for (int mt = 0; mt < 2; mt++)
        #pragma unroll
        for (int t = 0; t < 2; t++)
            #pragma unroll
            for (int i = 0; i < 4; i++) {
                int ridx = mt * 2 + (i >> 1);
                int jj = i & 1;
                float x1 = acc[mt][2 * t][i]     + bias_s[c0 + t * 16 + tg * 2 + jj];
                float x2 = acc[mt][2 * t + 1][i] + bias_s[c0 + t * 16 + 8 + tg * 2 + jj];
                float s = sn[ridx][jj], c = cs[ridx][jj];
                float y1 = x1 * c - x2 * s;
                float y2 = x1 * s + x2 * c;
                acc[mt][2 * t][i]     = y1 > 0.f ? y1 + 1.f : __expf(y1);
                acc[mt][2 * t + 1][i] = y2 > 0.f ? y2 + 1.f : __expf(y2);
            }
}

// Store accumulators to fp32 smem tile [128][128], float4-block XOR swizzle.
__device__ __forceinline__ void acc_store(float* dst, const float acc[2][4][4],
                                          const float* bias_s, bool add_bias,
                                          int r0, int c0, int qid, int tg) {
    #pragma unroll
    for (int mt = 0; mt < 2; mt++)
        #pragma unroll
        for (int nt = 0; nt < 4; nt++)
            #pragma unroll
            for (int h2 = 0; h2 < 2; h2++) {
                int row = r0 + mt * 16 + h2 * 8 + qid;
                int col = c0 + nt * 8 + tg * 2;
                float v0 = acc[mt][nt][h2 * 2];
                float v1 = acc[mt][nt][h2 * 2 + 1];
                if (add_bias) { v0 += bias_s[col]; v1 += bias_s[col + 1]; }
                float* p = dst + row * 128 + (((col >> 2) ^ (row & 7)) << 2) + (col & 3);
                p[0] = v0; p[1] = v1;
            }
}

__device__ __forceinline__ void make_rope_tables(int t0, int r0, int qid, int tg,
                                                 float sn[4][2], float cs[4][2]) {
    const float invf[8] = {1.0f, 0.31622776601683794f, 0.1f, 0.03162277660168379f,
                           0.01f, 0.0031622776601683794f, 0.001f, 0.00031622776601683794f};
    #pragma unroll
    for (int ridx = 0; ridx < 4; ridx++) {
        int mt = ridx >> 1, half = ridx & 1;
        float tf = (float)(t0 + r0 + mt * 16 + half * 8 + qid);
        #pragma unroll
        for (int jj = 0; jj < 2; jj++)
            sincosf(tf * invf[tg * 2 + jj], &sn[ridx][jj], &cs[ridx][jj]);
    }
}

// ---------------------------------------------------------------------------
// Kernel 1: K, Q, V GEMMs; k,v -> ctx/ksum partials; q -> g_q. 512 threads.
// smem: A_hi 32K | A_lo 32K | Wh 32K | Wl 32K | k_s 64K | bias 1.5K
// ---------------------------------------------------------------------------
#define KVQ_WH    65536
#define KVQ_WL    98304
#define KVQ_STAGE 131072
#define KVQ_BIAS  196608
#define KVQ_SMEM  198144

extern "C" __global__ void __launch_bounds__(512, 1)
la_kvq(const float* __restrict__ x,
       const float* __restrict__ Wq, const float* __restrict__ bq,
       const float* __restrict__ Wk, const float* __restrict__ bk,
       const float* __restrict__ Wv, const float* __restrict__ bv)
{
    extern __shared__ char sm[];
    char* A_hi = sm;
    char* A_lo = sm + 32768;
    char* Wh   = sm + KVQ_WH;
    char* Wl   = sm + KVQ_WL;
    float* k_s = (float*)(sm + KVQ_STAGE);
    float* v_s = (float*)sm;                 // alias A (used after all GEMMs)
    float* bias_s = (float*)(sm + KVQ_BIAS); // [3][128]: k, q, v

    const int tid = threadIdx.x;
    const int wid = tid >> 5;
    const int lane = tid & 31;
    const int qid = lane >> 2, tg = lane & 3;
    const int r0 = (wid & 3) * 32;
    const int c0 = (wid >> 2) * 32;
    const int b  = blockIdx.y;
    const int t0 = blockIdx.x * TILE;

    const uint32_t aHi = smem_u32(A_hi), aLo = smem_u32(A_lo);
    const uint32_t wHs = smem_u32(Wh),   wLs = smem_u32(Wl);

    const float4* xp = (const float4*)(x + ((size_t)(b * NT + t0)) * ND);
    for (int i = tid; i < 4096; i += 512) {
        int row = i >> 5, k4 = i & 31;
        a_store4(A_hi, A_lo, row, k4, xp[i]);
    }
    if (tid < 128) {
        bias_s[tid]       = bk[tid];
        bias_s[128 + tid] = bq[tid];
        bias_s[256 + tid] = bv[tid];
    }
    float sn[4][2], cs[4][2];
    make_rope_tables(t0, r0, qid, tg, sn, cs);

    float acc[2][4][4];

    // ---- K GEMM ----
    convert_w2(Wk, Wh, Wl, tid, 512);
    __syncthreads();
    gemm3(aHi, aLo, wHs, wLs, acc, r0, c0, lane);
    rope_elu_acc(acc, bias_s, c0, tg, sn, cs);
    acc_store(k_s, acc, bias_s, false, r0, c0, qid, tg);

    // ---- Q GEMM ----
    __syncthreads();
    convert_w2(Wq, Wh, Wl, tid, 512);
    __syncthreads();
    gemm3(aHi, aLo, wHs, wLs, acc, r0, c0, lane);
    rope_elu_acc(acc, bias_s + 128, c0, tg, sn, cs);
    {
        float* gq = g_q + ((size_t)(b * NT + t0)) * ND;
        #pragma unroll
        for (int mt = 0; mt < 2; mt++)
            #pragma unroll
            for (int nt = 0; nt < 4; nt++)
                #pragma unroll
                for (int h2 = 0; h2 < 2; h2++) {
                    int row = r0 + mt * 16 + h2 * 8 + qid;
                    int col = c0 + nt * 8 + tg * 2;
                    *(float2*)(gq + (size_t)row * ND + col) =
                        make_float2(acc[mt][nt][h2 * 2], acc[mt][nt][h2 * 2 + 1]);
                }
    }

    // ---- V GEMM ----
    __syncthreads();
    convert_w2(Wv, Wh, Wl, tid, 512);
    __syncthreads();
    gemm3(aHi, aLo, wHs, wLs, acc, r0, c0, lane);
    __syncthreads();                  // all A reads done before v_s overwrite
    acc_store(v_s, acc, bias_s + 256, true, r0, c0, qid, tg);
    __syncthreads();

    // ---- ctx / ksum partials (no atomics) ----
    {
        int grp = tid >> 7, id = tid & 127;
        int h = id >> 4, d = id & 15;
        float accc[16];
        #pragma unroll
        for (int e = 0; e < 16; e++) accc[e] = 0.f;
        float ksacc = 0.f;
        int ts = grp * 32;
        int kcol = h * 16 + d;
        for (int t = ts; t < ts + 32; t++) {
            int sw = t & 7;
            float kv = k_s[t * 128 + ((((kcol >> 2) ^ sw) << 2) | (kcol & 3))];
            ksacc += kv;
            #pragma unroll
            for (int e4 = 0; e4 < 4; e4++) {
                float4 vv = *(const float4*)&v_s[t * 128 + (((h * 4 + e4) ^ sw) << 2)];
                accc[e4 * 4 + 0] = fmaf(kv, vv.x, accc[e4 * 4 + 0]);
                accc[e4 * 4 + 1] = fmaf(kv, vv.y, accc[e4 * 4 + 1]);
                accc[e4 * 4 + 2] = fmaf(kv, vv.z, accc[e4 * 4 + 2]);
                accc[e4 * 4 + 3] = fmaf(kv, vv.w, accc[e4 * 4 + 3]);
            }
        }
        size_t slot = ((size_t)(b * NTILES + blockIdx.x) * NGRP + grp);
        float* pp = g_part + slot * 2048 + h * 256 + d * 16;
        #pragma unroll
        for (int e = 0; e < 16; e++) pp[e] = accc[e];
        g_partk[slot * 128 + kcol] = ksacc;
    }
}

// ---------------------------------------------------------------------------
// Kernel 2: reduce partials. grid = NB*8 blocks, 256 threads.
// ---------------------------------------------------------------------------
extern "C" __global__ void __launch_bounds__(256, 1)
la_red()
{
    int b = blockIdx.x >> 3, ch = blockIdx.x & 7;
    int e = ch * 256 + threadIdx.x;
    const float* pc = g_part + (size_t)b * NTILES * NGRP * 2048;
    float s = 0.f;
    for (int j = 0; j < NTILES * NGRP; j++) s += pc[(size_t)j * 2048 + e];
    g_ctx[b * 2048 + e] = s;
    if (ch == 0 && threadIdx.x < 128) {
        const float* pk = g_partk + (size_t)b * NTILES * NGRP * 128;
        float sk = 0.f;
        for (int j = 0; j < NTILES * NGRP; j++) sk += pk[(size_t)j * 128 + threadIdx.x];
        g_ksum[b * 128 + threadIdx.x] = sk;
    }
}

// ---------------------------------------------------------------------------
// Kernel 3: attn = (q@ctx)*z; out = attn@Wo + bo. 512 threads.
// ---------------------------------------------------------------------------
#define OUT_WH    65536
#define OUT_WL    98304
#define OUT_STAGE 131072
#define OUT_CTX   196608
#define OUT_KSUM  204800
#define OUT_BIAS  205312
#define OUT_SMEM  205824

extern "C" __global__ void __launch_bounds__(512, 1)
la_out(const float* __restrict__ Wo, const float* __restrict__ bo,
       float* __restrict__ out)
{
    extern __shared__ char sm[];
    char* A_hi = sm;
    char* A_lo = sm + 32768;
    char* Wh   = sm + OUT_WH;
    char* Wl   = sm + OUT_WL;
    float* q_s    = (float*)(sm + OUT_STAGE);   // q in, then out staging
    float* ctx_s  = (float*)(sm + OUT_CTX);
    float* ksum_s = (float*)(sm + OUT_KSUM);
    float* bias_s = (float*)(sm + OUT_BIAS);

    const int tid = threadIdx.x;
    const int wid = tid >> 5;
    const int lane = tid & 31;
    const int qid = lane >> 2, tg = lane & 3;
    const int r0 = (wid & 3) * 32;
    const int c0 = (wid >> 2) * 32;
    const int b  = blockIdx.y;
    const int t0 = blockIdx.x * TILE;

    const uint32_t aHi = smem_u32(A_hi), aLo = smem_u32(A_lo);
    const uint32_t wHs = smem_u32(Wh),   wLs = smem_u32(Wl);

    const float4* qp = (const float4*)(g_q + ((size_t)(b * NT + t0)) * ND);
    for (int i = tid; i < 4096; i += 512) {
        int row = i >> 5, c4 = i & 31;
        float4 v = qp[i];
        *(float4*)&q_s[row * 128 + ((c4 ^ (row & 7)) << 2)] = v;
    }
    for (int i = tid; i < 2048; i += 512) ctx_s[i] = g_ctx[b * 2048 + i];
    if (tid < 128) { ksum_s[tid] = g_ksum[b * 128 + tid]; bias_s[tid] = bo[tid]; }
    convert_w2(Wo, Wh, Wl, tid, 512);
    __syncthreads();

    // ---- attention apply: writes attn into A tiles (bf16 hi/lo) ----
    {
        int r = tid >> 2, hg = tid & 3, swr = r & 7;
        #pragma unroll
        for (int hh = 0; hh < 2; hh++) {
            int h = hg * 2 + hh;
            float zz = 1e-6f;
            float oo[16];
            #pragma unroll
            for (int e = 0; e < 16; e++) oo[e] = 0.f;
            #pragma unroll
            for (int d = 0; d < 16; d++) {
                int col = h * 16 + d;
                float qv = q_s[r * 128 + ((((col >> 2) ^ swr) << 2) | (col & 3))];
                zz = fmaf(qv, ksum_s[col], zz);
                const float* cr = ctx_s + col * 16;
                #pragma unroll
                for (int e = 0; e < 16; e++) oo[e] = fmaf(qv, cr[e], oo[e]);
            }
            float zi = 1.f / zz;
            #pragma unroll
            for (int e4 = 0; e4 < 4; e4++) {
                int kcol = h * 16 + e4 * 4;
                a_store4(A_hi, A_lo, r, kcol >> 2,
                         make_float4(oo[e4 * 4] * zi, oo[e4 * 4 + 1] * zi,
                                     oo[e4 * 4 + 2] * zi, oo[e4 * 4 + 3] * zi));
            }
        }
    }
    __syncthreads();

    // ---- O GEMM ----
    float acc[2][4][4];
    gemm3(aHi, aLo, wHs, wLs, acc, r0, c0, lane);
    acc_store(q_s, acc, bias_s, true, r0, c0, qid, tg);
    __syncthreads();

    float4* outp = (float4*)(out + ((size_t)(b * NT + t0)) * ND);
    for (int i = tid; i < 4096; i += 512) {
        int row = i >> 5, cb = i & 31;
        outp[i] = *(const float4*)&q_s[row * 128 + ((cb ^ (row & 7)) << 2)];
    }
}

// ---------------------------------------------------------------------------
extern "C" void kernel_launch(void* const* d_in, const int* in_sizes, int n_in,
                              void* d_out, int out_size)
{
    const float* x  = (const float*)d_in[0];
    const float* Wq = (const float*)d_in[1];
    const float* bq = (const float*)d_in[2];
    const float* Wk = (const float*)d_in[3];
    const float* bk = (const float*)d_in[4];
    const float* Wv = (const float*)d_in[5];
    const float* bv = (const float*)d_in[6];
    const float* Wo = (const float*)d_in[7];
    const float* bo = (const float*)d_in[8];
    float* out = (float*)d_out;

    cudaFuncSetAttribute(la_kvq, cudaFuncAttributeMaxDynamicSharedMemorySize, KVQ_SMEM);
    cudaFuncSetAttribute(la_out, cudaFuncAttributeMaxDynamicSharedMemorySize, OUT_SMEM);

    dim3 grid(NT / TILE, NB);
    la_kvq<<<grid, 512, KVQ_SMEM>>>(x, Wq, bq, Wk, bk, Wv, bv);
    la_red<<<NB * 8, 256>>>();
    la_out<<<grid, 512, OUT_SMEM>>>(Wo, bo, out);
}

// round 6
// speedup vs baseline: 1.5457x; 1.5457x over previous
#include <cuda_runtime.h>
#include <cuda_bf16.h>
#include <math.h>
#include <stdint.h>

#define NB 8
#define NT 8192
#define ND 128
#define NH 8
#define TILE 64
#define NTILES 128             // NT / TILE
#define NGRP 2                 // partial groups per block

// ---------------- scratch (device globals; no allocs allowed) ---------------
static __device__ float g_q[NB * NT * ND];                  // rope+elu'd q
static __device__ float g_part[NB * NTILES * NGRP * 2048];  // ctx partials
static __device__ float g_partk[NB * NTILES * NGRP * 128];  // ksum partials
static __device__ float g_ctx[NB * 2048];                   // [b][h][d][e]
static __device__ float g_ksum[NB * 128];                   // [b][h*16+d]
static __device__ __nv_bfloat16 g_wt[4][2][16384];          // pre-converted W tiles
                                                            // [w][hi/lo], swizzled

// ---------------------------------------------------------------------------
__device__ __forceinline__ void mma16816(float c[4], const uint32_t a[4],
                                         uint32_t b0, uint32_t b1) {
    asm volatile(
        "mma.sync.aligned.m16n8k16.row.col.f32.bf16.bf16.f32 "
        "{%0,%1,%2,%3}, {%4,%5,%6,%7}, {%8,%9}, {%0,%1,%2,%3};"
        : "+f"(c[0]), "+f"(c[1]), "+f"(c[2]), "+f"(c[3])
        : "r"(a[0]), "r"(a[1]), "r"(a[2]), "r"(a[3]), "r"(b0), "r"(b1));
}
__device__ __forceinline__ void ldsm4(uint32_t r[4], uint32_t addr) {
    asm volatile("ldmatrix.sync.aligned.m8n8.x4.shared.b16 {%0,%1,%2,%3}, [%4];"
                 : "=r"(r[0]), "=r"(r[1]), "=r"(r[2]), "=r"(r[3]) : "r"(addr));
}
__device__ __forceinline__ uint32_t smem_u32(const void* p) {
    return (uint32_t)__cvta_generic_to_shared(p);
}

// bf16 tile layout (A and W identical): [rows][128 bf16 = 256B], 16B-granule
// XOR swizzle: phys_byte = row*256 + (((k>>3) ^ (row&7))<<4) + (k&7)*2.

__device__ __forceinline__ void a_store4(char* hi, char* lo, int row, int k4, float4 v) {
    uint32_t off = (uint32_t)(row * 256 + ((((k4 >> 1) ^ (row & 7)) << 4) | ((k4 & 1) << 3)));
    __nv_bfloat16 h0 = __float2bfloat16(v.x), h1 = __float2bfloat16(v.y);
    __nv_bfloat16 h2 = __float2bfloat16(v.z), h3 = __float2bfloat16(v.w);
    *(__nv_bfloat162*)(hi + off)     = __halves2bfloat162(h0, h1);
    *(__nv_bfloat162*)(hi + off + 4) = __halves2bfloat162(h2, h3);
    __nv_bfloat16 l0 = __float2bfloat16(v.x - __bfloat162float(h0));
    __nv_bfloat16 l1 = __float2bfloat16(v.y - __bfloat162float(h1));
    __nv_bfloat16 l2 = __float2bfloat16(v.z - __bfloat162float(h2));
    __nv_bfloat16 l3 = __float2bfloat16(v.w - __bfloat162float(h3));
    *(__nv_bfloat162*)(lo + off)     = __halves2bfloat162(l0, l1);
    *(__nv_bfloat162*)(lo + off + 4) = __halves2bfloat162(l2, l3);
}

// Copy one pre-converted 32KB W tile (global, already swizzled) into smem.
__device__ __forceinline__ void cp_w(const __nv_bfloat16* __restrict__ src,
                                     char* dst, int tid) {
    const int4* s = (const int4*)src;
    int4* d = (int4*)dst;
    #pragma unroll
    for (int l = 0; l < 8; l++) d[tid + l * 256] = s[tid + l * 256];
}

// 2-product pass: acc = Ah@Wh + Al@Wh (zeroes acc first). Warp tile 32x32.
__device__ __forceinline__ void gemm2p(uint32_t aHi, uint32_t aLo, uint32_t wB,
                                       float acc[2][4][4], int r0, int c0, int lane) {
    #pragma unroll
    for (int mt = 0; mt < 2; mt++)
        #pragma unroll
        for (int nt = 0; nt < 4; nt++)
            #pragma unroll
            for (int i = 0; i < 4; i++) acc[mt][nt][i] = 0.f;

    const int l7 = lane & 7;
    const int am8 = ((lane >> 3) & 1) << 3;
    const int akh = lane >> 4;
    const int bm8 = ((lane >> 4) & 1) << 3;
    const int bpar = (lane >> 3) & 1;
    uint32_t arow[2], brow[2];
    int arow7[2], brow7[2];
    #pragma unroll
    for (int mt = 0; mt < 2; mt++) {
        int r = r0 + mt * 16 + am8 + l7;
        arow[mt] = (uint32_t)(r * 256); arow7[mt] = r & 7;
    }
    #pragma unroll
    for (int n2 = 0; n2 < 2; n2++) {
        int r = c0 + n2 * 16 + bm8 + l7;
        brow[n2] = (uint32_t)(r * 256); brow7[n2] = r & 7;
    }

    #pragma unroll
    for (int ks = 0; ks < 8; ks++) {
        uint32_t Ah[2][4], Al[2][4], Bh[2][4];
        #pragma unroll
        for (int mt = 0; mt < 2; mt++) {
            uint32_t g = (uint32_t)(((2 * ks + akh) ^ arow7[mt]) << 4);
            ldsm4(Ah[mt], aHi + arow[mt] + g);
            ldsm4(Al[mt], aLo + arow[mt] + g);
        }
        #pragma unroll
        for (int n2 = 0; n2 < 2; n2++) {
            uint32_t g = (uint32_t)(((2 * ks + bpar) ^ brow7[n2]) << 4);
            ldsm4(Bh[n2], wB + brow[n2] + g);
        }
        #pragma unroll
        for (int n2 = 0; n2 < 2; n2++)
            #pragma unroll
            for (int j = 0; j < 2; j++) {
                int nt = n2 * 2 + j;
                uint32_t b0 = Bh[n2][j * 2], b1 = Bh[n2][j * 2 + 1];
                #pragma unroll
                for (int mt = 0; mt < 2; mt++) {
                    mma16816(acc[mt][nt], Ah[mt], b0, b1);
                    mma16816(acc[mt][nt], Al[mt], b0, b1);
                }
            }
    }
}

// 1-product pass: acc += Ah@Wl.
__device__ __forceinline__ void gemm1p(uint32_t aHi, uint32_t wB,
                                       float acc[2][4][4], int r0, int c0, int lane) {
    const int l7 = lane & 7;
    const int am8 = ((lane >> 3) & 1) << 3;
    const int akh = lane >> 4;
    const int bm8 = ((lane >> 4) & 1) << 3;
    const int bpar = (lane >> 3) & 1;
    uint32_t arow[2], brow[2];
    int arow7[2], brow7[2];
    #pragma unroll
    for (int mt = 0; mt < 2; mt++) {
        int r = r0 + mt * 16 + am8 + l7;
        arow[mt] = (uint32_t)(r * 256); arow7[mt] = r & 7;
    }
    #pragma unroll
    for (int n2 = 0; n2 < 2; n2++) {
        int r = c0 + n2 * 16 + bm8 + l7;
        brow[n2] = (uint32_t)(r * 256); brow7[n2] = r & 7;
    }
    #pragma unroll
    for (int ks = 0; ks < 8; ks++) {
        uint32_t Ah[2][4], Bl[2][4];
        #pragma unroll
        for (int mt = 0; mt < 2; mt++) {
            uint32_t g = (uint32_t)(((2 * ks + akh) ^ arow7[mt]) << 4);
            ldsm4(Ah[mt], aHi + arow[mt] + g);
        }
        #pragma unroll
        for (int n2 = 0; n2 < 2; n2++) {
            uint32_t g = (uint32_t)(((2 * ks + bpar) ^ brow7[n2]) << 4);
            ldsm4(Bl[n2], wB + brow[n2] + g);
        }
        #pragma unroll
        for (int n2 = 0; n2 < 2; n2++)
            #pragma unroll
            for (int j = 0; j < 2; j++) {
                int nt = n2 * 2 + j;
                uint32_t b0 = Bl[n2][j * 2], b1 = Bl[n2][j * 2 + 1];
                #pragma unroll
                for (int mt = 0; mt < 2; mt++)
                    mma16816(acc[mt][nt], Ah[mt], b0, b1);
            }
    }
}

// Full 3-product GEMM with single shared W buffer (Wh then Wl).
__device__ __forceinline__ void gemm_full(int widx, char* Wbuf,
                                          uint32_t aHi, uint32_t aLo, uint32_t wB,
                                          float acc[2][4][4],
                                          int r0, int c0, int lane, int tid) {
    __syncthreads();                        // prior Wbuf readers done
    cp_w(g_wt[widx][0], Wbuf, tid);
    __syncthreads();
    gemm2p(aHi, aLo, wB, acc, r0, c0, lane);
    __syncthreads();
    cp_w(g_wt[widx][1], Wbuf, tid);
    __syncthreads();
    gemm1p(aHi, wB, acc, r0, c0, lane);
}

// bias + RoPE + elu+1 on accumulators (warp covers cols c0..c0+31 = 2 heads).
__device__ __forceinline__ void rope_elu_acc(float acc[2][4][4],
                                             const float* bias_s, int c0, int tg,
                                             const float sn[4][2], const float cs[4][2]) {
    #pragma unroll
    for (int mt = 0; mt < 2; mt++)
        #pragma unroll
        for (int t = 0; t < 2; t++)
            #pragma unroll
            for (int i = 0; i < 4; i++) {
                int ridx = mt * 2 + (i >> 1);
                int jj = i & 1;
                float x1 = acc[mt][2 * t][i]     + bias_s[c0 + t * 16 + tg * 2 + jj];
                float x2 = acc[mt][2 * t + 1][i] + bias_s[c0 + t * 16 + 8 + tg * 2 + jj];
                float s = sn[ridx][jj], c = cs[ridx][jj];
                float y1 = x1 * c - x2 * s;
                float y2 = x1 * s + x2 * c;
                acc[mt][2 * t][i]     = y1 > 0.f ? y1 + 1.f : __expf(y1);
                acc[mt][2 * t + 1][i] = y2 > 0.f ? y2 + 1.f : __expf(y2);
            }
}

// Store accumulators to fp32 smem tile [rows][128], float4-block XOR swizzle.
__device__ __forceinline__ void acc_store(float* dst, const float acc[2][4][4],
                                          const float* bias_s, bool add_bias,
                                          int r0, int c0, int qid, int tg) {
    #pragma unroll
    for (int mt = 0; mt < 2; mt++)
        #pragma unroll
        for (int nt = 0; nt < 4; nt++)
            #pragma unroll
            for (int h2 = 0; h2 < 2; h2++) {
                int row = r0 + mt * 16 + h2 * 8 + qid;
                int col = c0 + nt * 8 + tg * 2;
                float v0 = acc[mt][nt][h2 * 2];
                float v1 = acc[mt][nt][h2 * 2 + 1];
                if (add_bias) { v0 += bias_s[col]; v1 += bias_s[col + 1]; }
                float* p = dst + row * 128 + (((col >> 2) ^ (row & 7)) << 2) + (col & 3);
                p[0] = v0; p[1] = v1;
            }
}

__device__ __forceinline__ void make_rope_tables(int t0, int r0, int qid, int tg,
                                                 float sn[4][2], float cs[4][2]) {
    const float invf[8] = {1.0f, 0.31622776601683794f, 0.1f, 0.03162277660168379f,
                           0.01f, 0.0031622776601683794f, 0.001f, 0.00031622776601683794f};
    #pragma unroll
    for (int ridx = 0; ridx < 4; ridx++) {
        int mt = ridx >> 1, half = ridx & 1;
        float tf = (float)(t0 + r0 + mt * 16 + half * 8 + qid);
        #pragma unroll
        for (int jj = 0; jj < 2; jj++)
            sincosf(tf * invf[tg * 2 + jj], &sn[ridx][jj], &cs[ridx][jj]);
    }
}

// ---------------------------------------------------------------------------
// Kernel 0: pre-convert weights into swizzled bf16 hi/lo global tiles.
// grid = 4 blocks (0=Wk, 1=Wq, 2=Wv, 3=Wo), 256 threads.
// ---------------------------------------------------------------------------
extern "C" __global__ void __launch_bounds__(256)
la_wconv(const float* __restrict__ Wq, const float* __restrict__ Wk,
         const float* __restrict__ Wv, const float* __restrict__ Wo)
{
    const float* W = (blockIdx.x == 0) ? Wk : (blockIdx.x == 1) ? Wq
                   : (blockIdx.x == 2) ? Wv : Wo;
    __nv_bfloat16* wh = g_wt[blockIdx.x][0];
    __nv_bfloat16* wl = g_wt[blockIdx.x][1];
    const float4* Wp = (const float4*)W;
    for (int i = threadIdx.x; i < 4096; i += 256) {
        int k = i >> 5, n4 = i & 31;
        float4 w = Wp[i];
        float vv[4] = {w.x, w.y, w.z, w.w};
        #pragma unroll
        for (int u = 0; u < 4; u++) {
            int n = n4 * 4 + u;
            uint32_t e = (uint32_t)(n * 128 + ((((k >> 3) ^ (n & 7)) << 3) | (k & 7)));
            __nv_bfloat16 bh = __float2bfloat16(vv[u]);
            wh[e] = bh;
            wl[e] = __float2bfloat16(vv[u] - __bfloat162float(bh));
        }
    }
}

// ---------------------------------------------------------------------------
// Kernel 1: K, Q, V GEMMs; k,v -> ctx/ksum partials; q -> g_q.
// TILE=64 rows, 256 threads, ~98KB smem -> 2 blocks/SM.
// smem: A_hi 16K | A_lo 16K | Wbuf 32K | k_s 32K | bias 1.5K
// ---------------------------------------------------------------------------
#define KVQ_WB    32768
#define KVQ_KS    65536
#define KVQ_BIAS  98304
#define KVQ_SMEM  99840

extern "C" __global__ void __launch_bounds__(256, 2)
la_kvq(const float* __restrict__ x,
       const float* __restrict__ bq, const float* __restrict__ bk,
       const float* __restrict__ bv)
{
    extern __shared__ char sm[];
    char* A_hi = sm;
    char* A_lo = sm + 16384;
    char* Wbuf = sm + KVQ_WB;
    float* k_s = (float*)(sm + KVQ_KS);
    float* v_s = (float*)sm;                 // alias A (used after all GEMMs)
    float* bias_s = (float*)(sm + KVQ_BIAS); // [3][128]: k, q, v

    const int tid = threadIdx.x;
    const int wid = tid >> 5;
    const int lane = tid & 31;
    const int qid = lane >> 2, tg = lane & 3;
    const int r0 = (wid & 1) * 32;
    const int c0 = (wid >> 1) * 32;
    const int b  = blockIdx.y;
    const int t0 = blockIdx.x * TILE;

    const uint32_t aHi = smem_u32(A_hi), aLo = smem_u32(A_lo);
    const uint32_t wB  = smem_u32(Wbuf);

    const float4* xp = (const float4*)(x + ((size_t)(b * NT + t0)) * ND);
    for (int i = tid; i < 2048; i += 256) {
        int row = i >> 5, k4 = i & 31;
        a_store4(A_hi, A_lo, row, k4, xp[i]);
    }
    if (tid < 128) {
        bias_s[tid]       = bk[tid];
        bias_s[128 + tid] = bq[tid];
        bias_s[256 + tid] = bv[tid];
    }
    float sn[4][2], cs[4][2];
    make_rope_tables(t0, r0, qid, tg, sn, cs);

    float acc[2][4][4];

    // ---- K GEMM ----
    gemm_full(0, Wbuf, aHi, aLo, wB, acc, r0, c0, lane, tid);
    rope_elu_acc(acc, bias_s, c0, tg, sn, cs);
    acc_store(k_s, acc, bias_s, false, r0, c0, qid, tg);

    // ---- Q GEMM ----
    gemm_full(1, Wbuf, aHi, aLo, wB, acc, r0, c0, lane, tid);
    rope_elu_acc(acc, bias_s + 128, c0, tg, sn, cs);
    {
        float* gq = g_q + ((size_t)(b * NT + t0)) * ND;
        #pragma unroll
        for (int mt = 0; mt < 2; mt++)
            #pragma unroll
            for (int nt = 0; nt < 4; nt++)
                #pragma unroll
                for (int h2 = 0; h2 < 2; h2++) {
                    int row = r0 + mt * 16 + h2 * 8 + qid;
                    int col = c0 + nt * 8 + tg * 2;
                    *(float2*)(gq + (size_t)row * ND + col) =
                        make_float2(acc[mt][nt][h2 * 2], acc[mt][nt][h2 * 2 + 1]);
                }
    }

    // ---- V GEMM ----
    gemm_full(2, Wbuf, aHi, aLo, wB, acc, r0, c0, lane, tid);
    __syncthreads();                  // all A reads done before v_s overwrite
    acc_store(v_s, acc, bias_s + 256, true, r0, c0, qid, tg);
    __syncthreads();

    // ---- ctx / ksum partials (no atomics) ----
    {
        int grp = tid >> 7, id = tid & 127;
        int h = id >> 4, d = id & 15;
        float accc[16];
        #pragma unroll
        for (int e = 0; e < 16; e++) accc[e] = 0.f;
        float ksacc = 0.f;
        int ts = grp * 32;
        int kcol = h * 16 + d;
        for (int t = ts; t < ts + 32; t++) {
            int sw = t & 7;
            float kv = k_s[t * 128 + ((((kcol >> 2) ^ sw) << 2) | (kcol & 3))];
            ksacc += kv;
            #pragma unroll
            for (int e4 = 0; e4 < 4; e4++) {
                float4 vv = *(const float4*)&v_s[t * 128 + (((h * 4 + e4) ^ sw) << 2)];
                accc[e4 * 4 + 0] = fmaf(kv, vv.x, accc[e4 * 4 + 0]);
                accc[e4 * 4 + 1] = fmaf(kv, vv.y, accc[e4 * 4 + 1]);
                accc[e4 * 4 + 2] = fmaf(kv, vv.z, accc[e4 * 4 + 2]);
                accc[e4 * 4 + 3] = fmaf(kv, vv.w, accc[e4 * 4 + 3]);
            }
        }
        size_t slot = ((size_t)(b * NTILES + blockIdx.x) * NGRP + grp);
        float* pp = g_part + slot * 2048 + h * 256 + d * 16;
        #pragma unroll
        for (int e = 0; e < 16; e++) pp[e] = accc[e];
        g_partk[slot * 128 + kcol] = ksacc;
    }
}

// ---------------------------------------------------------------------------
// Kernel 2: reduce partials. grid = NB*8 blocks, 256 threads.
// ---------------------------------------------------------------------------
extern "C" __global__ void __launch_bounds__(256)
la_red()
{
    int b = blockIdx.x >> 3, ch = blockIdx.x & 7;
    int e = ch * 256 + threadIdx.x;
    const float* pc = g_part + (size_t)b * NTILES * NGRP * 2048;
    float s = 0.f;
    for (int j = 0; j < NTILES * NGRP; j++) s += pc[(size_t)j * 2048 + e];
    g_ctx[b * 2048 + e] = s;
    if (ch == 0 && threadIdx.x < 128) {
        const float* pk = g_partk + (size_t)b * NTILES * NGRP * 128;
        float sk = 0.f;
        for (int j = 0; j < NTILES * NGRP; j++) sk += pk[(size_t)j * 128 + threadIdx.x];
        g_ksum[b * 128 + threadIdx.x] = sk;
    }
}

// ---------------------------------------------------------------------------
// Kernel 3: attn = (q@ctx)*z; out = attn@Wo + bo. TILE=64, 256 threads.
// smem: A 32K | Wbuf 32K | q_s 32K | ctx 8K | ksum 512 | bias 512  (~106K)
// ---------------------------------------------------------------------------
#define OUT_WB    32768
#define OUT_QS    65536
#define OUT_CTX   98304
#define OUT_KSUM  106496
#define OUT_BIAS  107008
#define OUT_SMEM  107520

extern "C" __global__ void __launch_bounds__(256, 2)
la_out(const float* __restrict__ bo, float* __restrict__ out)
{
    extern __shared__ char sm[];
    char* A_hi = sm;
    char* A_lo = sm + 16384;
    char* Wbuf = sm + OUT_WB;
    float* q_s    = (float*)(sm + OUT_QS);
    float* ctx_s  = (float*)(sm + OUT_CTX);
    float* ksum_s = (float*)(sm + OUT_KSUM);
    float* bias_s = (float*)(sm + OUT_BIAS);

    const int tid = threadIdx.x;
    const int wid = tid >> 5;
    const int lane = tid & 31;
    const int qid = lane >> 2, tg = lane & 3;
    const int r0 = (wid & 1) * 32;
    const int c0 = (wid >> 1) * 32;
    const int b  = blockIdx.y;
    const int t0 = blockIdx.x * TILE;

    const uint32_t aHi = smem_u32(A_hi), aLo = smem_u32(A_lo);
    const uint32_t wB  = smem_u32(Wbuf);

    const float4* qp = (const float4*)(g_q + ((size_t)(b * NT + t0)) * ND);
    for (int i = tid; i < 2048; i += 256) {
        int row = i >> 5, c4 = i & 31;
        float4 v = qp[i];
        *(float4*)&q_s[row * 128 + ((c4 ^ (row & 7)) << 2)] = v;
    }
    for (int i = tid; i < 2048; i += 256) ctx_s[i] = g_ctx[b * 2048 + i];
    if (tid < 128) { ksum_s[tid] = g_ksum[b * 128 + tid]; bias_s[tid] = bo[tid]; }
    __syncthreads();

    // ---- attention apply: writes attn into A tiles (bf16 hi/lo) ----
    {
        int r = tid >> 2, hg = tid & 3, swr = r & 7;
        #pragma unroll
        for (int hh = 0; hh < 2; hh++) {
            int h = hg * 2 + hh;
            float zz = 1e-6f;
            float oo[16];
            #pragma unroll
            for (int e = 0; e < 16; e++) oo[e] = 0.f;
            #pragma unroll
            for (int d = 0; d < 16; d++) {
                int col = h * 16 + d;
                float qv = q_s[r * 128 + ((((col >> 2) ^ swr) << 2) | (col & 3))];
                zz = fmaf(qv, ksum_s[col], zz);
                const float* cr = ctx_s + col * 16;
                #pragma unroll
                for (int e = 0; e < 16; e++) oo[e] = fmaf(qv, cr[e], oo[e]);
            }
            float zi = 1.f / zz;
            #pragma unroll
            for (int e4 = 0; e4 < 4; e4++) {
                int kcol = h * 16 + e4 * 4;
                a_store4(A_hi, A_lo, r, kcol >> 2,
                         make_float4(oo[e4 * 4] * zi, oo[e4 * 4 + 1] * zi,
                                     oo[e4 * 4 + 2] * zi, oo[e4 * 4 + 3] * zi));
            }
        }
    }

    // ---- O GEMM (sync inside gemm_full covers A-tile writes) ----
    float acc[2][4][4];
    gemm_full(3, Wbuf, aHi, aLo, wB, acc, r0, c0, lane, tid);

    // direct global store with bias
    {
        float* op = out + ((size_t)(b * NT + t0)) * ND;
        #pragma unroll
        for (int mt = 0; mt < 2; mt++)
            #pragma unroll
            for (int nt = 0; nt < 4; nt++)
                #pragma unroll
                for (int h2 = 0; h2 < 2; h2++) {
                    int row = r0 + mt * 16 + h2 * 8 + qid;
                    int col = c0 + nt * 8 + tg * 2;
                    *(float2*)(op + (size_t)row * ND + col) =
                        make_float2(acc[mt][nt][h2 * 2] + bias_s[col],
                                    acc[mt][nt][h2 * 2 + 1] + bias_s[col + 1]);
                }
    }
}

// ---------------------------------------------------------------------------
extern "C" void kernel_launch(void* const* d_in, const int* in_sizes, int n_in,
                              void* d_out, int out_size)
{
    const float* x  = (const float*)d_in[0];
    const float* Wq = (const float*)d_in[1];
    const float* bq = (const float*)d_in[2];
    const float* Wk = (const float*)d_in[3];
    const float* bk = (const float*)d_in[4];
    const float* Wv = (const float*)d_in[5];
    const float* bv = (const float*)d_in[6];
    const float* Wo = (const float*)d_in[7];
    const float* bo = (const float*)d_in[8];
    float* out = (float*)d_out;

    cudaFuncSetAttribute(la_kvq, cudaFuncAttributeMaxDynamicSharedMemorySize, KVQ_SMEM);
    cudaFuncSetAttribute(la_out, cudaFuncAttributeMaxDynamicSharedMemorySize, OUT_SMEM);

    la_wconv<<<4, 256>>>(Wq, Wk, Wv, Wo);

    dim3 grid(NT / TILE, NB);
    la_kvq<<<grid, 256, KVQ_SMEM>>>(x, bq, bk, bv);
    la_red<<<NB * 8, 256>>>();
    la_out<<<grid, 256, OUT_SMEM>>>(bo, out);
}

// round 7
// speedup vs baseline: 1.9701x; 1.2746x over previous
#include <cuda_runtime.h>
#include <cuda_bf16.h>
#include <math.h>
#include <stdint.h>

#define NB 8
#define NT 8192
#define ND 128
#define NH 8
#define TILE 64
#define NTILES 128             // NT / TILE
#define NGRP 2                 // partial groups per block

// ---------------- scratch (device globals; no allocs allowed) ---------------
static __device__ float g_q[NB * NT * ND];                  // rope+elu'd q
static __device__ float g_part[NB * NTILES * NGRP * 2048];  // ctx partials
static __device__ float g_partk[NB * NTILES * NGRP * 128];  // ksum partials
static __device__ float g_ctx[NB * 2048];                   // [b][h][d][e]
static __device__ float g_ksum[NB * 128];                   // [b][h*16+d]
static __device__ __nv_bfloat16 g_wt[4][2][16384];          // pre-converted W tiles

// ---------------------------------------------------------------------------
__device__ __forceinline__ void mma16816(float c[4], const uint32_t a[4],
                                         uint32_t b0, uint32_t b1) {
    asm volatile(
        "mma.sync.aligned.m16n8k16.row.col.f32.bf16.bf16.f32 "
        "{%0,%1,%2,%3}, {%4,%5,%6,%7}, {%8,%9}, {%0,%1,%2,%3};"
        : "+f"(c[0]), "+f"(c[1]), "+f"(c[2]), "+f"(c[3])
        : "r"(a[0]), "r"(a[1]), "r"(a[2]), "r"(a[3]), "r"(b0), "r"(b1));
}
__device__ __forceinline__ void ldsm4(uint32_t r[4], uint32_t addr) {
    asm volatile("ldmatrix.sync.aligned.m8n8.x4.shared.b16 {%0,%1,%2,%3}, [%4];"
                 : "=r"(r[0]), "=r"(r[1]), "=r"(r[2]), "=r"(r[3]) : "r"(addr));
}
__device__ __forceinline__ uint32_t smem_u32(const void* p) {
    return (uint32_t)__cvta_generic_to_shared(p);
}
__device__ __forceinline__ void cp_async16(uint32_t dst, const void* src) {
    asm volatile("cp.async.cg.shared.global [%0], [%1], 16;" :: "r"(dst), "l"(src));
}
#define CP_COMMIT() asm volatile("cp.async.commit_group;" ::: "memory")
#define CP_WAIT(n)  asm volatile("cp.async.wait_group %0;" :: "n"(n) : "memory")

// A tile layout: [rows][128 bf16 = 256B], 16B-granule XOR swizzle:
// phys_byte = row*256 + (((k>>3) ^ (row&7))<<4) + (k&7)*2.
__device__ __forceinline__ void a_store4(char* hi, char* lo, int row, int k4, float4 v) {
    uint32_t off = (uint32_t)(row * 256 + ((((k4 >> 1) ^ (row & 7)) << 4) | ((k4 & 1) << 3)));
    __nv_bfloat16 h0 = __float2bfloat16(v.x), h1 = __float2bfloat16(v.y);
    __nv_bfloat16 h2 = __float2bfloat16(v.z), h3 = __float2bfloat16(v.w);
    *(__nv_bfloat162*)(hi + off)     = __halves2bfloat162(h0, h1);
    *(__nv_bfloat162*)(hi + off + 4) = __halves2bfloat162(h2, h3);
    __nv_bfloat16 l0 = __float2bfloat16(v.x - __bfloat162float(h0));
    __nv_bfloat16 l1 = __float2bfloat16(v.y - __bfloat162float(h1));
    __nv_bfloat16 l2 = __float2bfloat16(v.z - __bfloat162float(h2));
    __nv_bfloat16 l3 = __float2bfloat16(v.w - __bfloat162float(h3));
    *(__nv_bfloat162*)(lo + off)     = __halves2bfloat162(l0, l1);
    *(__nv_bfloat162*)(lo + off + 4) = __halves2bfloat162(l2, l3);
}

// Issue one 16KB W chunk (k-half 'half' of a 32KB polarity tile) via cp.async.
// Chunk buffer layout: [n][128B] with same granule swizzle (local to the half).
__device__ __forceinline__ void issue_wchunk(const __nv_bfloat16* __restrict__ wsrc,
                                             int half, uint32_t bufaddr, int tid) {
    const char* src = (const char*)wsrc + half * 128;
    #pragma unroll
    for (int l = 0; l < 4; l++) {
        int i = tid + l * 256;          // 0..1023
        int n = i >> 3, j = i & 7;
        cp_async16(bufaddr + (uint32_t)i * 16, src + n * 256 + j * 16);
    }
    CP_COMMIT();
}

// Compute 4 global ksteps (ks = half*4 + ksl) from one chunk buffer.
// pol 0: acc += Ah@W + Al@W ; pol 1: acc += Ah@W.
__device__ __forceinline__ void gemm_chunk(uint32_t aHi, uint32_t aLo, uint32_t wbuf,
                                           int half, int pol,
                                           float acc[2][4][4], int r0, int c0, int lane) {
    const int l7 = lane & 7;
    const int am8 = ((lane >> 3) & 1) << 3;
    const int akh = lane >> 4;
    const int bm8 = ((lane >> 4) & 1) << 3;
    const int bpar = (lane >> 3) & 1;
    uint32_t arow[2], brow[2];
    int arow7[2], brow7[2];
    #pragma unroll
    for (int mt = 0; mt < 2; mt++) {
        int r = r0 + mt * 16 + am8 + l7;
        arow[mt] = (uint32_t)(r * 256); arow7[mt] = r & 7;
    }
    #pragma unroll
    for (int n2 = 0; n2 < 2; n2++) {
        int r = c0 + n2 * 16 + bm8 + l7;
        brow[n2] = (uint32_t)(r * 128); brow7[n2] = r & 7;
    }
    #pragma unroll
    for (int ksl = 0; ksl < 4; ksl++) {
        int ks = half * 4 + ksl;
        uint32_t Ah[2][4], Al[2][4], Bh[2][4];
        #pragma unroll
        for (int mt = 0; mt < 2; mt++) {
            uint32_t g = (uint32_t)(((2 * ks + akh) ^ arow7[mt]) << 4);
            ldsm4(Ah[mt], aHi + arow[mt] + g);
            if (pol == 0) ldsm4(Al[mt], aLo + arow[mt] + g);
        }
        #pragma unroll
        for (int n2 = 0; n2 < 2; n2++) {
            uint32_t g = (uint32_t)(((2 * ksl + bpar) ^ brow7[n2]) << 4);
            ldsm4(Bh[n2], wbuf + brow[n2] + g);
        }
        #pragma unroll
        for (int n2 = 0; n2 < 2; n2++)
            #pragma unroll
            for (int j = 0; j < 2; j++) {
                int nt = n2 * 2 + j;
                uint32_t b0 = Bh[n2][j * 2], b1 = Bh[n2][j * 2 + 1];
                #pragma unroll
                for (int mt = 0; mt < 2; mt++) {
                    mma16816(acc[mt][nt], Ah[mt], b0, b1);
                    if (pol == 0) mma16816(acc[mt][nt], Al[mt], b0, b1);
                }
            }
    }
}

// Full 3-product GEMM with double-buffered cp.async W streaming (4x16KB chunks).
__device__ __forceinline__ void gemm_stream(int widx, uint32_t aHi, uint32_t aLo,
                                            uint32_t wB, float acc[2][4][4],
                                            int r0, int c0, int lane, int tid) {
    #pragma unroll
    for (int mt = 0; mt < 2; mt++)
        #pragma unroll
        for (int nt = 0; nt < 4; nt++)
            #pragma unroll
            for (int i = 0; i < 4; i++) acc[mt][nt][i] = 0.f;

    const __nv_bfloat16* wHi = g_wt[widx][0];
    const __nv_bfloat16* wLo = g_wt[widx][1];

    __syncthreads();                 // prior users of Wbuf (and A writers) done
    issue_wchunk(wHi, 0, wB, tid);
    issue_wchunk(wHi, 1, wB + 16384, tid);

    #pragma unroll
    for (int c = 0; c < 4; c++) {
        if (c < 3) CP_WAIT(1); else CP_WAIT(0);
        __syncthreads();             // chunk c visible to all warps
        gemm_chunk(aHi, aLo, wB + (uint32_t)((c & 1) * 16384), c & 1, c >> 1,
                   acc, r0, c0, lane);
        if (c < 2) {
            __syncthreads();         // all warps done with buffer c
            issue_wchunk(wLo, c & 1, wB + (uint32_t)((c & 1) * 16384), tid);
        }
    }
}

// bias + RoPE + elu+1 on accumulators (warp covers cols c0..c0+31 = 2 heads).
__device__ __forceinline__ void rope_elu_acc(float acc[2][4][4],
                                             const float* bias_s, int c0, int tg,
                                             const float sn[4][2], const float cs[4][2]) {
    #pragma unroll
    for (int mt = 0; mt < 2; mt++)
        #pragma unroll
        for (int t = 0; t < 2; t++)
            #pragma unroll
            for (int i = 0; i < 4; i++) {
                int ridx = mt * 2 + (i >> 1);
                int jj = i & 1;
                float x1 = acc[mt][2 * t][i]     + bias_s[c0 + t * 16 + tg * 2 + jj];
                float x2 = acc[mt][2 * t + 1][i] + bias_s[c0 + t * 16 + 8 + tg * 2 + jj];
                float s = sn[ridx][jj], c = cs[ridx][jj];
                float y1 = x1 * c - x2 * s;
                float y2 = x1 * s + x2 * c;
                acc[mt][2 * t][i]     = y1 > 0.f ? y1 + 1.f : __expf(y1);
                acc[mt][2 * t + 1][i] = y2 > 0.f ? y2 + 1.f : __expf(y2);
            }
}

// Store accumulators to fp32 smem tile [rows][128], float4-block XOR swizzle.
__device__ __forceinline__ void acc_store(float* dst, const float acc[2][4][4],
                                          const float* bias_s, bool add_bias,
                                          int r0, int c0, int qid, int tg) {
    #pragma unroll
    for (int mt = 0; mt < 2; mt++)
        #pragma unroll
        for (int nt = 0; nt < 4; nt++)
            #pragma unroll
            for (int h2 = 0; h2 < 2; h2++) {
                int row = r0 + mt * 16 + h2 * 8 + qid;
                int col = c0 + nt * 8 + tg * 2;
                float v0 = acc[mt][nt][h2 * 2];
                float v1 = acc[mt][nt][h2 * 2 + 1];
                if (add_bias) { v0 += bias_s[col]; v1 += bias_s[col + 1]; }
                float* p = dst + row * 128 + (((col >> 2) ^ (row & 7)) << 2) + (col & 3);
                p[0] = v0; p[1] = v1;
            }
}

__device__ __forceinline__ void make_rope_tables(int t0, int r0, int qid, int tg,
                                                 float sn[4][2], float cs[4][2]) {
    const float invf[8] = {1.0f, 0.31622776601683794f, 0.1f, 0.03162277660168379f,
                           0.01f, 0.0031622776601683794f, 0.001f, 0.00031622776601683794f};
    #pragma unroll
    for (int ridx = 0; ridx < 4; ridx++) {
        int mt = ridx >> 1, half = ridx & 1;
        float tf = (float)(t0 + r0 + mt * 16 + half * 8 + qid);
        #pragma unroll
        for (int jj = 0; jj < 2; jj++)
            sincosf(tf * invf[tg * 2 + jj], &sn[ridx][jj], &cs[ridx][jj]);
    }
}

// ---------------------------------------------------------------------------
// Kernel 0: pre-convert weights. grid = 4 (0=Wk, 1=Wq, 2=Wv, 3=Wo).
// ---------------------------------------------------------------------------
extern "C" __global__ void __launch_bounds__(256)
la_wconv(const float* __restrict__ Wq, const float* __restrict__ Wk,
         const float* __restrict__ Wv, const float* __restrict__ Wo)
{
    const float* W = (blockIdx.x == 0) ? Wk : (blockIdx.x == 1) ? Wq
                   : (blockIdx.x == 2) ? Wv : Wo;
    __nv_bfloat16* wh = g_wt[blockIdx.x][0];
    __nv_bfloat16* wl = g_wt[blockIdx.x][1];
    const float4* Wp = (const float4*)W;
    for (int i = threadIdx.x; i < 4096; i += 256) {
        int k = i >> 5, n4 = i & 31;
        float4 w = Wp[i];
        float vv[4] = {w.x, w.y, w.z, w.w};
        #pragma unroll
        for (int u = 0; u < 4; u++) {
            int n = n4 * 4 + u;
            uint32_t e = (uint32_t)(n * 128 + ((((k >> 3) ^ (n & 7)) << 3) | (k & 7)));
            __nv_bfloat16 bh = __float2bfloat16(vv[u]);
            wh[e] = bh;
            wl[e] = __float2bfloat16(vv[u] - __bfloat162float(bh));
        }
    }
}

// ---------------------------------------------------------------------------
// Kernel 1: K, Q, V GEMMs; k,v -> ctx/ksum partials; q -> g_q.
// smem: A_hi 16K | A_lo 16K | Wbuf 32K (2x16K) | k_s 32K | bias 1.5K
// ---------------------------------------------------------------------------
#define KVQ_WB    32768
#define KVQ_KS    65536
#define KVQ_BIAS  98304
#define KVQ_SMEM  99840

extern "C" __global__ void __launch_bounds__(256, 2)
la_kvq(const float* __restrict__ x,
       const float* __restrict__ bq, const float* __restrict__ bk,
       const float* __restrict__ bv)
{
    extern __shared__ char sm[];
    char* A_hi = sm;
    char* A_lo = sm + 16384;
    float* k_s = (float*)(sm + KVQ_KS);
    float* v_s = (float*)sm;                 // alias A (used after all GEMMs)
    float* bias_s = (float*)(sm + KVQ_BIAS); // [3][128]: k, q, v

    const int tid = threadIdx.x;
    const int wid = tid >> 5;
    const int lane = tid & 31;
    const int qid = lane >> 2, tg = lane & 3;
    const int r0 = (wid & 1) * 32;
    const int c0 = (wid >> 1) * 32;
    const int b  = blockIdx.y;
    const int t0 = blockIdx.x * TILE;

    const uint32_t aHi = smem_u32(A_hi), aLo = smem_u32(A_lo);
    const uint32_t wB  = smem_u32(sm + KVQ_WB);

    const float4* xp = (const float4*)(x + ((size_t)(b * NT + t0)) * ND);
    for (int i = tid; i < 2048; i += 256) {
        int row = i >> 5, k4 = i & 31;
        a_store4(A_hi, A_lo, row, k4, xp[i]);
    }
    if (tid < 128) {
        bias_s[tid]       = bk[tid];
        bias_s[128 + tid] = bq[tid];
        bias_s[256 + tid] = bv[tid];
    }
    float sn[4][2], cs[4][2];
    make_rope_tables(t0, r0, qid, tg, sn, cs);

    float acc[2][4][4];

    // ---- K GEMM ----
    gemm_stream(0, aHi, aLo, wB, acc, r0, c0, lane, tid);
    rope_elu_acc(acc, bias_s, c0, tg, sn, cs);
    acc_store(k_s, acc, bias_s, false, r0, c0, qid, tg);

    // ---- Q GEMM ----
    gemm_stream(1, aHi, aLo, wB, acc, r0, c0, lane, tid);
    rope_elu_acc(acc, bias_s + 128, c0, tg, sn, cs);
    {
        float* gq = g_q + ((size_t)(b * NT + t0)) * ND;
        #pragma unroll
        for (int mt = 0; mt < 2; mt++)
            #pragma unroll
            for (int nt = 0; nt < 4; nt++)
                #pragma unroll
                for (int h2 = 0; h2 < 2; h2++) {
                    int row = r0 + mt * 16 + h2 * 8 + qid;
                    int col = c0 + nt * 8 + tg * 2;
                    *(float2*)(gq + (size_t)row * ND + col) =
                        make_float2(acc[mt][nt][h2 * 2], acc[mt][nt][h2 * 2 + 1]);
                }
    }

    // ---- V GEMM ----
    gemm_stream(2, aHi, aLo, wB, acc, r0, c0, lane, tid);
    __syncthreads();                  // all A reads done before v_s overwrite
    acc_store(v_s, acc, bias_s + 256, true, r0, c0, qid, tg);
    __syncthreads();

    // ---- ctx / ksum partials (no atomics) ----
    {
        int grp = tid >> 7, id = tid & 127;
        int h = id >> 4, d = id & 15;
        float accc[16];
        #pragma unroll
        for (int e = 0; e < 16; e++) accc[e] = 0.f;
        float ksacc = 0.f;
        int ts = grp * 32;
        int kcol = h * 16 + d;
        for (int t = ts; t < ts + 32; t++) {
            int sw = t & 7;
            float kv = k_s[t * 128 + ((((kcol >> 2) ^ sw) << 2) | (kcol & 3))];
            ksacc += kv;
            #pragma unroll
            for (int e4 = 0; e4 < 4; e4++) {
                float4 vv = *(const float4*)&v_s[t * 128 + (((h * 4 + e4) ^ sw) << 2)];
                accc[e4 * 4 + 0] = fmaf(kv, vv.x, accc[e4 * 4 + 0]);
                accc[e4 * 4 + 1] = fmaf(kv, vv.y, accc[e4 * 4 + 1]);
                accc[e4 * 4 + 2] = fmaf(kv, vv.z, accc[e4 * 4 + 2]);
                accc[e4 * 4 + 3] = fmaf(kv, vv.w, accc[e4 * 4 + 3]);
            }
        }
        size_t slot = ((size_t)(b * NTILES + blockIdx.x) * NGRP + grp);
        float* pp = g_part + slot * 2048 + h * 256 + d * 16;
        #pragma unroll
        for (int e = 0; e < 16; e++) pp[e] = accc[e];
        g_partk[slot * 128 + kcol] = ksacc;
    }
}

// ---------------------------------------------------------------------------
// Kernel 2: reduce partials. grid = NB*8 blocks, 256 threads.
// ---------------------------------------------------------------------------
extern "C" __global__ void __launch_bounds__(256)
la_red()
{
    int b = blockIdx.x >> 3, ch = blockIdx.x & 7;
    int e = ch * 256 + threadIdx.x;
    const float* pc = g_part + (size_t)b * NTILES * NGRP * 2048;
    float s = 0.f;
    for (int j = 0; j < NTILES * NGRP; j++) s += pc[(size_t)j * 2048 + e];
    g_ctx[b * 2048 + e] = s;
    if (ch == 0 && threadIdx.x < 128) {
        const float* pk = g_partk + (size_t)b * NTILES * NGRP * 128;
        float sk = 0.f;
        for (int j = 0; j < NTILES * NGRP; j++) sk += pk[(size_t)j * 128 + threadIdx.x];
        g_ksum[b * 128 + threadIdx.x] = sk;
    }
}

// ---------------------------------------------------------------------------
// Kernel 3: attn = (q@ctx)*z; out = attn@Wo + bo.
// smem: A 32K | Wbuf 32K | q_s 32K | ctx 8.32K(padded) | ksum .5K | bias .5K
// ---------------------------------------------------------------------------
#define OUT_WB    32768
#define OUT_QS    65536
#define OUT_CTX   98304
#define OUT_KSUM  106624
#define OUT_BIAS  107136
#define OUT_SMEM  107648
#define CTXP 260               // padded floats per head (bank shift 4)

extern "C" __global__ void __launch_bounds__(256, 2)
la_out(const float* __restrict__ bo, float* __restrict__ out)
{
    extern __shared__ char sm[];
    char* A_hi = sm;
    char* A_lo = sm + 16384;
    float* q_s    = (float*)(sm + OUT_QS);
    float* ctx_s  = (float*)(sm + OUT_CTX);   // [8][CTXP]
    float* ksum_s = (float*)(sm + OUT_KSUM);
    float* bias_s = (float*)(sm + OUT_BIAS);

    const int tid = threadIdx.x;
    const int wid = tid >> 5;
    const int lane = tid & 31;
    const int qid = lane >> 2, tg = lane & 3;
    const int r0 = (wid & 1) * 32;
    const int c0 = (wid >> 1) * 32;
    const int b  = blockIdx.y;
    const int t0 = blockIdx.x * TILE;

    const uint32_t aHi = smem_u32(A_hi), aLo = smem_u32(A_lo);
    const uint32_t wB  = smem_u32(sm + OUT_WB);

    const float4* qp = (const float4*)(g_q + ((size_t)(b * NT + t0)) * ND);
    for (int i = tid; i < 2048; i += 256) {
        int row = i >> 5, c4 = i & 31;
        float4 v = qp[i];
        *(float4*)&q_s[row * 128 + ((c4 ^ (row & 7)) << 2)] = v;
    }
    for (int i = tid; i < 2048; i += 256)
        ctx_s[(i >> 8) * CTXP + (i & 255)] = g_ctx[b * 2048 + i];
    if (tid < 128) { ksum_s[tid] = g_ksum[b * 128 + tid]; bias_s[tid] = bo[tid]; }
    __syncthreads();

    // ---- attention apply (float4, padded ctx -> conflict-free broadcasts) ----
    {
        int r = tid >> 2, hg = tid & 3, swr = r & 7;
        #pragma unroll
        for (int hh = 0; hh < 2; hh++) {
            int h = hg * 2 + hh;
            float qv[16];
            #pragma unroll
            for (int e4 = 0; e4 < 4; e4++) {
                int col = h * 16 + e4 * 4;
                float4 t = *(const float4*)&q_s[r * 128 + (((col >> 2) ^ swr) << 2)];
                qv[e4 * 4] = t.x; qv[e4 * 4 + 1] = t.y;
                qv[e4 * 4 + 2] = t.z; qv[e4 * 4 + 3] = t.w;
            }
            float zz = 1e-6f;
            #pragma unroll
            for (int d = 0; d < 16; d++) zz = fmaf(qv[d], ksum_s[h * 16 + d], zz);
            float4 oo[4];
            #pragma unroll
            for (int e4 = 0; e4 < 4; e4++) oo[e4] = make_float4(0.f, 0.f, 0.f, 0.f);
            #pragma unroll
            for (int d = 0; d < 16; d++) {
                const float4* cr = (const float4*)&ctx_s[h * CTXP + d * 16];
                float q = qv[d];
                #pragma unroll
                for (int e4 = 0; e4 < 4; e4++) {
                    float4 c = cr[e4];
                    oo[e4].x = fmaf(q, c.x, oo[e4].x);
                    oo[e4].y = fmaf(q, c.y, oo[e4].y);
                    oo[e4].z = fmaf(q, c.z, oo[e4].z);
                    oo[e4].w = fmaf(q, c.w, oo[e4].w);
                }
            }
            float zi = 1.f / zz;
            #pragma unroll
            for (int e4 = 0; e4 < 4; e4++) {
                int kcol = h * 16 + e4 * 4;
                a_store4(A_hi, A_lo, r, kcol >> 2,
                         make_float4(oo[e4].x * zi, oo[e4].y * zi,
                                     oo[e4].z * zi, oo[e4].w * zi));
            }
        }
    }

    // ---- O GEMM (entry sync inside gemm_stream covers A-tile writes) ----
    float acc[2][4][4];
    gemm_stream(3, aHi, aLo, wB, acc, r0, c0, lane, tid);

    // direct global store with bias
    {
        float* op = out + ((size_t)(b * NT + t0)) * ND;
        #pragma unroll
        for (int mt = 0; mt < 2; mt++)
            #pragma unroll
            for (int nt = 0; nt < 4; nt++)
                #pragma unroll
                for (int h2 = 0; h2 < 2; h2++) {
                    int row = r0 + mt * 16 + h2 * 8 + qid;
                    int col = c0 + nt * 8 + tg * 2;
                    *(float2*)(op + (size_t)row * ND + col) =
                        make_float2(acc[mt][nt][h2 * 2] + bias_s[col],
                                    acc[mt][nt][h2 * 2 + 1] + bias_s[col + 1]);
                }
    }
}

// ---------------------------------------------------------------------------
extern "C" void kernel_launch(void* const* d_in, const int* in_sizes, int n_in,
                              void* d_out, int out_size)
{
    const float* x  = (const float*)d_in[0];
    const float* Wq = (const float*)d_in[1];
    const float* bq = (const float*)d_in[2];
    const float* Wk = (const float*)d_in[3];
    const float* bk = (const float*)d_in[4];
    const float* Wv = (const float*)d_in[5];
    const float* bv = (const float*)d_in[6];
    const float* Wo = (const float*)d_in[7];
    const float* bo = (const float*)d_in[8];
    float* out = (float*)d_out;

    cudaFuncSetAttribute(la_kvq, cudaFuncAttributeMaxDynamicSharedMemorySize, KVQ_SMEM);
    cudaFuncSetAttribute(la_out, cudaFuncAttributeMaxDynamicSharedMemorySize, OUT_SMEM);

    la_wconv<<<4, 256>>>(Wq, Wk, Wv, Wo);

    dim3 grid(NT / TILE, NB);
    la_kvq<<<grid, 256, KVQ_SMEM>>>(x, bq, bk, bv);
    la_red<<<NB * 8, 256>>>();
    la_out<<<grid, 256, OUT_SMEM>>>(bo, out);
}

// round 8
// speedup vs baseline: 2.0360x; 1.0335x over previous
#include <cuda_runtime.h>
#include <cuda_bf16.h>
#include <math.h>
#include <stdint.h>

#define NB 8
#define NT 8192
#define ND 128
#define NH 8
#define TILE 64
#define NTILES 128             // NT / TILE
#define NGRP 2                 // partial groups per block

// ---------------- scratch (device globals; no allocs allowed) ---------------
static __device__ float g_part[NB * NTILES * NGRP * 2048];  // ctx partials
static __device__ float g_partk[NB * NTILES * NGRP * 128];  // ksum partials
static __device__ float g_ctx[NB * 2048];                   // [b][h][d][e]
static __device__ float g_ksum[NB * 128];                   // [b][h*16+d]
static __device__ __nv_bfloat16 g_wt[4][2][16384];          // pre-converted W tiles

// ---------------------------------------------------------------------------
__device__ __forceinline__ void mma16816(float c[4], const uint32_t a[4],
                                         uint32_t b0, uint32_t b1) {
    asm volatile(
        "mma.sync.aligned.m16n8k16.row.col.f32.bf16.bf16.f32 "
        "{%0,%1,%2,%3}, {%4,%5,%6,%7}, {%8,%9}, {%0,%1,%2,%3};"
        : "+f"(c[0]), "+f"(c[1]), "+f"(c[2]), "+f"(c[3])
        : "r"(a[0]), "r"(a[1]), "r"(a[2]), "r"(a[3]), "r"(b0), "r"(b1));
}
__device__ __forceinline__ void ldsm4(uint32_t r[4], uint32_t addr) {
    asm volatile("ldmatrix.sync.aligned.m8n8.x4.shared.b16 {%0,%1,%2,%3}, [%4];"
                 : "=r"(r[0]), "=r"(r[1]), "=r"(r[2]), "=r"(r[3]) : "r"(addr));
}
__device__ __forceinline__ uint32_t smem_u32(const void* p) {
    return (uint32_t)__cvta_generic_to_shared(p);
}
__device__ __forceinline__ void cp_async16(uint32_t dst, const void* src) {
    asm volatile("cp.async.cg.shared.global [%0], [%1], 16;" :: "r"(dst), "l"(src));
}
#define CP_COMMIT() asm volatile("cp.async.commit_group;" ::: "memory")
#define CP_WAIT(n)  asm volatile("cp.async.wait_group %0;" :: "n"(n) : "memory")

// A tile layout: [rows][128 bf16 = 256B], 16B-granule XOR swizzle:
// phys_byte = row*256 + (((k>>3) ^ (row&7))<<4) + (k&7)*2.
__device__ __forceinline__ void a_store4(char* hi, char* lo, int row, int k4, float4 v) {
    uint32_t off = (uint32_t)(row * 256 + ((((k4 >> 1) ^ (row & 7)) << 4) | ((k4 & 1) << 3)));
    __nv_bfloat16 h0 = __float2bfloat16(v.x), h1 = __float2bfloat16(v.y);
    __nv_bfloat16 h2 = __float2bfloat16(v.z), h3 = __float2bfloat16(v.w);
    *(__nv_bfloat162*)(hi + off)     = __halves2bfloat162(h0, h1);
    *(__nv_bfloat162*)(hi + off + 4) = __halves2bfloat162(h2, h3);
    __nv_bfloat16 l0 = __float2bfloat16(v.x - __bfloat162float(h0));
    __nv_bfloat16 l1 = __float2bfloat16(v.y - __bfloat162float(h1));
    __nv_bfloat16 l2 = __float2bfloat16(v.z - __bfloat162float(h2));
    __nv_bfloat16 l3 = __float2bfloat16(v.w - __bfloat162float(h3));
    *(__nv_bfloat162*)(lo + off)     = __halves2bfloat162(l0, l1);
    *(__nv_bfloat162*)(lo + off + 4) = __halves2bfloat162(l2, l3);
}

// Issue one 16KB W chunk (k-half 'half' of a 32KB polarity tile) via cp.async.
__device__ __forceinline__ void issue_wchunk(const __nv_bfloat16* __restrict__ wsrc,
                                             int half, uint32_t bufaddr, int tid) {
    const char* src = (const char*)wsrc + half * 128;
    #pragma unroll
    for (int l = 0; l < 4; l++) {
        int i = tid + l * 256;
        int n = i >> 3, j = i & 7;
        cp_async16(bufaddr + (uint32_t)i * 16, src + n * 256 + j * 16);
    }
    CP_COMMIT();
}

// Compute 4 global ksteps (ks = half*4 + ksl) from one chunk buffer.
__device__ __forceinline__ void gemm_chunk(uint32_t aHi, uint32_t aLo, uint32_t wbuf,
                                           int half, int pol,
                                           float acc[2][4][4], int r0, int c0, int lane) {
    const int l7 = lane & 7;
    const int am8 = ((lane >> 3) & 1) << 3;
    const int akh = lane >> 4;
    const int bm8 = ((lane >> 4) & 1) << 3;
    const int bpar = (lane >> 3) & 1;
    uint32_t arow[2], brow[2];
    int arow7[2], brow7[2];
    #pragma unroll
    for (int mt = 0; mt < 2; mt++) {
        int r = r0 + mt * 16 + am8 + l7;
        arow[mt] = (uint32_t)(r * 256); arow7[mt] = r & 7;
    }
    #pragma unroll
    for (int n2 = 0; n2 < 2; n2++) {
        int r = c0 + n2 * 16 + bm8 + l7;
        brow[n2] = (uint32_t)(r * 128); brow7[n2] = r & 7;
    }
    #pragma unroll
    for (int ksl = 0; ksl < 4; ksl++) {
        int ks = half * 4 + ksl;
        uint32_t Ah[2][4], Al[2][4], Bh[2][4];
        #pragma unroll
        for (int mt = 0; mt < 2; mt++) {
            uint32_t g = (uint32_t)(((2 * ks + akh) ^ arow7[mt]) << 4);
            ldsm4(Ah[mt], aHi + arow[mt] + g);
            if (pol == 0) ldsm4(Al[mt], aLo + arow[mt] + g);
        }
        #pragma unroll
        for (int n2 = 0; n2 < 2; n2++) {
            uint32_t g = (uint32_t)(((2 * ksl + bpar) ^ brow7[n2]) << 4);
            ldsm4(Bh[n2], wbuf + brow[n2] + g);
        }
        #pragma unroll
        for (int n2 = 0; n2 < 2; n2++)
            #pragma unroll
            for (int j = 0; j < 2; j++) {
                int nt = n2 * 2 + j;
                uint32_t b0 = Bh[n2][j * 2], b1 = Bh[n2][j * 2 + 1];
                #pragma unroll
                for (int mt = 0; mt < 2; mt++) {
                    mma16816(acc[mt][nt], Ah[mt], b0, b1);
                    if (pol == 0) mma16816(acc[mt][nt], Al[mt], b0, b1);
                }
            }
    }
}

// Full 3-product GEMM with double-buffered cp.async W streaming (4x16KB chunks).
__device__ __forceinline__ void gemm_stream(int widx, uint32_t aHi, uint32_t aLo,
                                            uint32_t wB, float acc[2][4][4],
                                            int r0, int c0, int lane, int tid) {
    #pragma unroll
    for (int mt = 0; mt < 2; mt++)
        #pragma unroll
        for (int nt = 0; nt < 4; nt++)
            #pragma unroll
            for (int i = 0; i < 4; i++) acc[mt][nt][i] = 0.f;

    const __nv_bfloat16* wHi = g_wt[widx][0];
    const __nv_bfloat16* wLo = g_wt[widx][1];

    __syncthreads();                 // prior users of Wbuf / A writers done
    issue_wchunk(wHi, 0, wB, tid);
    issue_wchunk(wHi, 1, wB + 16384, tid);

    #pragma unroll
    for (int c = 0; c < 4; c++) {
        if (c < 3) CP_WAIT(1); else CP_WAIT(0);
        __syncthreads();             // chunk c visible to all warps
        gemm_chunk(aHi, aLo, wB + (uint32_t)((c & 1) * 16384), c & 1, c >> 1,
                   acc, r0, c0, lane);
        if (c < 2) {
            __syncthreads();         // all warps done with buffer c
            issue_wchunk(wLo, c & 1, wB + (uint32_t)((c & 1) * 16384), tid);
        }
    }
}

// bias + RoPE + elu+1 on accumulators (warp covers cols c0..c0+31 = 2 heads).
__device__ __forceinline__ void rope_elu_acc(float acc[2][4][4],
                                             const float* bias_s, int c0, int tg,
                                             const float sn[4][2], const float cs[4][2]) {
    #pragma unroll
    for (int mt = 0; mt < 2; mt++)
        #pragma unroll
        for (int t = 0; t < 2; t++)
            #pragma unroll
            for (int i = 0; i < 4; i++) {
                int ridx = mt * 2 + (i >> 1);
                int jj = i & 1;
                float x1 = acc[mt][2 * t][i]     + bias_s[c0 + t * 16 + tg * 2 + jj];
                float x2 = acc[mt][2 * t + 1][i] + bias_s[c0 + t * 16 + 8 + tg * 2 + jj];
                float s = sn[ridx][jj], c = cs[ridx][jj];
                float y1 = x1 * c - x2 * s;
                float y2 = x1 * s + x2 * c;
                acc[mt][2 * t][i]     = y1 > 0.f ? y1 + 1.f : __expf(y1);
                acc[mt][2 * t + 1][i] = y2 > 0.f ? y2 + 1.f : __expf(y2);
            }
}

// Store accumulators to fp32 smem tile [rows][128], float4-block XOR swizzle.
__device__ __forceinline__ void acc_store(float* dst, const float acc[2][4][4],
                                          const float* bias_s, bool add_bias,
                                          int r0, int c0, int qid, int tg) {
    #pragma unroll
    for (int mt = 0; mt < 2; mt++)
        #pragma unroll
        for (int nt = 0; nt < 4; nt++)
            #pragma unroll
            for (int h2 = 0; h2 < 2; h2++) {
                int row = r0 + mt * 16 + h2 * 8 + qid;
                int col = c0 + nt * 8 + tg * 2;
                float v0 = acc[mt][nt][h2 * 2];
                float v1 = acc[mt][nt][h2 * 2 + 1];
                if (add_bias) { v0 += bias_s[col]; v1 += bias_s[col + 1]; }
                float* p = dst + row * 128 + (((col >> 2) ^ (row & 7)) << 2) + (col & 3);
                p[0] = v0; p[1] = v1;
            }
}

__device__ __forceinline__ void make_rope_tables(int t0, int r0, int qid, int tg,
                                                 float sn[4][2], float cs[4][2]) {
    const float invf[8] = {1.0f, 0.31622776601683794f, 0.1f, 0.03162277660168379f,
                           0.01f, 0.0031622776601683794f, 0.001f, 0.00031622776601683794f};
    #pragma unroll
    for (int ridx = 0; ridx < 4; ridx++) {
        int mt = ridx >> 1, half = ridx & 1;
        float tf = (float)(t0 + r0 + mt * 16 + half * 8 + qid);
        #pragma unroll
        for (int jj = 0; jj < 2; jj++)
            sincosf(tf * invf[tg * 2 + jj], &sn[ridx][jj], &cs[ridx][jj]);
    }
}

// ---------------------------------------------------------------------------
// Kernel 0: pre-convert weights. grid = 4 (0=Wk, 1=Wq, 2=Wv, 3=Wo).
// ---------------------------------------------------------------------------
extern "C" __global__ void __launch_bounds__(256)
la_wconv(const float* __restrict__ Wq, const float* __restrict__ Wk,
         const float* __restrict__ Wv, const float* __restrict__ Wo)
{
    const float* W = (blockIdx.x == 0) ? Wk : (blockIdx.x == 1) ? Wq
                   : (blockIdx.x == 2) ? Wv : Wo;
    __nv_bfloat16* wh = g_wt[blockIdx.x][0];
    __nv_bfloat16* wl = g_wt[blockIdx.x][1];
    const float4* Wp = (const float4*)W;
    for (int i = threadIdx.x; i < 4096; i += 256) {
        int k = i >> 5, n4 = i & 31;
        float4 w = Wp[i];
        float vv[4] = {w.x, w.y, w.z, w.w};
        #pragma unroll
        for (int u = 0; u < 4; u++) {
            int n = n4 * 4 + u;
            uint32_t e = (uint32_t)(n * 128 + ((((k >> 3) ^ (n & 7)) << 3) | (k & 7)));
            __nv_bfloat16 bh = __float2bfloat16(vv[u]);
            wh[e] = bh;
            wl[e] = __float2bfloat16(vv[u] - __bfloat162float(bh));
        }
    }
}

// ---------------------------------------------------------------------------
// Kernel 1: K, V GEMMs; k,v -> ctx/ksum partials.
// smem: A_hi 16K | A_lo 16K | Wbuf 32K | k_s 32K | bias 1K
// ---------------------------------------------------------------------------
#define KV_WB    32768
#define KV_KS    65536
#define KV_BIAS  98304
#define KV_SMEM  99328

extern "C" __global__ void __launch_bounds__(256, 2)
la_kv(const float* __restrict__ x,
      const float* __restrict__ bk, const float* __restrict__ bv)
{
    extern __shared__ char sm[];
    char* A_hi = sm;
    char* A_lo = sm + 16384;
    float* k_s = (float*)(sm + KV_KS);
    float* v_s = (float*)sm;                // alias A (used after both GEMMs)
    float* bias_s = (float*)(sm + KV_BIAS); // [2][128]: k, v

    const int tid = threadIdx.x;
    const int lane = tid & 31;
    const int wid = tid >> 5;
    const int qid = lane >> 2, tg = lane & 3;
    const int r0 = (wid & 1) * 32;
    const int c0 = (wid >> 1) * 32;
    const int b  = blockIdx.y;
    const int t0 = blockIdx.x * TILE;

    const uint32_t aHi = smem_u32(A_hi), aLo = smem_u32(A_lo);
    const uint32_t wB  = smem_u32(sm + KV_WB);

    const float4* xp = (const float4*)(x + ((size_t)(b * NT + t0)) * ND);
    for (int i = tid; i < 2048; i += 256) {
        int row = i >> 5, k4 = i & 31;
        a_store4(A_hi, A_lo, row, k4, xp[i]);
    }
    if (tid < 128) {
        bias_s[tid]       = bk[tid];
        bias_s[128 + tid] = bv[tid];
    }
    float sn[4][2], cs[4][2];
    make_rope_tables(t0, r0, qid, tg, sn, cs);

    float acc[2][4][4];

    // ---- K GEMM ----
    gemm_stream(0, aHi, aLo, wB, acc, r0, c0, lane, tid);
    rope_elu_acc(acc, bias_s, c0, tg, sn, cs);
    acc_store(k_s, acc, bias_s, false, r0, c0, qid, tg);

    // ---- V GEMM ----
    gemm_stream(2, aHi, aLo, wB, acc, r0, c0, lane, tid);
    __syncthreads();                  // all A reads done before v_s overwrite
    acc_store(v_s, acc, bias_s + 128, true, r0, c0, qid, tg);
    __syncthreads();

    // ---- ctx / ksum partials (no atomics) ----
    {
        int grp = tid >> 7, id = tid & 127;
        int h = id >> 4, d = id & 15;
        float accc[16];
        #pragma unroll
        for (int e = 0; e < 16; e++) accc[e] = 0.f;
        float ksacc = 0.f;
        int ts = grp * 32;
        int kcol = h * 16 + d;
        for (int t = ts; t < ts + 32; t++) {
            int sw = t & 7;
            float kv = k_s[t * 128 + ((((kcol >> 2) ^ sw) << 2) | (kcol & 3))];
            ksacc += kv;
            #pragma unroll
            for (int e4 = 0; e4 < 4; e4++) {
                float4 vv = *(const float4*)&v_s[t * 128 + (((h * 4 + e4) ^ sw) << 2)];
                accc[e4 * 4 + 0] = fmaf(kv, vv.x, accc[e4 * 4 + 0]);
                accc[e4 * 4 + 1] = fmaf(kv, vv.y, accc[e4 * 4 + 1]);
                accc[e4 * 4 + 2] = fmaf(kv, vv.z, accc[e4 * 4 + 2]);
                accc[e4 * 4 + 3] = fmaf(kv, vv.w, accc[e4 * 4 + 3]);
            }
        }
        size_t slot = ((size_t)(b * NTILES + blockIdx.x) * NGRP + grp);
        float* pp = g_part + slot * 2048 + h * 256 + d * 16;
        #pragma unroll
        for (int e = 0; e < 16; e++) pp[e] = accc[e];
        g_partk[slot * 128 + kcol] = ksacc;
    }
}

// ---------------------------------------------------------------------------
// Kernel 2: reduce partials. grid = NB*8 blocks, 256 threads.
// ---------------------------------------------------------------------------
extern "C" __global__ void __launch_bounds__(256)
la_red()
{
    int b = blockIdx.x >> 3, ch = blockIdx.x & 7;
    int e = ch * 256 + threadIdx.x;
    const float* pc = g_part + (size_t)b * NTILES * NGRP * 2048;
    float s = 0.f;
    for (int j = 0; j < NTILES * NGRP; j++) s += pc[(size_t)j * 2048 + e];
    g_ctx[b * 2048 + e] = s;
    if (ch == 0 && threadIdx.x < 128) {
        const float* pk = g_partk + (size_t)b * NTILES * NGRP * 128;
        float sk = 0.f;
        for (int j = 0; j < NTILES * NGRP; j++) sk += pk[(size_t)j * 128 + threadIdx.x];
        g_ksum[b * 128 + threadIdx.x] = sk;
    }
}

// ---------------------------------------------------------------------------
// Kernel 3: q = rope_elu(x@Wq+bq); attn = (q@ctx)*z; out = attn@Wo + bo.
// smem: A 32K | Wbuf 32K | q_s 32K | ctx 8.32K | ksum .5K | bias 1K
// ---------------------------------------------------------------------------
#define QO_WB    32768
#define QO_QS    65536
#define QO_CTX   98304
#define QO_KSUM  106624
#define QO_BIAS  107136
#define QO_SMEM  108160
#define CTXP 260               // padded floats per head (bank shift 4)

extern "C" __global__ void __launch_bounds__(256, 2)
la_qout(const float* __restrict__ x,
        const float* __restrict__ bq, const float* __restrict__ bo,
        float* __restrict__ out)
{
    extern __shared__ char sm[];
    char* A_hi = sm;
    char* A_lo = sm + 16384;
    float* q_s    = (float*)(sm + QO_QS);
    float* ctx_s  = (float*)(sm + QO_CTX);   // [8][CTXP]
    float* ksum_s = (float*)(sm + QO_KSUM);
    float* bias_s = (float*)(sm + QO_BIAS);  // [2][128]: q, o

    const int tid = threadIdx.x;
    const int lane = tid & 31;
    const int wid = tid >> 5;
    const int qid = lane >> 2, tg = lane & 3;
    const int r0 = (wid & 1) * 32;
    const int c0 = (wid >> 1) * 32;
    const int b  = blockIdx.y;
    const int t0 = blockIdx.x * TILE;

    const uint32_t aHi = smem_u32(A_hi), aLo = smem_u32(A_lo);
    const uint32_t wB  = smem_u32(sm + QO_WB);

    const float4* xp = (const float4*)(x + ((size_t)(b * NT + t0)) * ND);
    for (int i = tid; i < 2048; i += 256) {
        int row = i >> 5, k4 = i & 31;
        a_store4(A_hi, A_lo, row, k4, xp[i]);
    }
    for (int i = tid; i < 2048; i += 256)
        ctx_s[(i >> 8) * CTXP + (i & 255)] = g_ctx[b * 2048 + i];
    if (tid < 128) {
        ksum_s[tid] = g_ksum[b * 128 + tid];
        bias_s[tid] = bq[tid];
        bias_s[128 + tid] = bo[tid];
    }
    float sn[4][2], cs[4][2];
    make_rope_tables(t0, r0, qid, tg, sn, cs);

    float acc[2][4][4];

    // ---- Q GEMM ----
    gemm_stream(1, aHi, aLo, wB, acc, r0, c0, lane, tid);
    rope_elu_acc(acc, bias_s, c0, tg, sn, cs);
    acc_store(q_s, acc, bias_s, false, r0, c0, qid, tg);
    __syncthreads();

    // ---- attention apply (float4, padded ctx -> conflict-free broadcasts) ----
    {
        int r = tid >> 2, hg = tid & 3, swr = r & 7;
        #pragma unroll
        for (int hh = 0; hh < 2; hh++) {
            int h = hg * 2 + hh;
            float qv[16];
            #pragma unroll
            for (int e4 = 0; e4 < 4; e4++) {
                int col = h * 16 + e4 * 4;
                float4 t = *(const float4*)&q_s[r * 128 + (((col >> 2) ^ swr) << 2)];
                qv[e4 * 4] = t.x; qv[e4 * 4 + 1] = t.y;
                qv[e4 * 4 + 2] = t.z; qv[e4 * 4 + 3] = t.w;
            }
            float zz = 1e-6f;
            #pragma unroll
            for (int d = 0; d < 16; d++) zz = fmaf(qv[d], ksum_s[h * 16 + d], zz);
            float4 oo[4];
            #pragma unroll
            for (int e4 = 0; e4 < 4; e4++) oo[e4] = make_float4(0.f, 0.f, 0.f, 0.f);
            #pragma unroll
            for (int d = 0; d < 16; d++) {
                const float4* cr = (const float4*)&ctx_s[h * CTXP + d * 16];
                float q = qv[d];
                #pragma unroll
                for (int e4 = 0; e4 < 4; e4++) {
                    float4 c = cr[e4];
                    oo[e4].x = fmaf(q, c.x, oo[e4].x);
                    oo[e4].y = fmaf(q, c.y, oo[e4].y);
                    oo[e4].z = fmaf(q, c.z, oo[e4].z);
                    oo[e4].w = fmaf(q, c.w, oo[e4].w);
                }
            }
            float zi = 1.f / zz;
            #pragma unroll
            for (int e4 = 0; e4 < 4; e4++) {
                int kcol = h * 16 + e4 * 4;
                a_store4(A_hi, A_lo, r, kcol >> 2,
                         make_float4(oo[e4].x * zi, oo[e4].y * zi,
                                     oo[e4].z * zi, oo[e4].w * zi));
            }
        }
    }

    // ---- O GEMM (entry sync inside gemm_stream covers attn A-tile writes) ----
    gemm_stream(3, aHi, aLo, wB, acc, r0, c0, lane, tid);

    // direct global store with bias
    {
        float* op = out + ((size_t)(b * NT + t0)) * ND;
        #pragma unroll
        for (int mt = 0; mt < 2; mt++)
            #pragma unroll
            for (int nt = 0; nt < 4; nt++)
                #pragma unroll
                for (int h2 = 0; h2 < 2; h2++) {
                    int row = r0 + mt * 16 + h2 * 8 + qid;
                    int col = c0 + nt * 8 + tg * 2;
                    *(float2*)(op + (size_t)row * ND + col) =
                        make_float2(acc[mt][nt][h2 * 2] + bias_s[128 + col],
                                    acc[mt][nt][h2 * 2 + 1] + bias_s[128 + col + 1]);
                }
    }
}

// ---------------------------------------------------------------------------
extern "C" void kernel_launch(void* const* d_in, const int* in_sizes, int n_in,
                              void* d_out, int out_size)
{
    const float* x  = (const float*)d_in[0];
    const float* Wq = (const float*)d_in[1];
    const float* bq = (const float*)d_in[2];
    const float* Wk = (const float*)d_in[3];
    const float* bk = (const float*)d_in[4];
    const float* Wv = (const float*)d_in[5];
    const float* bv = (const float*)d_in[6];
    const float* Wo = (const float*)d_in[7];
    const float* bo = (const float*)d_in[8];
    float* out = (float*)d_out;

    cudaFuncSetAttribute(la_kv,   cudaFuncAttributeMaxDynamicSharedMemorySize, KV_SMEM);
    cudaFuncSetAttribute(la_qout, cudaFuncAttributeMaxDynamicSharedMemorySize, QO_SMEM);

    la_wconv<<<4, 256>>>(Wq, Wk, Wv, Wo);

    dim3 grid(NT / TILE, NB);
    la_kv<<<grid, 256, KV_SMEM>>>(x, bk, bv);
    la_red<<<NB * 8, 256>>>();
    la_qout<<<grid, 256, QO_SMEM>>>(x, bq, bo, out);
}

// round 9
// speedup vs baseline: 2.1758x; 1.0686x over previous
#include <cuda_runtime.h>
#include <cuda_fp16.h>
#include <math.h>
#include <stdint.h>

#define NB 8
#define NT 8192
#define ND 128
#define NH 8
#define TILE 64
#define NTILES 128             // NT / TILE
#define NGRP 2                 // partial groups per block

// ---------------- scratch (device globals; no allocs allowed) ---------------
static __device__ float g_part[NB * NTILES * NGRP * 2048];  // ctx partials
static __device__ float g_partk[NB * NTILES * NGRP * 128];  // ksum partials
static __device__ float g_ctx[NB * 2048];                   // [b][h][d][e]
static __device__ float g_ksum[NB * 128];                   // [b][h*16+d]
static __device__ __half g_wt[4][2][16384];                 // W tiles [w][hi/lo]

// ---------------------------------------------------------------------------
__device__ __forceinline__ void mma16816(float c[4], const uint32_t a[4],
                                         uint32_t b0, uint32_t b1) {
    asm volatile(
        "mma.sync.aligned.m16n8k16.row.col.f32.f16.f16.f32 "
        "{%0,%1,%2,%3}, {%4,%5,%6,%7}, {%8,%9}, {%0,%1,%2,%3};"
        : "+f"(c[0]), "+f"(c[1]), "+f"(c[2]), "+f"(c[3])
        : "r"(a[0]), "r"(a[1]), "r"(a[2]), "r"(a[3]), "r"(b0), "r"(b1));
}
__device__ __forceinline__ void ldsm4(uint32_t r[4], uint32_t addr) {
    asm volatile("ldmatrix.sync.aligned.m8n8.x4.shared.b16 {%0,%1,%2,%3}, [%4];"
                 : "=r"(r[0]), "=r"(r[1]), "=r"(r[2]), "=r"(r[3]) : "r"(addr));
}
__device__ __forceinline__ uint32_t smem_u32(const void* p) {
    return (uint32_t)__cvta_generic_to_shared(p);
}
__device__ __forceinline__ void cp_async16(uint32_t dst, const void* src) {
    asm volatile("cp.async.cg.shared.global [%0], [%1], 16;" :: "r"(dst), "l"(src));
}
#define CP_COMMIT() asm volatile("cp.async.commit_group;" ::: "memory")
#define CP_WAIT(n)  asm volatile("cp.async.wait_group %0;" :: "n"(n) : "memory")

// A tile layout: [rows][128 fp16 = 256B], 16B-granule XOR swizzle:
// phys_byte = row*256 + (((k>>3) ^ (row&7))<<4) + (k&7)*2.
__device__ __forceinline__ void a_store4(char* a, int row, int k4, float4 v) {
    uint32_t off = (uint32_t)(row * 256 + ((((k4 >> 1) ^ (row & 7)) << 4) | ((k4 & 1) << 3)));
    *(__half2*)(a + off)     = __floats2half2_rn(v.x, v.y);
    *(__half2*)(a + off + 4) = __floats2half2_rn(v.z, v.w);
}

// Issue one 16KB W chunk (k-half 'half' of a 32KB polarity tile) via cp.async.
__device__ __forceinline__ void issue_wchunk(const __half* __restrict__ wsrc,
                                             int half, uint32_t bufaddr, int tid) {
    const char* src = (const char*)wsrc + half * 128;
    #pragma unroll
    for (int l = 0; l < 4; l++) {
        int i = tid + l * 256;
        int n = i >> 3, j = i & 7;
        cp_async16(bufaddr + (uint32_t)i * 16, src + n * 256 + j * 16);
    }
    CP_COMMIT();
}

// Compute 4 global ksteps (ks = half*4 + ksl) from one chunk buffer:
// acc += A @ Wchunk (single fp16 product).
__device__ __forceinline__ void gemm_chunk(uint32_t aT, uint32_t wbuf, int half,
                                           float acc[2][4][4], int r0, int c0, int lane) {
    const int l7 = lane & 7;
    const int am8 = ((lane >> 3) & 1) << 3;
    const int akh = lane >> 4;
    const int bm8 = ((lane >> 4) & 1) << 3;
    const int bpar = (lane >> 3) & 1;
    uint32_t arow[2], brow[2];
    int arow7[2], brow7[2];
    #pragma unroll
    for (int mt = 0; mt < 2; mt++) {
        int r = r0 + mt * 16 + am8 + l7;
        arow[mt] = (uint32_t)(r * 256); arow7[mt] = r & 7;
    }
    #pragma unroll
    for (int n2 = 0; n2 < 2; n2++) {
        int r = c0 + n2 * 16 + bm8 + l7;
        brow[n2] = (uint32_t)(r * 128); brow7[n2] = r & 7;
    }
    #pragma unroll
    for (int ksl = 0; ksl < 4; ksl++) {
        int ks = half * 4 + ksl;
        uint32_t Af[2][4], Bf[2][4];
        #pragma unroll
        for (int mt = 0; mt < 2; mt++) {
            uint32_t g = (uint32_t)(((2 * ks + akh) ^ arow7[mt]) << 4);
            ldsm4(Af[mt], aT + arow[mt] + g);
        }
        #pragma unroll
        for (int n2 = 0; n2 < 2; n2++) {
            uint32_t g = (uint32_t)(((2 * ksl + bpar) ^ brow7[n2]) << 4);
            ldsm4(Bf[n2], wbuf + brow[n2] + g);
        }
        #pragma unroll
        for (int n2 = 0; n2 < 2; n2++)
            #pragma unroll
            for (int j = 0; j < 2; j++) {
                int nt = n2 * 2 + j;
                uint32_t b0 = Bf[n2][j * 2], b1 = Bf[n2][j * 2 + 1];
                #pragma unroll
                for (int mt = 0; mt < 2; mt++)
                    mma16816(acc[mt][nt], Af[mt], b0, b1);
            }
    }
}

// Full GEMM: acc = A @ (Wh + Wl), W streamed as 4x16KB chunks, double-buffered.
__device__ __forceinline__ void gemm_stream(int widx, uint32_t aT, uint32_t wB,
                                            float acc[2][4][4],
                                            int r0, int c0, int lane, int tid) {
    #pragma unroll
    for (int mt = 0; mt < 2; mt++)
        #pragma unroll
        for (int nt = 0; nt < 4; nt++)
            #pragma unroll
            for (int i = 0; i < 4; i++) acc[mt][nt][i] = 0.f;

    const __half* wHi = g_wt[widx][0];
    const __half* wLo = g_wt[widx][1];

    __syncthreads();                 // prior users of Wbuf / A writers done
    issue_wchunk(wHi, 0, wB, tid);
    issue_wchunk(wHi, 1, wB + 16384, tid);

    #pragma unroll
    for (int c = 0; c < 4; c++) {
        if (c < 3) CP_WAIT(1); else CP_WAIT(0);
        __syncthreads();             // chunk c visible to all warps
        gemm_chunk(aT, wB + (uint32_t)((c & 1) * 16384), c & 1, acc, r0, c0, lane);
        if (c < 2) {
            __syncthreads();         // all warps done with buffer c
            issue_wchunk(wLo, c & 1, wB + (uint32_t)((c & 1) * 16384), tid);
        }
    }
}

// bias + RoPE + elu+1 on accumulators (warp covers cols c0..c0+31 = 2 heads).
__device__ __forceinline__ void rope_elu_acc(float acc[2][4][4],
                                             const float* bias_s, int c0, int tg,
                                             const float sn[4][2], const float cs[4][2]) {
    #pragma unroll
    for (int mt = 0; mt < 2; mt++)
        #pragma unroll
        for (int t = 0; t < 2; t++)
            #pragma unroll
            for (int i = 0; i < 4; i++) {
                int ridx = mt * 2 + (i >> 1);
                int jj = i & 1;
                float x1 = acc[mt][2 * t][i]     + bias_s[c0 + t * 16 + tg * 2 + jj];
                float x2 = acc[mt][2 * t + 1][i] + bias_s[c0 + t * 16 + 8 + tg * 2 + jj];
                float s = sn[ridx][jj], c = cs[ridx][jj];
                float y1 = x1 * c - x2 * s;
                float y2 = x1 * s + x2 * c;
                acc[mt][2 * t][i]     = y1 > 0.f ? y1 + 1.f : __expf(y1);
                acc[mt][2 * t + 1][i] = y2 > 0.f ? y2 + 1.f : __expf(y2);
            }
}

// Store accumulators to fp32 smem tile [rows][128], float4-block XOR swizzle.
__device__ __forceinline__ void acc_store(float* dst, const float acc[2][4][4],
                                          const float* bias_s, bool add_bias,
                                          int r0, int c0, int qid, int tg) {
    #pragma unroll
    for (int mt = 0; mt < 2; mt++)
        #pragma unroll
        for (int nt = 0; nt < 4; nt++)
            #pragma unroll
            for (int h2 = 0; h2 < 2; h2++) {
                int row = r0 + mt * 16 + h2 * 8 + qid;
                int col = c0 + nt * 8 + tg * 2;
                float v0 = acc[mt][nt][h2 * 2];
                float v1 = acc[mt][nt][h2 * 2 + 1];
                if (add_bias) { v0 += bias_s[col]; v1 += bias_s[col + 1]; }
                float* p = dst + row * 128 + (((col >> 2) ^ (row & 7)) << 2) + (col & 3);
                p[0] = v0; p[1] = v1;
            }
}

__device__ __forceinline__ void make_rope_tables(int t0, int r0, int qid, int tg,
                                                 float sn[4][2], float cs[4][2]) {
    const float invf[8] = {1.0f, 0.31622776601683794f, 0.1f, 0.03162277660168379f,
                           0.01f, 0.0031622776601683794f, 0.001f, 0.00031622776601683794f};
    #pragma unroll
    for (int ridx = 0; ridx < 4; ridx++) {
        int mt = ridx >> 1, half = ridx & 1;
        float tf = (float)(t0 + r0 + mt * 16 + half * 8 + qid);
        #pragma unroll
        for (int jj = 0; jj < 2; jj++)
            sincosf(tf * invf[tg * 2 + jj], &sn[ridx][jj], &cs[ridx][jj]);
    }
}

// ---------------------------------------------------------------------------
// Kernel 0: pre-convert weights to fp16 hi/lo. grid = 4 (0=Wk,1=Wq,2=Wv,3=Wo).
// ---------------------------------------------------------------------------
extern "C" __global__ void __launch_bounds__(256)
la_wconv(const float* __restrict__ Wq, const float* __restrict__ Wk,
         const float* __restrict__ Wv, const float* __restrict__ Wo)
{
    const float* W = (blockIdx.x == 0) ? Wk : (blockIdx.x == 1) ? Wq
                   : (blockIdx.x == 2) ? Wv : Wo;
    __half* wh = g_wt[blockIdx.x][0];
    __half* wl = g_wt[blockIdx.x][1];
    const float4* Wp = (const float4*)W;
    for (int i = threadIdx.x; i < 4096; i += 256) {
        int k = i >> 5, n4 = i & 31;
        float4 w = Wp[i];
        float vv[4] = {w.x, w.y, w.z, w.w};
        #pragma unroll
        for (int u = 0; u < 4; u++) {
            int n = n4 * 4 + u;
            uint32_t e = (uint32_t)(n * 128 + ((((k >> 3) ^ (n & 7)) << 3) | (k & 7)));
            __half h = __float2half_rn(vv[u]);
            wh[e] = h;
            wl[e] = __float2half_rn(vv[u] - __half2float(h));
        }
    }
}

// ---------------------------------------------------------------------------
// Kernel 1: K, V GEMMs; k,v -> ctx/ksum partials.
// smem: A 16K | Wbuf 32K (2x16K) | k_s 32K | bias 1K  (~81K -> 2 blocks/SM)
// v_s aliases [0,32K) = A + Wbuf0 (both dead after V GEMM).
// ---------------------------------------------------------------------------
#define KV_WB    16384
#define KV_KS    49152
#define KV_BIAS  81920
#define KV_SMEM  82944

extern "C" __global__ void __launch_bounds__(256, 2)
la_kv(const float* __restrict__ x,
      const float* __restrict__ bk, const float* __restrict__ bv)
{
    extern __shared__ char sm[];
    char* A_t  = sm;
    float* k_s = (float*)(sm + KV_KS);
    float* v_s = (float*)sm;                // alias A+Wbuf0 (post-GEMM use only)
    float* bias_s = (float*)(sm + KV_BIAS); // [2][128]: k, v

    const int tid = threadIdx.x;
    const int lane = tid & 31;
    const int wid = tid >> 5;
    const int qid = lane >> 2, tg = lane & 3;
    const int r0 = (wid & 1) * 32;
    const int c0 = (wid >> 1) * 32;
    const int b  = blockIdx.y;
    const int t0 = blockIdx.x * TILE;

    const uint32_t aT = smem_u32(A_t);
    const uint32_t wB = smem_u32(sm + KV_WB);

    const float4* xp = (const float4*)(x + ((size_t)(b * NT + t0)) * ND);
    for (int i = tid; i < 2048; i += 256) {
        int row = i >> 5, k4 = i & 31;
        a_store4(A_t, row, k4, xp[i]);
    }
    if (tid < 128) {
        bias_s[tid]       = bk[tid];
        bias_s[128 + tid] = bv[tid];
    }
    float sn[4][2], cs[4][2];
    make_rope_tables(t0, r0, qid, tg, sn, cs);

    float acc[2][4][4];

    // ---- K GEMM ----
    gemm_stream(0, aT, wB, acc, r0, c0, lane, tid);
    rope_elu_acc(acc, bias_s, c0, tg, sn, cs);
    acc_store(k_s, acc, bias_s, false, r0, c0, qid, tg);

    // ---- V GEMM ----
    gemm_stream(2, aT, wB, acc, r0, c0, lane, tid);
    __syncthreads();                  // all reads done before v_s overwrite
    acc_store(v_s, acc, bias_s + 128, true, r0, c0, qid, tg);
    __syncthreads();

    // ---- ctx / ksum partials (no atomics) ----
    {
        int grp = tid >> 7, id = tid & 127;
        int h = id >> 4, d = id & 15;
        float accc[16];
        #pragma unroll
        for (int e = 0; e < 16; e++) accc[e] = 0.f;
        float ksacc = 0.f;
        int ts = grp * 32;
        int kcol = h * 16 + d;
        for (int t = ts; t < ts + 32; t++) {
            int sw = t & 7;
            float kv = k_s[t * 128 + ((((kcol >> 2) ^ sw) << 2) | (kcol & 3))];
            ksacc += kv;
            #pragma unroll
            for (int e4 = 0; e4 < 4; e4++) {
                float4 vv = *(const float4*)&v_s[t * 128 + (((h * 4 + e4) ^ sw) << 2)];
                accc[e4 * 4 + 0] = fmaf(kv, vv.x, accc[e4 * 4 + 0]);
                accc[e4 * 4 + 1] = fmaf(kv, vv.y, accc[e4 * 4 + 1]);
                accc[e4 * 4 + 2] = fmaf(kv, vv.z, accc[e4 * 4 + 2]);
                accc[e4 * 4 + 3] = fmaf(kv, vv.w, accc[e4 * 4 + 3]);
            }
        }
        size_t slot = ((size_t)(b * NTILES + blockIdx.x) * NGRP + grp);
        float* pp = g_part + slot * 2048 + h * 256 + d * 16;
        #pragma unroll
        for (int e = 0; e < 16; e++) pp[e] = accc[e];
        g_partk[slot * 128 + kcol] = ksacc;
    }
}

// ---------------------------------------------------------------------------
// Kernel 2: reduce partials. grid = NB*8 blocks, 256 threads.
// ---------------------------------------------------------------------------
extern "C" __global__ void __launch_bounds__(256)
la_red()
{
    int b = blockIdx.x >> 3, ch = blockIdx.x & 7;
    int e = ch * 256 + threadIdx.x;
    const float* pc = g_part + (size_t)b * NTILES * NGRP * 2048;
    float s = 0.f;
    for (int j = 0; j < NTILES * NGRP; j++) s += pc[(size_t)j * 2048 + e];
    g_ctx[b * 2048 + e] = s;
    if (ch == 0 && threadIdx.x < 128) {
        const float* pk = g_partk + (size_t)b * NTILES * NGRP * 128;
        float sk = 0.f;
        for (int j = 0; j < NTILES * NGRP; j++) sk += pk[(size_t)j * 128 + threadIdx.x];
        g_ksum[b * 128 + threadIdx.x] = sk;
    }
}

// ---------------------------------------------------------------------------
// Kernel 3: q = rope_elu(x@Wq+bq); attn = (q@ctx)*z; out = attn@Wo + bo.
// smem: A 16K | Wbuf 32K | q_s 32K | ctx 8.32K | ksum .5K | bias 1K (~90K)
// ---------------------------------------------------------------------------
#define QO_WB    16384
#define QO_QS    49152
#define QO_CTX   81920
#define QO_KSUM  90240
#define QO_BIAS  90752
#define QO_SMEM  91776
#define CTXP 260               // padded floats per head (bank shift 4)

extern "C" __global__ void __launch_bounds__(256, 2)
la_qout(const float* __restrict__ x,
        const float* __restrict__ bq, const float* __restrict__ bo,
        float* __restrict__ out)
{
    extern __shared__ char sm[];
    char* A_t = sm;
    float* q_s    = (float*)(sm + QO_QS);
    float* ctx_s  = (float*)(sm + QO_CTX);   // [8][CTXP]
    float* ksum_s = (float*)(sm + QO_KSUM);
    float* bias_s = (float*)(sm + QO_BIAS);  // [2][128]: q, o

    const int tid = threadIdx.x;
    const int lane = tid & 31;
    const int wid = tid >> 5;
    const int qid = lane >> 2, tg = lane & 3;
    const int r0 = (wid & 1) * 32;
    const int c0 = (wid >> 1) * 32;
    const int b  = blockIdx.y;
    const int t0 = blockIdx.x * TILE;

    const uint32_t aT = smem_u32(A_t);
    const uint32_t wB = smem_u32(sm + QO_WB);

    const float4* xp = (const float4*)(x + ((size_t)(b * NT + t0)) * ND);
    for (int i = tid; i < 2048; i += 256) {
        int row = i >> 5, k4 = i & 31;
        a_store4(A_t, row, k4, xp[i]);
    }
    for (int i = tid; i < 2048; i += 256)
        ctx_s[(i >> 8) * CTXP + (i & 255)] = g_ctx[b * 2048 + i];
    if (tid < 128) {
        ksum_s[tid] = g_ksum[b * 128 + tid];
        bias_s[tid] = bq[tid];
        bias_s[128 + tid] = bo[tid];
    }
    float sn[4][2], cs[4][2];
    make_rope_tables(t0, r0, qid, tg, sn, cs);

    float acc[2][4][4];

    // ---- Q GEMM ----
    gemm_stream(1, aT, wB, acc, r0, c0, lane, tid);
    rope_elu_acc(acc, bias_s, c0, tg, sn, cs);
    acc_store(q_s, acc, bias_s, false, r0, c0, qid, tg);
    __syncthreads();

    // ---- attention apply (float4, padded ctx -> conflict-free broadcasts) ----
    {
        int r = tid >> 2, hg = tid & 3, swr = r & 7;
        #pragma unroll
        for (int hh = 0; hh < 2; hh++) {
            int h = hg * 2 + hh;
            float qv[16];
            #pragma unroll
            for (int e4 = 0; e4 < 4; e4++) {
                int col = h * 16 + e4 * 4;
                float4 t = *(const float4*)&q_s[r * 128 + (((col >> 2) ^ swr) << 2)];
                qv[e4 * 4] = t.x; qv[e4 * 4 + 1] = t.y;
                qv[e4 * 4 + 2] = t.z; qv[e4 * 4 + 3] = t.w;
            }
            float zz = 1e-6f;
            #pragma unroll
            for (int d = 0; d < 16; d++) zz = fmaf(qv[d], ksum_s[h * 16 + d], zz);
            float4 oo[4];
            #pragma unroll
            for (int e4 = 0; e4 < 4; e4++) oo[e4] = make_float4(0.f, 0.f, 0.f, 0.f);
            #pragma unroll
            for (int d = 0; d < 16; d++) {
                const float4* cr = (const float4*)&ctx_s[h * CTXP + d * 16];
                float q = qv[d];
                #pragma unroll
                for (int e4 = 0; e4 < 4; e4++) {
                    float4 c = cr[e4];
                    oo[e4].x = fmaf(q, c.x, oo[e4].x);
                    oo[e4].y = fmaf(q, c.y, oo[e4].y);
                    oo[e4].z = fmaf(q, c.z, oo[e4].z);
                    oo[e4].w = fmaf(q, c.w, oo[e4].w);
                }
            }
            float zi = 1.f / zz;
            #pragma unroll
            for (int e4 = 0; e4 < 4; e4++) {
                int kcol = h * 16 + e4 * 4;
                a_store4(A_t, r, kcol >> 2,
                         make_float4(oo[e4].x * zi, oo[e4].y * zi,
                                     oo[e4].z * zi, oo[e4].w * zi));
            }
        }
    }

    // ---- O GEMM (entry sync inside gemm_stream covers attn A-tile writes) ----
    gemm_stream(3, aT, wB, acc, r0, c0, lane, tid);

    // direct global store with bias
    {
        float* op = out + ((size_t)(b * NT + t0)) * ND;
        #pragma unroll
        for (int mt = 0; mt < 2; mt++)
            #pragma unroll
            for (int nt = 0; nt < 4; nt++)
                #pragma unroll
                for (int h2 = 0; h2 < 2; h2++) {
                    int row = r0 + mt * 16 + h2 * 8 + qid;
                    int col = c0 + nt * 8 + tg * 2;
                    *(float2*)(op + (size_t)row * ND + col) =
                        make_float2(acc[mt][nt][h2 * 2] + bias_s[128 + col],
                                    acc[mt][nt][h2 * 2 + 1] + bias_s[128 + col + 1]);
                }
    }
}

// ---------------------------------------------------------------------------
extern "C" void kernel_launch(void* const* d_in, const int* in_sizes, int n_in,
                              void* d_out, int out_size)
{
    const float* x  = (const float*)d_in[0];
    const float* Wq = (const float*)d_in[1];
    const float* bq = (const float*)d_in[2];
    const float* Wk = (const float*)d_in[3];
    const float* bk = (const float*)d_in[4];
    const float* Wv = (const float*)d_in[5];
    const float* bv = (const float*)d_in[6];
    const float* Wo = (const float*)d_in[7];
    const float* bo = (const float*)d_in[8];
    float* out = (float*)d_out;

    cudaFuncSetAttribute(la_kv,   cudaFuncAttributeMaxDynamicSharedMemorySize, KV_SMEM);
    cudaFuncSetAttribute(la_qout, cudaFuncAttributeMaxDynamicSharedMemorySize, QO_SMEM);

    la_wconv<<<4, 256>>>(Wq, Wk, Wv, Wo);

    dim3 grid(NT / TILE, NB);
    la_kv<<<grid, 256, KV_SMEM>>>(x, bk, bv);
    la_red<<<NB * 8, 256>>>();
    la_qout<<<grid, 256, QO_SMEM>>>(x, bq, bo, out);
}

// round 10
// speedup vs baseline: 2.7041x; 1.2428x over previous
#include <cuda_runtime.h>
#include <cuda_fp16.h>
#include <math.h>
#include <stdint.h>

#define NB 8
#define NT 8192
#define ND 128
#define NH 8
#define TILE 64
#define NTILES 128             // NT / TILE
#define NGRP 2                 // partial groups per block

// ---------------- scratch (device globals; no allocs allowed) ---------------
static __device__ float g_part[NB * NTILES * NGRP * 2048];  // ctx partials
static __device__ float g_partk[NB * NTILES * NGRP * 128];  // ksum partials
static __device__ float g_ctx[NB * 2048];                   // [b][h][d][e]
static __device__ float g_ksum[NB * 128];                   // [b][h*16+d]
static __device__ __half g_wt[4][16384];                    // W tiles (fp16, swizzled)

// ---------------------------------------------------------------------------
__device__ __forceinline__ void mma16816(float c[4], const uint32_t a[4],
                                         uint32_t b0, uint32_t b1) {
    asm volatile(
        "mma.sync.aligned.m16n8k16.row.col.f32.f16.f16.f32 "
        "{%0,%1,%2,%3}, {%4,%5,%6,%7}, {%8,%9}, {%0,%1,%2,%3};"
        : "+f"(c[0]), "+f"(c[1]), "+f"(c[2]), "+f"(c[3])
        : "r"(a[0]), "r"(a[1]), "r"(a[2]), "r"(a[3]), "r"(b0), "r"(b1));
}
__device__ __forceinline__ void ldsm4(uint32_t r[4], uint32_t addr) {
    asm volatile("ldmatrix.sync.aligned.m8n8.x4.shared.b16 {%0,%1,%2,%3}, [%4];"
                 : "=r"(r[0]), "=r"(r[1]), "=r"(r[2]), "=r"(r[3]) : "r"(addr));
}
__device__ __forceinline__ uint32_t smem_u32(const void* p) {
    return (uint32_t)__cvta_generic_to_shared(p);
}
__device__ __forceinline__ void cp_async16(uint32_t dst, const void* src) {
    asm volatile("cp.async.cg.shared.global [%0], [%1], 16;" :: "r"(dst), "l"(src));
}
#define CP_COMMIT() asm volatile("cp.async.commit_group;" ::: "memory")
#define CP_WAIT(n)  asm volatile("cp.async.wait_group %0;" :: "n"(n) : "memory")

// A tile layout: [rows][128 fp16 = 256B], 16B-granule XOR swizzle:
// phys_byte = row*256 + (((k>>3) ^ (row&7))<<4) + (k&7)*2.
__device__ __forceinline__ void a_store4(char* a, int row, int k4, float4 v) {
    uint32_t off = (uint32_t)(row * 256 + ((((k4 >> 1) ^ (row & 7)) << 4) | ((k4 & 1) << 3)));
    *(__half2*)(a + off)     = __floats2half2_rn(v.x, v.y);
    *(__half2*)(a + off + 4) = __floats2half2_rn(v.z, v.w);
}

// Issue both 16KB W chunks of one W tile (two commit groups).
__device__ __forceinline__ void issue_w2(const __half* __restrict__ wsrc,
                                         uint32_t wB, int tid) {
    #pragma unroll
    for (int half = 0; half < 2; half++) {
        const char* src = (const char*)wsrc + half * 128;
        uint32_t buf = wB + (uint32_t)half * 16384;
        #pragma unroll
        for (int l = 0; l < 4; l++) {
            int i = tid + l * 256;
            int n = i >> 3, j = i & 7;
            cp_async16(buf + (uint32_t)i * 16, src + n * 256 + j * 16);
        }
        CP_COMMIT();
    }
}

// Compute 4 global ksteps (ks = half*4 + ksl): acc += A @ Wchunk.
__device__ __forceinline__ void gemm_chunk(uint32_t aT, uint32_t wbuf, int half,
                                           float acc[2][4][4], int r0, int c0, int lane) {
    const int l7 = lane & 7;
    const int am8 = ((lane >> 3) & 1) << 3;
    const int akh = lane >> 4;
    const int bm8 = ((lane >> 4) & 1) << 3;
    const int bpar = (lane >> 3) & 1;
    uint32_t arow[2], brow[2];
    int arow7[2], brow7[2];
    #pragma unroll
    for (int mt = 0; mt < 2; mt++) {
        int r = r0 + mt * 16 + am8 + l7;
        arow[mt] = (uint32_t)(r * 256); arow7[mt] = r & 7;
    }
    #pragma unroll
    for (int n2 = 0; n2 < 2; n2++) {
        int r = c0 + n2 * 16 + bm8 + l7;
        brow[n2] = (uint32_t)(r * 128); brow7[n2] = r & 7;
    }
    #pragma unroll
    for (int ksl = 0; ksl < 4; ksl++) {
        int ks = half * 4 + ksl;
        uint32_t Af[2][4], Bf[2][4];
        #pragma unroll
        for (int mt = 0; mt < 2; mt++) {
            uint32_t g = (uint32_t)(((2 * ks + akh) ^ arow7[mt]) << 4);
            ldsm4(Af[mt], aT + arow[mt] + g);
        }
        #pragma unroll
        for (int n2 = 0; n2 < 2; n2++) {
            uint32_t g = (uint32_t)(((2 * ksl + bpar) ^ brow7[n2]) << 4);
            ldsm4(Bf[n2], wbuf + brow[n2] + g);
        }
        #pragma unroll
        for (int n2 = 0; n2 < 2; n2++)
            #pragma unroll
            for (int j = 0; j < 2; j++) {
                int nt = n2 * 2 + j;
                uint32_t b0 = Bf[n2][j * 2], b1 = Bf[n2][j * 2 + 1];
                #pragma unroll
                for (int mt = 0; mt < 2; mt++)
                    mma16816(acc[mt][nt], Af[mt], b0, b1);
            }
    }
}

// Full GEMM from pre-issued chunks: waits chunk-by-chunk, computes.
__device__ __forceinline__ void gemm_go(uint32_t aT, uint32_t wB, float acc[2][4][4],
                                        int r0, int c0, int lane) {
    #pragma unroll
    for (int mt = 0; mt < 2; mt++)
        #pragma unroll
        for (int nt = 0; nt < 4; nt++)
            #pragma unroll
            for (int i = 0; i < 4; i++) acc[mt][nt][i] = 0.f;
    CP_WAIT(1);
    __syncthreads();
    gemm_chunk(aT, wB, 0, acc, r0, c0, lane);
    CP_WAIT(0);
    __syncthreads();
    gemm_chunk(aT, wB + 16384, 1, acc, r0, c0, lane);
}

// bias + RoPE + elu+1 on accumulators (warp covers cols c0..c0+31 = 2 heads).
__device__ __forceinline__ void rope_elu_acc(float acc[2][4][4],
                                             const float* bias_s, int c0, int tg,
                                             const float sn[4][2], const float cs[4][2]) {
    #pragma unroll
    for (int mt = 0; mt < 2; mt++)
        #pragma unroll
        for (int t = 0; t < 2; t++)
            #pragma unroll
            for (int i = 0; i < 4; i++) {
                int ridx = mt * 2 + (i >> 1);
                int jj = i & 1;
                float x1 = acc[mt][2 * t][i]     + bias_s[c0 + t * 16 + tg * 2 + jj];
                float x2 = acc[mt][2 * t + 1][i] + bias_s[c0 + t * 16 + 8 + tg * 2 + jj];
                float s = sn[ridx][jj], c = cs[ridx][jj];
                float y1 = x1 * c - x2 * s;
                float y2 = x1 * s + x2 * c;
                acc[mt][2 * t][i]     = y1 > 0.f ? y1 + 1.f : __expf(y1);
                acc[mt][2 * t + 1][i] = y2 > 0.f ? y2 + 1.f : __expf(y2);
            }
}

// Store accumulators to fp32 smem tile [rows][128], float4-block XOR swizzle.
__device__ __forceinline__ void acc_store(float* dst, const float acc[2][4][4],
                                          const float* bias_s, bool add_bias,
                                          int r0, int c0, int qid, int tg) {
    #pragma unroll
    for (int mt = 0; mt < 2; mt++)
        #pragma unroll
        for (int nt = 0; nt < 4; nt++)
            #pragma unroll
            for (int h2 = 0; h2 < 2; h2++) {
                int row = r0 + mt * 16 + h2 * 8 + qid;
                int col = c0 + nt * 8 + tg * 2;
                float v0 = acc[mt][nt][h2 * 2];
                float v1 = acc[mt][nt][h2 * 2 + 1];
                if (add_bias) { v0 += bias_s[col]; v1 += bias_s[col + 1]; }
                float* p = dst + row * 128 + (((col >> 2) ^ (row & 7)) << 2) + (col & 3);
                p[0] = v0; p[1] = v1;
            }
}

__device__ __forceinline__ void make_rope_tables(int t0, int r0, int qid, int tg,
                                                 float sn[4][2], float cs[4][2]) {
    const float invf[8] = {1.0f, 0.31622776601683794f, 0.1f, 0.03162277660168379f,
                           0.01f, 0.0031622776601683794f, 0.001f, 0.00031622776601683794f};
    #pragma unroll
    for (int ridx = 0; ridx < 4; ridx++) {
        int mt = ridx >> 1, half = ridx & 1;
        float tf = (float)(t0 + r0 + mt * 16 + half * 8 + qid);
        #pragma unroll
        for (int jj = 0; jj < 2; jj++)
            sincosf(tf * invf[tg * 2 + jj], &sn[ridx][jj], &cs[ridx][jj]);
    }
}

// ---------------------------------------------------------------------------
// Kernel 0: pre-convert weights to fp16. grid = 4 (0=Wk,1=Wq,2=Wv,3=Wo).
// ---------------------------------------------------------------------------
extern "C" __global__ void __launch_bounds__(256)
la_wconv(const float* __restrict__ Wq, const float* __restrict__ Wk,
         const float* __restrict__ Wv, const float* __restrict__ Wo)
{
    const float* W = (blockIdx.x == 0) ? Wk : (blockIdx.x == 1) ? Wq
                   : (blockIdx.x == 2) ? Wv : Wo;
    __half* wh = g_wt[blockIdx.x];
    const float4* Wp = (const float4*)W;
    for (int i = threadIdx.x; i < 4096; i += 256) {
        int k = i >> 5, n4 = i & 31;
        float4 w = Wp[i];
        float vv[4] = {w.x, w.y, w.z, w.w};
        #pragma unroll
        for (int u = 0; u < 4; u++) {
            int n = n4 * 4 + u;
            uint32_t e = (uint32_t)(n * 128 + ((((k >> 3) ^ (n & 7)) << 3) | (k & 7)));
            wh[e] = __float2half_rn(vv[u]);
        }
    }
}

// ---------------------------------------------------------------------------
// Kernel 1: K, V GEMMs; k,v -> ctx/ksum partials.
// smem: A 16K | Wbuf 32K (2x16K) | k_s 32K | bias 1K  (~81K -> 2 blocks/SM)
// v_s aliases [0,32K) = A + Wbuf chunk0 (both dead at v_s store time).
// ---------------------------------------------------------------------------
#define KV_WB    16384
#define KV_KS    49152
#define KV_BIAS  81920
#define KV_SMEM  82944

extern "C" __global__ void __launch_bounds__(256, 2)
la_kv(const float* __restrict__ x,
      const float* __restrict__ bk, const float* __restrict__ bv)
{
    extern __shared__ char sm[];
    char* A_t  = sm;
    float* k_s = (float*)(sm + KV_KS);
    float* v_s = (float*)sm;                // alias A+Wbuf0 (post-GEMM use only)
    float* bias_s = (float*)(sm + KV_BIAS); // [2][128]: k, v

    const int tid = threadIdx.x;
    const int lane = tid & 31;
    const int wid = tid >> 5;
    const int qid = lane >> 2, tg = lane & 3;
    const int r0 = (wid & 1) * 32;
    const int c0 = (wid >> 1) * 32;
    const int b  = blockIdx.y;
    const int t0 = blockIdx.x * TILE;

    const uint32_t aT = smem_u32(A_t);
    const uint32_t wB = smem_u32(sm + KV_WB);

    issue_w2(g_wt[0], wB, tid);             // Wk in flight under x load

    const float4* xp = (const float4*)(x + ((size_t)(b * NT + t0)) * ND);
    for (int i = tid; i < 2048; i += 256) {
        int row = i >> 5, k4 = i & 31;
        a_store4(A_t, row, k4, xp[i]);
    }
    if (tid < 128) {
        bias_s[tid]       = bk[tid];
        bias_s[128 + tid] = bv[tid];
    }
    float sn[4][2], cs[4][2];
    make_rope_tables(t0, r0, qid, tg, sn, cs);

    float acc[2][4][4];

    // ---- K GEMM (first sync inside gemm_go also publishes A stores) ----
    gemm_go(aT, wB, acc, r0, c0, lane);
    __syncthreads();                        // all Wbuf reads done
    issue_w2(g_wt[2], wB, tid);             // Wv in flight under K epilogue
    rope_elu_acc(acc, bias_s, c0, tg, sn, cs);
    acc_store(k_s, acc, bias_s, false, r0, c0, qid, tg);

    // ---- V GEMM ----
    gemm_go(aT, wB, acc, r0, c0, lane);
    __syncthreads();                        // A + Wbuf0 reads done
    acc_store(v_s, acc, bias_s + 128, true, r0, c0, qid, tg);
    __syncthreads();

    // ---- ctx / ksum partials (no atomics) ----
    {
        int grp = tid >> 7, id = tid & 127;
        int h = id >> 4, d = id & 15;
        float accc[16];
        #pragma unroll
        for (int e = 0; e < 16; e++) accc[e] = 0.f;
        float ksacc = 0.f;
        int ts = grp * 32;
        int kcol = h * 16 + d;
        for (int t = ts; t < ts + 32; t++) {
            int sw = t & 7;
            float kv = k_s[t * 128 + ((((kcol >> 2) ^ sw) << 2) | (kcol & 3))];
            ksacc += kv;
            #pragma unroll
            for (int e4 = 0; e4 < 4; e4++) {
                float4 vv = *(const float4*)&v_s[t * 128 + (((h * 4 + e4) ^ sw) << 2)];
                accc[e4 * 4 + 0] = fmaf(kv, vv.x, accc[e4 * 4 + 0]);
                accc[e4 * 4 + 1] = fmaf(kv, vv.y, accc[e4 * 4 + 1]);
                accc[e4 * 4 + 2] = fmaf(kv, vv.z, accc[e4 * 4 + 2]);
                accc[e4 * 4 + 3] = fmaf(kv, vv.w, accc[e4 * 4 + 3]);
            }
        }
        size_t slot = ((size_t)(b * NTILES + blockIdx.x) * NGRP + grp);
        float* pp = g_part + slot * 2048 + h * 256 + d * 16;
        #pragma unroll
        for (int e = 0; e < 16; e++) pp[e] = accc[e];
        g_partk[slot * 128 + kcol] = ksacc;
    }
}

// ---------------------------------------------------------------------------
// Kernel 2: reduce partials. grid = NB*8 blocks, 256 threads.
// ---------------------------------------------------------------------------
extern "C" __global__ void __launch_bounds__(256)
la_red()
{
    int b = blockIdx.x >> 3, ch = blockIdx.x & 7;
    int e = ch * 256 + threadIdx.x;
    const float* pc = g_part + (size_t)b * NTILES * NGRP * 2048;
    float s = 0.f;
    for (int j = 0; j < NTILES * NGRP; j++) s += pc[(size_t)j * 2048 + e];
    g_ctx[b * 2048 + e] = s;
    if (ch == 0 && threadIdx.x < 128) {
        const float* pk = g_partk + (size_t)b * NTILES * NGRP * 128;
        float sk = 0.f;
        for (int j = 0; j < NTILES * NGRP; j++) sk += pk[(size_t)j * 128 + threadIdx.x];
        g_ksum[b * 128 + threadIdx.x] = sk;
    }
}

// ---------------------------------------------------------------------------
// Kernel 3: q = rope_elu(x@Wq+bq); attn = (q@ctx)*z; out = attn@Wo + bo.
// smem: A 16K | Wbuf 32K | q_s 32K | ctx 8.32K | ksum .5K | bias 1K (~90K)
// ---------------------------------------------------------------------------
#define QO_WB    16384
#define QO_QS    49152
#define QO_CTX   81920
#define QO_KSUM  90240
#define QO_BIAS  90752
#define QO_SMEM  91776
#define CTXP 260               // padded floats per head (bank shift 4)

extern "C" __global__ void __launch_bounds__(256, 2)
la_qout(const float* __restrict__ x,
        const float* __restrict__ bq, const float* __restrict__ bo,
        float* __restrict__ out)
{
    extern __shared__ char sm[];
    char* A_t = sm;
    float* q_s    = (float*)(sm + QO_QS);
    float* ctx_s  = (float*)(sm + QO_CTX);   // [8][CTXP]
    float* ksum_s = (float*)(sm + QO_KSUM);
    float* bias_s = (float*)(sm + QO_BIAS);  // [2][128]: q, o

    const int tid = threadIdx.x;
    const int lane = tid & 31;
    const int wid = tid >> 5;
    const int qid = lane >> 2, tg = lane & 3;
    const int r0 = (wid & 1) * 32;
    const int c0 = (wid >> 1) * 32;
    const int b  = blockIdx.y;
    const int t0 = blockIdx.x * TILE;

    const uint32_t aT = smem_u32(A_t);
    const uint32_t wB = smem_u32(sm + QO_WB);

    issue_w2(g_wt[1], wB, tid);             // Wq in flight under x/ctx load

    const float4* xp = (const float4*)(x + ((size_t)(b * NT + t0)) * ND);
    for (int i = tid; i < 2048; i += 256) {
        int row = i >> 5, k4 = i & 31;
        a_store4(A_t, row, k4, xp[i]);
    }
    for (int i = tid; i < 2048; i += 256)
        ctx_s[(i >> 8) * CTXP + (i & 255)] = g_ctx[b * 2048 + i];
    if (tid < 128) {
        ksum_s[tid] = g_ksum[b * 128 + tid];
        bias_s[tid] = bq[tid];
        bias_s[128 + tid] = bo[tid];
    }
    float sn[4][2], cs[4][2];
    make_rope_tables(t0, r0, qid, tg, sn, cs);

    float acc[2][4][4];

    // ---- Q GEMM ----
    gemm_go(aT, wB, acc, r0, c0, lane);
    __syncthreads();                        // all Wbuf reads done
    issue_w2(g_wt[3], wB, tid);             // Wo in flight under apply
    rope_elu_acc(acc, bias_s, c0, tg, sn, cs);
    acc_store(q_s, acc, bias_s, false, r0, c0, qid, tg);
    __syncthreads();                        // q_s visible to apply

    // ---- attention apply (float4, padded ctx -> conflict-free broadcasts) ----
    {
        int r = tid >> 2, hg = tid & 3, swr = r & 7;
        #pragma unroll
        for (int hh = 0; hh < 2; hh++) {
            int h = hg * 2 + hh;
            float qv[16];
            #pragma unroll
            for (int e4 = 0; e4 < 4; e4++) {
                int col = h * 16 + e4 * 4;
                float4 t = *(const float4*)&q_s[r * 128 + (((col >> 2) ^ swr) << 2)];
                qv[e4 * 4] = t.x; qv[e4 * 4 + 1] = t.y;
                qv[e4 * 4 + 2] = t.z; qv[e4 * 4 + 3] = t.w;
            }
            float zz = 1e-6f;
            #pragma unroll
            for (int d = 0; d < 16; d++) zz = fmaf(qv[d], ksum_s[h * 16 + d], zz);
            float4 oo[4];
            #pragma unroll
            for (int e4 = 0; e4 < 4; e4++) oo[e4] = make_float4(0.f, 0.f, 0.f, 0.f);
            #pragma unroll
            for (int d = 0; d < 16; d++) {
                const float4* cr = (const float4*)&ctx_s[h * CTXP + d * 16];
                float q = qv[d];
                #pragma unroll
                for (int e4 = 0; e4 < 4; e4++) {
                    float4 c = cr[e4];
                    oo[e4].x = fmaf(q, c.x, oo[e4].x);
                    oo[e4].y = fmaf(q, c.y, oo[e4].y);
                    oo[e4].z = fmaf(q, c.z, oo[e4].z);
                    oo[e4].w = fmaf(q, c.w, oo[e4].w);
                }
            }
            float zi = 1.f / zz;
            #pragma unroll
            for (int e4 = 0; e4 < 4; e4++) {
                int kcol = h * 16 + e4 * 4;
                a_store4(A_t, r, kcol >> 2,
                         make_float4(oo[e4].x * zi, oo[e4].y * zi,
                                     oo[e4].z * zi, oo[e4].w * zi));
            }
        }
    }

    // ---- O GEMM (first sync inside gemm_go publishes attn A-tile writes) ----
    gemm_go(aT, wB, acc, r0, c0, lane);

    // direct global store with bias
    {
        float* op = out + ((size_t)(b * NT + t0)) * ND;
        #pragma unroll
        for (int mt = 0; mt < 2; mt++)
            #pragma unroll
            for (int nt = 0; nt < 4; nt++)
                #pragma unroll
                for (int h2 = 0; h2 < 2; h2++) {
                    int row = r0 + mt * 16 + h2 * 8 + qid;
                    int col = c0 + nt * 8 + tg * 2;
                    *(float2*)(op + (size_t)row * ND + col) =
                        make_float2(acc[mt][nt][h2 * 2] + bias_s[128 + col],
                                    acc[mt][nt][h2 * 2 + 1] + bias_s[128 + col + 1]);
                }
    }
}

// ---------------------------------------------------------------------------
extern "C" void kernel_launch(void* const* d_in, const int* in_sizes, int n_in,
                              void* d_out, int out_size)
{
    const float* x  = (const float*)d_in[0];
    const float* Wq = (const float*)d_in[1];
    const float* bq = (const float*)d_in[2];
    const float* Wk = (const float*)d_in[3];
    const float* bk = (const float*)d_in[4];
    const float* Wv = (const float*)d_in[5];
    const float* bv = (const float*)d_in[6];
    const float* Wo = (const float*)d_in[7];
    const float* bo = (const float*)d_in[8];
    float* out = (float*)d_out;

    cudaFuncSetAttribute(la_kv,   cudaFuncAttributeMaxDynamicSharedMemorySize, KV_SMEM);
    cudaFuncSetAttribute(la_qout, cudaFuncAttributeMaxDynamicSharedMemorySize, QO_SMEM);

    la_wconv<<<4, 256>>>(Wq, Wk, Wv, Wo);

    dim3 grid(NT / TILE, NB);
    la_kv<<<grid, 256, KV_SMEM>>>(x, bk, bv);
    la_red<<<NB * 8, 256>>>();
    la_qout<<<grid, 256, QO_SMEM>>>(x, bq, bo, out);
}

// round 11
// speedup vs baseline: 3.1724x; 1.1732x over previous
#include <cuda_runtime.h>
#include <cuda_fp16.h>
#include <math.h>
#include <stdint.h>

#define NB 8
#define NT 8192
#define ND 128
#define NH 8
#define TILE 64
#define NTILES 128             // NT / TILE
#define NGRP 2                 // partial groups per block

// ---------------- scratch (device globals; no allocs allowed) ---------------
static __device__ float g_part[NB * NTILES * NGRP * 2048];  // ctx partials
static __device__ float g_partk[NB * NTILES * NGRP * 128];  // ksum partials
static __device__ float g_ctx[NB * 2048];                   // [b][h][d][e]
static __device__ float g_ksum[NB * 128];                   // [b][h*16+d]
static __device__ __half g_wt[4][16384];                    // W tiles (fp16, swizzled)
static __device__ float g_rope[NT * 16];                    // [t][j*2]=sin, [j*2+1]=cos

// ---------------------------------------------------------------------------
__device__ __forceinline__ void mma16816(float c[4], const uint32_t a[4],
                                         uint32_t b0, uint32_t b1) {
    asm volatile(
        "mma.sync.aligned.m16n8k16.row.col.f32.f16.f16.f32 "
        "{%0,%1,%2,%3}, {%4,%5,%6,%7}, {%8,%9}, {%0,%1,%2,%3};"
        : "+f"(c[0]), "+f"(c[1]), "+f"(c[2]), "+f"(c[3])
        : "r"(a[0]), "r"(a[1]), "r"(a[2]), "r"(a[3]), "r"(b0), "r"(b1));
}
__device__ __forceinline__ void ldsm4(uint32_t r[4], uint32_t addr) {
    asm volatile("ldmatrix.sync.aligned.m8n8.x4.shared.b16 {%0,%1,%2,%3}, [%4];"
                 : "=r"(r[0]), "=r"(r[1]), "=r"(r[2]), "=r"(r[3]) : "r"(addr));
}
__device__ __forceinline__ uint32_t smem_u32(const void* p) {
    return (uint32_t)__cvta_generic_to_shared(p);
}
__device__ __forceinline__ void cp_async16(uint32_t dst, const void* src) {
    asm volatile("cp.async.cg.shared.global [%0], [%1], 16;" :: "r"(dst), "l"(src));
}
#define CP_COMMIT() asm volatile("cp.async.commit_group;" ::: "memory")
#define CP_WAIT(n)  asm volatile("cp.async.wait_group %0;" :: "n"(n) : "memory")

// A tile layout: [rows][128 fp16 = 256B], 16B-granule XOR swizzle:
// phys_byte = row*256 + (((k>>3) ^ (row&7))<<4) + (k&7)*2.
__device__ __forceinline__ void a_store4(char* a, int row, int k4, float4 v) {
    uint32_t off = (uint32_t)(row * 256 + ((((k4 >> 1) ^ (row & 7)) << 4) | ((k4 & 1) << 3)));
    *(__half2*)(a + off)     = __floats2half2_rn(v.x, v.y);
    *(__half2*)(a + off + 4) = __floats2half2_rn(v.z, v.w);
}

// Issue both 16KB W chunks of one W tile (two commit groups).
__device__ __forceinline__ void issue_w2(const __half* __restrict__ wsrc,
                                         uint32_t wB, int tid) {
    #pragma unroll
    for (int half = 0; half < 2; half++) {
        const char* src = (const char*)wsrc + half * 128;
        uint32_t buf = wB + (uint32_t)half * 16384;
        #pragma unroll
        for (int l = 0; l < 4; l++) {
            int i = tid + l * 256;
            int n = i >> 3, j = i & 7;
            cp_async16(buf + (uint32_t)i * 16, src + n * 256 + j * 16);
        }
        CP_COMMIT();
    }
}

// Compute 4 global ksteps (ks = half*4 + ksl): acc += A @ Wchunk.
__device__ __forceinline__ void gemm_chunk(uint32_t aT, uint32_t wbuf, int half,
                                           float acc[2][4][4], int r0, int c0, int lane) {
    const int l7 = lane & 7;
    const int am8 = ((lane >> 3) & 1) << 3;
    const int akh = lane >> 4;
    const int bm8 = ((lane >> 4) & 1) << 3;
    const int bpar = (lane >> 3) & 1;
    uint32_t arow[2], brow[2];
    int arow7[2], brow7[2];
    #pragma unroll
    for (int mt = 0; mt < 2; mt++) {
        int r = r0 + mt * 16 + am8 + l7;
        arow[mt] = (uint32_t)(r * 256); arow7[mt] = r & 7;
    }
    #pragma unroll
    for (int n2 = 0; n2 < 2; n2++) {
        int r = c0 + n2 * 16 + bm8 + l7;
        brow[n2] = (uint32_t)(r * 128); brow7[n2] = r & 7;
    }
    #pragma unroll
    for (int ksl = 0; ksl < 4; ksl++) {
        int ks = half * 4 + ksl;
        uint32_t Af[2][4], Bf[2][4];
        #pragma unroll
        for (int mt = 0; mt < 2; mt++) {
            uint32_t g = (uint32_t)(((2 * ks + akh) ^ arow7[mt]) << 4);
            ldsm4(Af[mt], aT + arow[mt] + g);
        }
        #pragma unroll
        for (int n2 = 0; n2 < 2; n2++) {
            uint32_t g = (uint32_t)(((2 * ksl + bpar) ^ brow7[n2]) << 4);
            ldsm4(Bf[n2], wbuf + brow[n2] + g);
        }
        #pragma unroll
        for (int n2 = 0; n2 < 2; n2++)
            #pragma unroll
            for (int j = 0; j < 2; j++) {
                int nt = n2 * 2 + j;
                uint32_t b0 = Bf[n2][j * 2], b1 = Bf[n2][j * 2 + 1];
                #pragma unroll
                for (int mt = 0; mt < 2; mt++)
                    mma16816(acc[mt][nt], Af[mt], b0, b1);
            }
    }
}

// Full GEMM from pre-issued chunks: waits chunk-by-chunk, computes.
__device__ __forceinline__ void gemm_go(uint32_t aT, uint32_t wB, float acc[2][4][4],
                                        int r0, int c0, int lane) {
    #pragma unroll
    for (int mt = 0; mt < 2; mt++)
        #pragma unroll
        for (int nt = 0; nt < 4; nt++)
            #pragma unroll
            for (int i = 0; i < 4; i++) acc[mt][nt][i] = 0.f;
    CP_WAIT(1);
    __syncthreads();
    gemm_chunk(aT, wB, 0, acc, r0, c0, lane);
    CP_WAIT(0);
    __syncthreads();
    gemm_chunk(aT, wB + 16384, 1, acc, r0, c0, lane);
}

// bias + RoPE + elu+1 on accumulators.
__device__ __forceinline__ void rope_elu_acc(float acc[2][4][4],
                                             const float* bias_s, int c0, int tg,
                                             const float sn[4][2], const float cs[4][2]) {
    #pragma unroll
    for (int mt = 0; mt < 2; mt++)
        #pragma unroll
        for (int t = 0; t < 2; t++)
            #pragma unroll
            for (int i = 0; i < 4; i++) {
                int ridx = mt * 2 + (i >> 1);
                int jj = i & 1;
                float x1 = acc[mt][2 * t][i]     + bias_s[c0 + t * 16 + tg * 2 + jj];
                float x2 = acc[mt][2 * t + 1][i] + bias_s[c0 + t * 16 + 8 + tg * 2 + jj];
                float s = sn[ridx][jj], c = cs[ridx][jj];
                float y1 = x1 * c - x2 * s;
                float y2 = x1 * s + x2 * c;
                acc[mt][2 * t][i]     = y1 > 0.f ? y1 + 1.f : __expf(y1);
                acc[mt][2 * t + 1][i] = y2 > 0.f ? y2 + 1.f : __expf(y2);
            }
}

// Store accumulators to fp32 smem tile [rows][128], float4-block XOR swizzle.
__device__ __forceinline__ void acc_store(float* dst, const float acc[2][4][4],
                                          const float* bias_s, bool add_bias,
                                          int r0, int c0, int qid, int tg) {
    #pragma unroll
    for (int mt = 0; mt < 2; mt++)
        #pragma unroll
        for (int nt = 0; nt < 4; nt++)
            #pragma unroll
            for (int h2 = 0; h2 < 2; h2++) {
                int row = r0 + mt * 16 + h2 * 8 + qid;
                int col = c0 + nt * 8 + tg * 2;
                float v0 = acc[mt][nt][h2 * 2];
                float v1 = acc[mt][nt][h2 * 2 + 1];
                if (add_bias) { v0 += bias_s[col]; v1 += bias_s[col + 1]; }
                float* p = dst + row * 128 + (((col >> 2) ^ (row & 7)) << 2) + (col & 3);
                p[0] = v0; p[1] = v1;
            }
}

// Store accumulators TRANSPOSED as fp16: dstT[feature][t], rows 128B,
// phys = f*128 + (((t>>3) ^ (f&7))<<4) + (t&7)*2.
__device__ __forceinline__ void acc_storeT(char* dstT, const float acc[2][4][4],
                                           const float* bias_s, bool add_bias,
                                           int r0, int c0, int qid, int tg) {
    #pragma unroll
    for (int mt = 0; mt < 2; mt++)
        #pragma unroll
        for (int nt = 0; nt < 4; nt++)
            #pragma unroll
            for (int i = 0; i < 4; i++) {
                int t = r0 + mt * 16 + (i >> 1) * 8 + qid;
                int f = c0 + nt * 8 + tg * 2 + (i & 1);
                float v = acc[mt][nt][i];
                if (add_bias) v += bias_s[f];
                uint32_t off = (uint32_t)(f * 128 + (((t >> 3) ^ (f & 7)) << 4) + (t & 7) * 2);
                *(__half*)(dstT + off) = __float2half_rn(v);
            }
}

// Load rope tables from global.
__device__ __forceinline__ void load_rope(int t0, int r0, int qid, int tg,
                                          float sn[4][2], float cs[4][2]) {
    #pragma unroll
    for (int ridx = 0; ridx < 4; ridx++) {
        int mt = ridx >> 1, half = ridx & 1;
        int t = t0 + r0 + mt * 16 + half * 8 + qid;
        float4 v = *(const float4*)&g_rope[t * 16 + tg * 4];
        sn[ridx][0] = v.x; cs[ridx][0] = v.y;
        sn[ridx][1] = v.z; cs[ridx][1] = v.w;
    }
}

// ---------------------------------------------------------------------------
// Kernel 0: setup. Blocks 0-3: W->fp16 swizzled; blocks 4-35: rope tables.
// ---------------------------------------------------------------------------
extern "C" __global__ void __launch_bounds__(256)
la_setup(const float* __restrict__ Wq, const float* __restrict__ Wk,
         const float* __restrict__ Wv, const float* __restrict__ Wo)
{
    if (blockIdx.x < 4) {
        const float* W = (blockIdx.x == 0) ? Wk : (blockIdx.x == 1) ? Wq
                       : (blockIdx.x == 2) ? Wv : Wo;
        __half* wh = g_wt[blockIdx.x];
        const float4* Wp = (const float4*)W;
        for (int i = threadIdx.x; i < 4096; i += 256) {
            int k = i >> 5, n4 = i & 31;
            float4 w = Wp[i];
            float vv[4] = {w.x, w.y, w.z, w.w};
            #pragma unroll
            for (int u = 0; u < 4; u++) {
                int n = n4 * 4 + u;
                uint32_t e = (uint32_t)(n * 128 + ((((k >> 3) ^ (n & 7)) << 3) | (k & 7)));
                wh[e] = __float2half_rn(vv[u]);
            }
        }
    } else {
        const float invf[8] = {1.0f, 0.31622776601683794f, 0.1f, 0.03162277660168379f,
                               0.01f, 0.0031622776601683794f, 0.001f, 0.00031622776601683794f};
        int t = (blockIdx.x - 4) * 256 + threadIdx.x;     // 32 blocks x 256 = 8192
        float tf = (float)t;
        #pragma unroll
        for (int j = 0; j < 8; j++) {
            float s, c;
            sincosf(tf * invf[j], &s, &c);
            g_rope[t * 16 + j * 2] = s;
            g_rope[t * 16 + j * 2 + 1] = c;
        }
    }
}

// ---------------------------------------------------------------------------
// Kernel 1: K, V GEMMs; transposed fp16 k/v tiles; ctx via diagonal MMA.
// smem: A 16K | Wbuf 32K | kT 16K | vT 16K | bias 1K   (~81K -> 2 blocks/SM)
// ---------------------------------------------------------------------------
#define KV_WB    16384
#define KV_KT    49152
#define KV_VT    65536
#define KV_BIAS  81920
#define KV_SMEM  82944

extern "C" __global__ void __launch_bounds__(256, 2)
la_kv(const float* __restrict__ x,
      const float* __restrict__ bk, const float* __restrict__ bv)
{
    extern __shared__ char sm[];
    char* A_t = sm;
    char* kT  = sm + KV_KT;
    char* vT  = sm + KV_VT;
    float* bias_s = (float*)(sm + KV_BIAS); // [2][128]: k, v

    const int tid = threadIdx.x;
    const int lane = tid & 31;
    const int wid = tid >> 5;
    const int qid = lane >> 2, tg = lane & 3;
    const int r0 = (wid & 1) * 32;
    const int c0 = (wid >> 1) * 32;
    const int b  = blockIdx.y;
    const int t0 = blockIdx.x * TILE;

    const uint32_t aT  = smem_u32(A_t);
    const uint32_t wB  = smem_u32(sm + KV_WB);
    const uint32_t kTa = smem_u32(kT);
    const uint32_t vTa = smem_u32(vT);

    issue_w2(g_wt[0], wB, tid);             // Wk in flight under x load

    const float4* xp = (const float4*)(x + ((size_t)(b * NT + t0)) * ND);
    for (int i = tid; i < 2048; i += 256) {
        int row = i >> 5, k4 = i & 31;
        a_store4(A_t, row, k4, xp[i]);
    }
    if (tid < 128) {
        bias_s[tid]       = bk[tid];
        bias_s[128 + tid] = bv[tid];
    }
    float sn[4][2], cs[4][2];
    load_rope(t0, r0, qid, tg, sn, cs);

    float acc[2][4][4];

    // ---- K GEMM (first sync inside gemm_go also publishes A stores) ----
    gemm_go(aT, wB, acc, r0, c0, lane);
    __syncthreads();                        // all Wbuf reads done
    issue_w2(g_wt[2], wB, tid);             // Wv in flight under K epilogue
    rope_elu_acc(acc, bias_s, c0, tg, sn, cs);

    // ksum partials via register shuffles (rows r0..r0+31 per warp)
    {
        float s[8];
        #pragma unroll
        for (int nt = 0; nt < 4; nt++)
            #pragma unroll
            for (int j = 0; j < 2; j++) {
                float v = 0.f;
                #pragma unroll
                for (int mt = 0; mt < 2; mt++)
                    #pragma unroll
                    for (int h2 = 0; h2 < 2; h2++)
                        v += acc[mt][nt][h2 * 2 + j];
                s[nt * 2 + j] = v;
            }
        #pragma unroll
        for (int off = 4; off <= 16; off <<= 1)
            #pragma unroll
            for (int u = 0; u < 8; u++)
                s[u] += __shfl_xor_sync(0xffffffffu, s[u], off);
        if (qid == 0) {
            size_t slot = ((size_t)(b * NTILES + blockIdx.x) * NGRP + (wid & 1));
            #pragma unroll
            for (int nt = 0; nt < 4; nt++)
                #pragma unroll
                for (int j = 0; j < 2; j++)
                    g_partk[slot * 128 + c0 + nt * 8 + tg * 2 + j] = s[nt * 2 + j];
        }
    }
    acc_storeT(kT, acc, bias_s, false, r0, c0, qid, tg);

    // ---- V GEMM (syncs inside publish kT stores too) ----
    gemm_go(aT, wB, acc, r0, c0, lane);
    acc_storeT(vT, acc, bias_s + 128, true, r0, c0, qid, tg);
    __syncthreads();                        // kT + vT visible

    // ---- ctx via diagonal MMA: warp = (tile = wid&3, tgrp = wid>>2) ----
    {
        const int tile = wid & 3, tgrp = wid >> 2;
        const int base = tile * 32;
        const int l7 = lane & 7;
        const int am8 = ((lane >> 3) & 1) << 3;
        const int akh = lane >> 4;
        const int bm8 = ((lane >> 4) & 1) << 3;
        const int bpar = (lane >> 3) & 1;
        float c2[2][4][4];
        #pragma unroll
        for (int mt = 0; mt < 2; mt++)
            #pragma unroll
            for (int nt = 0; nt < 4; nt++)
                #pragma unroll
                for (int i = 0; i < 4; i++) c2[mt][nt][i] = 0.f;

        #pragma unroll
        for (int ksl = 0; ksl < 2; ksl++) {
            uint32_t Af[2][4], Bf[2][4];
            #pragma unroll
            for (int mt = 0; mt < 2; mt++) {
                int r = base + mt * 16 + am8 + l7;
                uint32_t g = (uint32_t)(((tgrp * 4 + 2 * ksl + akh) ^ (r & 7)) << 4);
                ldsm4(Af[mt], kTa + (uint32_t)(r * 128) + g);
            }
            #pragma unroll
            for (int n2 = 0; n2 < 2; n2++) {
                int r = base + n2 * 16 + bm8 + l7;
                uint32_t g = (uint32_t)(((tgrp * 4 + 2 * ksl + bpar) ^ (r & 7)) << 4);
                ldsm4(Bf[n2], vTa + (uint32_t)(r * 128) + g);
            }
            #pragma unroll
            for (int n2 = 0; n2 < 2; n2++)
                #pragma unroll
                for (int j = 0; j < 2; j++) {
                    int nt = n2 * 2 + j;
                    uint32_t b0 = Bf[n2][j * 2], b1 = Bf[n2][j * 2 + 1];
                    #pragma unroll
                    for (int mt = 0; mt < 2; mt++)
                        mma16816(c2[mt][nt], Af[mt], b0, b1);
                }
        }

        // keep diagonal blocks: mt == nt>>1
        size_t slot = ((size_t)(b * NTILES + blockIdx.x) * NGRP + tgrp);
        float* pp = g_part + slot * 2048;
        #pragma unroll
        for (int mt = 0; mt < 2; mt++)
            #pragma unroll
            for (int n1 = 0; n1 < 2; n1++) {
                int nt = mt * 2 + n1;
                #pragma unroll
                for (int i = 0; i < 4; i++) {
                    int head = tile * 2 + mt;
                    int d = (i >> 1) * 8 + qid;
                    int e = n1 * 8 + tg * 2 + (i & 1);
                    pp[head * 256 + d * 16 + e] = c2[mt][nt][i];
                }
            }
    }
}

// ---------------------------------------------------------------------------
// Kernel 2: reduce partials. grid = NB*8 blocks, 256 threads.
// ---------------------------------------------------------------------------
extern "C" __global__ void __launch_bounds__(256)
la_red()
{
    int b = blockIdx.x >> 3, ch = blockIdx.x & 7;
    int e = ch * 256 + threadIdx.x;
    const float* pc = g_part + (size_t)b * NTILES * NGRP * 2048;
    float s = 0.f;
    for (int j = 0; j < NTILES * NGRP; j++) s += pc[(size_t)j * 2048 + e];
    g_ctx[b * 2048 + e] = s;
    if (ch == 0 && threadIdx.x < 128) {
        const float* pk = g_partk + (size_t)b * NTILES * NGRP * 128;
        float sk = 0.f;
        for (int j = 0; j < NTILES * NGRP; j++) sk += pk[(size_t)j * 128 + threadIdx.x];
        g_ksum[b * 128 + threadIdx.x] = sk;
    }
}

// ---------------------------------------------------------------------------
// Kernel 3: q = rope_elu(x@Wq+bq); attn = (q@ctx)*z; out = attn@Wo + bo.
// smem: A 16K | Wbuf 32K | q_s 32K | ctx 8.32K | ksum .5K | bias 1K (~90K)
// ---------------------------------------------------------------------------
#define QO_WB    16384
#define QO_QS    49152
#define QO_CTX   81920
#define QO_KSUM  90240
#define QO_BIAS  90752
#define QO_SMEM  91776
#define CTXP 260               // padded floats per head (bank shift 4)

extern "C" __global__ void __launch_bounds__(256, 2)
la_qout(const float* __restrict__ x,
        const float* __restrict__ bq, const float* __restrict__ bo,
        float* __restrict__ out)
{
    extern __shared__ char sm[];
    char* A_t = sm;
    float* q_s    = (float*)(sm + QO_QS);
    float* ctx_s  = (float*)(sm + QO_CTX);   // [8][CTXP]
    float* ksum_s = (float*)(sm + QO_KSUM);
    float* bias_s = (float*)(sm + QO_BIAS);  // [2][128]: q, o

    const int tid = threadIdx.x;
    const int lane = tid & 31;
    const int wid = tid >> 5;
    const int qid = lane >> 2, tg = lane & 3;
    const int r0 = (wid & 1) * 32;
    const int c0 = (wid >> 1) * 32;
    const int b  = blockIdx.y;
    const int t0 = blockIdx.x * TILE;

    const uint32_t aT = smem_u32(A_t);
    const uint32_t wB = smem_u32(sm + QO_WB);

    issue_w2(g_wt[1], wB, tid);             // Wq in flight under x/ctx load

    const float4* xp = (const float4*)(x + ((size_t)(b * NT + t0)) * ND);
    for (int i = tid; i < 2048; i += 256) {
        int row = i >> 5, k4 = i & 31;
        a_store4(A_t, row, k4, xp[i]);
    }
    for (int i = tid; i < 2048; i += 256)
        ctx_s[(i >> 8) * CTXP + (i & 255)] = g_ctx[b * 2048 + i];
    if (tid < 128) {
        ksum_s[tid] = g_ksum[b * 128 + tid];
        bias_s[tid] = bq[tid];
        bias_s[128 + tid] = bo[tid];
    }
    float sn[4][2], cs[4][2];
    load_rope(t0, r0, qid, tg, sn, cs);

    float acc[2][4][4];

    // ---- Q GEMM ----
    gemm_go(aT, wB, acc, r0, c0, lane);
    __syncthreads();                        // all Wbuf reads done
    issue_w2(g_wt[3], wB, tid);             // Wo in flight under apply
    rope_elu_acc(acc, bias_s, c0, tg, sn, cs);
    acc_store(q_s, acc, bias_s, false, r0, c0, qid, tg);
    __syncthreads();                        // q_s visible to apply

    // ---- attention apply (float4, padded ctx -> conflict-free broadcasts) ----
    {
        int r = tid >> 2, hg = tid & 3, swr = r & 7;
        #pragma unroll
        for (int hh = 0; hh < 2; hh++) {
            int h = hg * 2 + hh;
            float qv[16];
            #pragma unroll
            for (int e4 = 0; e4 < 4; e4++) {
                int col = h * 16 + e4 * 4;
                float4 t = *(const float4*)&q_s[r * 128 + (((col >> 2) ^ swr) << 2)];
                qv[e4 * 4] = t.x; qv[e4 * 4 + 1] = t.y;
                qv[e4 * 4 + 2] = t.z; qv[e4 * 4 + 3] = t.w;
            }
            float zz = 1e-6f;
            #pragma unroll
            for (int d = 0; d < 16; d++) zz = fmaf(qv[d], ksum_s[h * 16 + d], zz);
            float4 oo[4];
            #pragma unroll
            for (int e4 = 0; e4 < 4; e4++) oo[e4] = make_float4(0.f, 0.f, 0.f, 0.f);
            #pragma unroll
            for (int d = 0; d < 16; d++) {
                const float4* cr = (const float4*)&ctx_s[h * CTXP + d * 16];
                float q = qv[d];
                #pragma unroll
                for (int e4 = 0; e4 < 4; e4++) {
                    float4 c = cr[e4];
                    oo[e4].x = fmaf(q, c.x, oo[e4].x);
                    oo[e4].y = fmaf(q, c.y, oo[e4].y);
                    oo[e4].z = fmaf(q, c.z, oo[e4].z);
                    oo[e4].w = fmaf(q, c.w, oo[e4].w);
                }
            }
            float zi = 1.f / zz;
            #pragma unroll
            for (int e4 = 0; e4 < 4; e4++) {
                int kcol = h * 16 + e4 * 4;
                a_store4(A_t, r, kcol >> 2,
                         make_float4(oo[e4].x * zi, oo[e4].y * zi,
                                     oo[e4].z * zi, oo[e4].w * zi));
            }
        }
    }

    // ---- O GEMM (first sync inside gemm_go publishes attn A-tile writes) ----
    gemm_go(aT, wB, acc, r0, c0, lane);

    // direct global store with bias
    {
        float* op = out + ((size_t)(b * NT + t0)) * ND;
        #pragma unroll
        for (int mt = 0; mt < 2; mt++)
            #pragma unroll
            for (int nt = 0; nt < 4; nt++)
                #pragma unroll
                for (int h2 = 0; h2 < 2; h2++) {
                    int row = r0 + mt * 16 + h2 * 8 + qid;
                    int col = c0 + nt * 8 + tg * 2;
                    *(float2*)(op + (size_t)row * ND + col) =
                        make_float2(acc[mt][nt][h2 * 2] + bias_s[128 + col],
                                    acc[mt][nt][h2 * 2 + 1] + bias_s[128 + col + 1]);
                }
    }
}

// ---------------------------------------------------------------------------
extern "C" void kernel_launch(void* const* d_in, const int* in_sizes, int n_in,
                              void* d_out, int out_size)
{
    const float* x  = (const float*)d_in[0];
    const float* Wq = (const float*)d_in[1];
    const float* bq = (const float*)d_in[2];
    const float* Wk = (const float*)d_in[3];
    const float* bk = (const float*)d_in[4];
    const float* Wv = (const float*)d_in[5];
    const float* bv = (const float*)d_in[6];
    const float* Wo = (const float*)d_in[7];
    const float* bo = (const float*)d_in[8];
    float* out = (float*)d_out;

    cudaFuncSetAttribute(la_kv,   cudaFuncAttributeMaxDynamicSharedMemorySize, KV_SMEM);
    cudaFuncSetAttribute(la_qout, cudaFuncAttributeMaxDynamicSharedMemorySize, QO_SMEM);

    la_setup<<<36, 256>>>(Wq, Wk, Wv, Wo);

    dim3 grid(NT / TILE, NB);
    la_kv<<<grid, 256, KV_SMEM>>>(x, bk, bv);
    la_red<<<NB * 8, 256>>>();
    la_qout<<<grid, 256, QO_SMEM>>>(x, bq, bo, out);
}

// round 12
// speedup vs baseline: 3.4831x; 1.0980x over previous
#include <cuda_runtime.h>
#include <cuda_fp16.h>
#include <math.h>
#include <stdint.h>

#define NB 8
#define NT 8192
#define ND 128
#define NH 8
#define TILE 64
#define NTILES 128             // NT / TILE
#define NGRP 2                 // partial groups per block

// ---------------- scratch (device globals; no allocs allowed) ---------------
static __device__ float g_part[NB * NTILES * NGRP * 2048];  // ctx partials
static __device__ float g_partk[NB * NTILES * NGRP * 128];  // ksum partials
static __device__ float g_ctx[NB * 2048];                   // [b][h][d][e]
static __device__ float g_ksum[NB * 128];                   // [b][h*16+d]
static __device__ __half g_wt[4][16384];                    // W tiles (fp16, swizzled)
static __device__ float g_rope[NT * 16];                    // [t][j*2]=sin, [j*2+1]=cos

// ---------------------------------------------------------------------------
__device__ __forceinline__ void mma16816(float c[4], const uint32_t a[4],
                                         uint32_t b0, uint32_t b1) {
    asm volatile(
        "mma.sync.aligned.m16n8k16.row.col.f32.f16.f16.f32 "
        "{%0,%1,%2,%3}, {%4,%5,%6,%7}, {%8,%9}, {%0,%1,%2,%3};"
        : "+f"(c[0]), "+f"(c[1]), "+f"(c[2]), "+f"(c[3])
        : "r"(a[0]), "r"(a[1]), "r"(a[2]), "r"(a[3]), "r"(b0), "r"(b1));
}
__device__ __forceinline__ void ldsm4(uint32_t r[4], uint32_t addr) {
    asm volatile("ldmatrix.sync.aligned.m8n8.x4.shared.b16 {%0,%1,%2,%3}, [%4];"
                 : "=r"(r[0]), "=r"(r[1]), "=r"(r[2]), "=r"(r[3]) : "r"(addr));
}
__device__ __forceinline__ uint32_t smem_u32(const void* p) {
    return (uint32_t)__cvta_generic_to_shared(p);
}
__device__ __forceinline__ void cp_async16(uint32_t dst, const void* src) {
    asm volatile("cp.async.cg.shared.global [%0], [%1], 16;" :: "r"(dst), "l"(src));
}
#define CP_COMMIT() asm volatile("cp.async.commit_group;" ::: "memory")
#define CP_WAIT(n)  asm volatile("cp.async.wait_group %0;" :: "n"(n) : "memory")

// A tile layout: [rows][128 fp16 = 256B], 16B-granule XOR swizzle:
// phys_byte = row*256 + (((k>>3) ^ (row&7))<<4) + (k&7)*2.
__device__ __forceinline__ void a_store4(char* a, int row, int k4, float4 v) {
    uint32_t off = (uint32_t)(row * 256 + ((((k4 >> 1) ^ (row & 7)) << 4) | ((k4 & 1) << 3)));
    *(__half2*)(a + off)     = __floats2half2_rn(v.x, v.y);
    *(__half2*)(a + off + 4) = __floats2half2_rn(v.z, v.w);
}

// Issue both 16KB W chunks of one W tile (two commit groups).
__device__ __forceinline__ void issue_w2(const __half* __restrict__ wsrc,
                                         uint32_t wB, int tid) {
    #pragma unroll
    for (int half = 0; half < 2; half++) {
        const char* src = (const char*)wsrc + half * 128;
        uint32_t buf = wB + (uint32_t)half * 16384;
        #pragma unroll
        for (int l = 0; l < 4; l++) {
            int i = tid + l * 256;
            int n = i >> 3, j = i & 7;
            cp_async16(buf + (uint32_t)i * 16, src + n * 256 + j * 16);
        }
        CP_COMMIT();
    }
}

// Compute 4 global ksteps (ks = half*4 + ksl): acc += A @ Wchunk.
__device__ __forceinline__ void gemm_chunk(uint32_t aT, uint32_t wbuf, int half,
                                           float acc[2][4][4], int r0, int c0, int lane) {
    const int l7 = lane & 7;
    const int am8 = ((lane >> 3) & 1) << 3;
    const int akh = lane >> 4;
    const int bm8 = ((lane >> 4) & 1) << 3;
    const int bpar = (lane >> 3) & 1;
    uint32_t arow[2], brow[2];
    int arow7[2], brow7[2];
    #pragma unroll
    for (int mt = 0; mt < 2; mt++) {
        int r = r0 + mt * 16 + am8 + l7;
        arow[mt] = (uint32_t)(r * 256); arow7[mt] = r & 7;
    }
    #pragma unroll
    for (int n2 = 0; n2 < 2; n2++) {
        int r = c0 + n2 * 16 + bm8 + l7;
        brow[n2] = (uint32_t)(r * 128); brow7[n2] = r & 7;
    }
    #pragma unroll
    for (int ksl = 0; ksl < 4; ksl++) {
        int ks = half * 4 + ksl;
        uint32_t Af[2][4], Bf[2][4];
        #pragma unroll
        for (int mt = 0; mt < 2; mt++) {
            uint32_t g = (uint32_t)(((2 * ks + akh) ^ arow7[mt]) << 4);
            ldsm4(Af[mt], aT + arow[mt] + g);
        }
        #pragma unroll
        for (int n2 = 0; n2 < 2; n2++) {
            uint32_t g = (uint32_t)(((2 * ksl + bpar) ^ brow7[n2]) << 4);
            ldsm4(Bf[n2], wbuf + brow[n2] + g);
        }
        #pragma unroll
        for (int n2 = 0; n2 < 2; n2++)
            #pragma unroll
            for (int j = 0; j < 2; j++) {
                int nt = n2 * 2 + j;
                uint32_t b0 = Bf[n2][j * 2], b1 = Bf[n2][j * 2 + 1];
                #pragma unroll
                for (int mt = 0; mt < 2; mt++)
                    mma16816(acc[mt][nt], Af[mt], b0, b1);
            }
    }
}

// Full GEMM from pre-issued chunks: waits chunk-by-chunk, computes.
__device__ __forceinline__ void gemm_go(uint32_t aT, uint32_t wB, float acc[2][4][4],
                                        int r0, int c0, int lane) {
    #pragma unroll
    for (int mt = 0; mt < 2; mt++)
        #pragma unroll
        for (int nt = 0; nt < 4; nt++)
            #pragma unroll
            for (int i = 0; i < 4; i++) acc[mt][nt][i] = 0.f;
    CP_WAIT(1);
    __syncthreads();
    gemm_chunk(aT, wB, 0, acc, r0, c0, lane);
    CP_WAIT(0);
    __syncthreads();
    gemm_chunk(aT, wB + 16384, 1, acc, r0, c0, lane);
}

// bias + RoPE + elu+1 on accumulators.
__device__ __forceinline__ void rope_elu_acc(float acc[2][4][4],
                                             const float* bias_s, int c0, int tg,
                                             const float sn[4][2], const float cs[4][2]) {
    #pragma unroll
    for (int mt = 0; mt < 2; mt++)
        #pragma unroll
        for (int t = 0; t < 2; t++)
            #pragma unroll
            for (int i = 0; i < 4; i++) {
                int ridx = mt * 2 + (i >> 1);
                int jj = i & 1;
                float x1 = acc[mt][2 * t][i]     + bias_s[c0 + t * 16 + tg * 2 + jj];
                float x2 = acc[mt][2 * t + 1][i] + bias_s[c0 + t * 16 + 8 + tg * 2 + jj];
                float s = sn[ridx][jj], c = cs[ridx][jj];
                float y1 = x1 * c - x2 * s;
                float y2 = x1 * s + x2 * c;
                acc[mt][2 * t][i]     = y1 > 0.f ? y1 + 1.f : __expf(y1);
                acc[mt][2 * t + 1][i] = y2 > 0.f ? y2 + 1.f : __expf(y2);
            }
}

// Store accumulators as fp16 tile [rows][128 fp16], 16B-granule swizzle.
__device__ __forceinline__ void acc_storeH(char* dstH, const float acc[2][4][4],
                                           int r0, int c0, int qid, int tg) {
    #pragma unroll
    for (int mt = 0; mt < 2; mt++)
        #pragma unroll
        for (int nt = 0; nt < 4; nt++)
            #pragma unroll
            for (int h2 = 0; h2 < 2; h2++) {
                int row = r0 + mt * 16 + h2 * 8 + qid;
                int col = c0 + nt * 8 + tg * 2;
                uint32_t off = (uint32_t)(row * 256 +
                    (((col >> 3) ^ (row & 7)) << 4) + (col & 7) * 2);
                *(__half2*)(dstH + off) =
                    __floats2half2_rn(acc[mt][nt][h2 * 2], acc[mt][nt][h2 * 2 + 1]);
            }
}

// Store accumulators TRANSPOSED as fp16: dstT[feature][t], rows 128B,
// phys = f*128 + (((t>>3) ^ (f&7))<<4) + (t&7)*2.
__device__ __forceinline__ void acc_storeT(char* dstT, const float acc[2][4][4],
                                           const float* bias_s, bool add_bias,
                                           int r0, int c0, int qid, int tg) {
    #pragma unroll
    for (int mt = 0; mt < 2; mt++)
        #pragma unroll
        for (int nt = 0; nt < 4; nt++)
            #pragma unroll
            for (int i = 0; i < 4; i++) {
                int t = r0 + mt * 16 + (i >> 1) * 8 + qid;
                int f = c0 + nt * 8 + tg * 2 + (i & 1);
                float v = acc[mt][nt][i];
                if (add_bias) v += bias_s[f];
                uint32_t off = (uint32_t)(f * 128 + (((t >> 3) ^ (f & 7)) << 4) + (t & 7) * 2);
                *(__half*)(dstT + off) = __float2half_rn(v);
            }
}

// Load rope tables from global.
__device__ __forceinline__ void load_rope(int t0, int r0, int qid, int tg,
                                          float sn[4][2], float cs[4][2]) {
    #pragma unroll
    for (int ridx = 0; ridx < 4; ridx++) {
        int mt = ridx >> 1, half = ridx & 1;
        int t = t0 + r0 + mt * 16 + half * 8 + qid;
        float4 v = *(const float4*)&g_rope[t * 16 + tg * 4];
        sn[ridx][0] = v.x; cs[ridx][0] = v.y;
        sn[ridx][1] = v.z; cs[ridx][1] = v.w;
    }
}

// ---------------------------------------------------------------------------
// Kernel 0: setup. Blocks 0-3: W->fp16 swizzled; blocks 4-35: rope tables.
// ---------------------------------------------------------------------------
extern "C" __global__ void __launch_bounds__(256)
la_setup(const float* __restrict__ Wq, const float* __restrict__ Wk,
         const float* __restrict__ Wv, const float* __restrict__ Wo)
{
    if (blockIdx.x < 4) {
        const float* W = (blockIdx.x == 0) ? Wk : (blockIdx.x == 1) ? Wq
                       : (blockIdx.x == 2) ? Wv : Wo;
        __half* wh = g_wt[blockIdx.x];
        const float4* Wp = (const float4*)W;
        for (int i = threadIdx.x; i < 4096; i += 256) {
            int k = i >> 5, n4 = i & 31;
            float4 w = Wp[i];
            float vv[4] = {w.x, w.y, w.z, w.w};
            #pragma unroll
            for (int u = 0; u < 4; u++) {
                int n = n4 * 4 + u;
                uint32_t e = (uint32_t)(n * 128 + ((((k >> 3) ^ (n & 7)) << 3) | (k & 7)));
                wh[e] = __float2half_rn(vv[u]);
            }
        }
    } else {
        const float invf[8] = {1.0f, 0.31622776601683794f, 0.1f, 0.03162277660168379f,
                               0.01f, 0.0031622776601683794f, 0.001f, 0.00031622776601683794f};
        int t = (blockIdx.x - 4) * 256 + threadIdx.x;     // 32 blocks x 256 = 8192
        float tf = (float)t;
        #pragma unroll
        for (int j = 0; j < 8; j++) {
            float s, c;
            sincosf(tf * invf[j], &s, &c);
            g_rope[t * 16 + j * 2] = s;
            g_rope[t * 16 + j * 2 + 1] = c;
        }
    }
}

// ---------------------------------------------------------------------------
// Kernel 1: K, V GEMMs; transposed fp16 k/v tiles; ctx via diagonal MMA.
// smem: A/vT 16K | Wbuf 32K | kT 16K | bias 1K  (~65.5K -> 3 blocks/SM)
// ---------------------------------------------------------------------------
#define KV_WB    16384
#define KV_KT    49152
#define KV_BIAS  65536
#define KV_SMEM  66560

extern "C" __global__ void __launch_bounds__(256, 3)
la_kv(const float* __restrict__ x,
      const float* __restrict__ bk, const float* __restrict__ bv)
{
    extern __shared__ char sm[];
    char* A_t = sm;
    char* kT  = sm + KV_KT;
    char* vT  = sm;                         // alias A (A dead after V GEMM)
    float* bias_s = (float*)(sm + KV_BIAS); // [2][128]: k, v

    const int tid = threadIdx.x;
    const int lane = tid & 31;
    const int wid = tid >> 5;
    const int qid = lane >> 2, tg = lane & 3;
    const int r0 = (wid & 1) * 32;
    const int c0 = (wid >> 1) * 32;
    const int b  = blockIdx.y;
    const int t0 = blockIdx.x * TILE;

    const uint32_t aT  = smem_u32(A_t);
    const uint32_t wB  = smem_u32(sm + KV_WB);
    const uint32_t kTa = smem_u32(kT);
    const uint32_t vTa = aT;

    issue_w2(g_wt[0], wB, tid);             // Wk in flight under x load

    const float4* xp = (const float4*)(x + ((size_t)(b * NT + t0)) * ND);
    for (int i = tid; i < 2048; i += 256) {
        int row = i >> 5, k4 = i & 31;
        a_store4(A_t, row, k4, xp[i]);
    }
    if (tid < 128) {
        bias_s[tid]       = bk[tid];
        bias_s[128 + tid] = bv[tid];
    }
    float sn[4][2], cs[4][2];
    load_rope(t0, r0, qid, tg, sn, cs);

    float acc[2][4][4];

    // ---- K GEMM (first sync inside gemm_go also publishes A stores) ----
    gemm_go(aT, wB, acc, r0, c0, lane);
    __syncthreads();                        // all Wbuf reads done
    issue_w2(g_wt[2], wB, tid);             // Wv in flight under K epilogue
    rope_elu_acc(acc, bias_s, c0, tg, sn, cs);

    // ksum partials via register shuffles (rows r0..r0+31 per warp)
    {
        float s[8];
        #pragma unroll
        for (int nt = 0; nt < 4; nt++)
            #pragma unroll
            for (int j = 0; j < 2; j++) {
                float v = 0.f;
                #pragma unroll
                for (int mt = 0; mt < 2; mt++)
                    #pragma unroll
                    for (int h2 = 0; h2 < 2; h2++)
                        v += acc[mt][nt][h2 * 2 + j];
                s[nt * 2 + j] = v;
            }
        #pragma unroll
        for (int off = 4; off <= 16; off <<= 1)
            #pragma unroll
            for (int u = 0; u < 8; u++)
                s[u] += __shfl_xor_sync(0xffffffffu, s[u], off);
        if (qid == 0) {
            size_t slot = ((size_t)(b * NTILES + blockIdx.x) * NGRP + (wid & 1));
            #pragma unroll
            for (int nt = 0; nt < 4; nt++)
                #pragma unroll
                for (int j = 0; j < 2; j++)
                    g_partk[slot * 128 + c0 + nt * 8 + tg * 2 + j] = s[nt * 2 + j];
        }
    }
    acc_storeT(kT, acc, bias_s, false, r0, c0, qid, tg);

    // ---- V GEMM ----
    gemm_go(aT, wB, acc, r0, c0, lane);
    __syncthreads();                        // all A reads done before vT overwrite
    acc_storeT(vT, acc, bias_s + 128, true, r0, c0, qid, tg);
    __syncthreads();                        // kT + vT visible

    // ---- ctx via diagonal MMA: warp = (tile = wid&3, tgrp = wid>>2) ----
    {
        const int tile = wid & 3, tgrp = wid >> 2;
        const int base = tile * 32;
        const int l7 = lane & 7;
        const int am8 = ((lane >> 3) & 1) << 3;
        const int akh = lane >> 4;
        const int bm8 = ((lane >> 4) & 1) << 3;
        const int bpar = (lane >> 3) & 1;
        float c2[2][4][4];
        #pragma unroll
        for (int mt = 0; mt < 2; mt++)
            #pragma unroll
            for (int nt = 0; nt < 4; nt++)
                #pragma unroll
                for (int i = 0; i < 4; i++) c2[mt][nt][i] = 0.f;

        #pragma unroll
        for (int ksl = 0; ksl < 2; ksl++) {
            uint32_t Af[2][4], Bf[2][4];
            #pragma unroll
            for (int mt = 0; mt < 2; mt++) {
                int r = base + mt * 16 + am8 + l7;
                uint32_t g = (uint32_t)(((tgrp * 4 + 2 * ksl + akh) ^ (r & 7)) << 4);
                ldsm4(Af[mt], kTa + (uint32_t)(r * 128) + g);
            }
            #pragma unroll
            for (int n2 = 0; n2 < 2; n2++) {
                int r = base + n2 * 16 + bm8 + l7;
                uint32_t g = (uint32_t)(((tgrp * 4 + 2 * ksl + bpar) ^ (r & 7)) << 4);
                ldsm4(Bf[n2], vTa + (uint32_t)(r * 128) + g);
            }
            #pragma unroll
            for (int n2 = 0; n2 < 2; n2++)
                #pragma unroll
                for (int j = 0; j < 2; j++) {
                    int nt = n2 * 2 + j;
                    uint32_t b0 = Bf[n2][j * 2], b1 = Bf[n2][j * 2 + 1];
                    #pragma unroll
                    for (int mt = 0; mt < 2; mt++)
                        mma16816(c2[mt][nt], Af[mt], b0, b1);
                }
        }

        // keep diagonal blocks: mt == nt>>1
        size_t slot = ((size_t)(b * NTILES + blockIdx.x) * NGRP + tgrp);
        float* pp = g_part + slot * 2048;
        #pragma unroll
        for (int mt = 0; mt < 2; mt++)
            #pragma unroll
            for (int n1 = 0; n1 < 2; n1++) {
                int nt = mt * 2 + n1;
                #pragma unroll
                for (int i = 0; i < 4; i++) {
                    int head = tile * 2 + mt;
                    int d = (i >> 1) * 8 + qid;
                    int e = n1 * 8 + tg * 2 + (i & 1);
                    pp[head * 256 + d * 16 + e] = c2[mt][nt][i];
                }
            }
    }
}

// ---------------------------------------------------------------------------
// Kernel 2: reduce partials. grid = NB*8 blocks, 256 threads.
// ---------------------------------------------------------------------------
extern "C" __global__ void __launch_bounds__(256)
la_red()
{
    int b = blockIdx.x >> 3, ch = blockIdx.x & 7;
    int e = ch * 256 + threadIdx.x;
    const float* pc = g_part + (size_t)b * NTILES * NGRP * 2048;
    float s = 0.f;
    for (int j = 0; j < NTILES * NGRP; j++) s += pc[(size_t)j * 2048 + e];
    g_ctx[b * 2048 + e] = s;
    if (ch == 0 && threadIdx.x < 128) {
        const float* pk = g_partk + (size_t)b * NTILES * NGRP * 128;
        float sk = 0.f;
        for (int j = 0; j < NTILES * NGRP; j++) sk += pk[(size_t)j * 128 + threadIdx.x];
        g_ksum[b * 128 + threadIdx.x] = sk;
    }
}

// ---------------------------------------------------------------------------
// Kernel 3: q = rope_elu(x@Wq+bq); attn = (q@ctx)*z; out = attn@Wo + bo.
// smem: A 16K | Wbuf 32K | qH 16K | ctx 8.3K | ksum .5K | bias 1K (~73.6K)
// ---------------------------------------------------------------------------
#define QO_WB    16384
#define QO_QH    49152
#define QO_CTX   65536
#define QO_KSUM  73856
#define QO_BIAS  74368
#define QO_SMEM  75392
#define CTXP 260               // padded floats per head (bank shift 4)

extern "C" __global__ void __launch_bounds__(256, 3)
la_qout(const float* __restrict__ x,
        const float* __restrict__ bq, const float* __restrict__ bo,
        float* __restrict__ out)
{
    extern __shared__ char sm[];
    char* A_t = sm;
    char* qH  = sm + QO_QH;                  // fp16 q staging [64][128]
    float* ctx_s  = (float*)(sm + QO_CTX);   // [8][CTXP]
    float* ksum_s = (float*)(sm + QO_KSUM);
    float* bias_s = (float*)(sm + QO_BIAS);  // [2][128]: q, o

    const int tid = threadIdx.x;
    const int lane = tid & 31;
    const int wid = tid >> 5;
    const int qid = lane >> 2, tg = lane & 3;
    const int r0 = (wid & 1) * 32;
    const int c0 = (wid >> 1) * 32;
    const int b  = blockIdx.y;
    const int t0 = blockIdx.x * TILE;

    const uint32_t aT = smem_u32(A_t);
    const uint32_t wB = smem_u32(sm + QO_WB);

    issue_w2(g_wt[1], wB, tid);             // Wq in flight under x/ctx load

    const float4* xp = (const float4*)(x + ((size_t)(b * NT + t0)) * ND);
    for (int i = tid; i < 2048; i += 256) {
        int row = i >> 5, k4 = i & 31;
        a_store4(A_t, row, k4, xp[i]);
    }
    for (int i = tid; i < 2048; i += 256)
        ctx_s[(i >> 8) * CTXP + (i & 255)] = g_ctx[b * 2048 + i];
    if (tid < 128) {
        ksum_s[tid] = g_ksum[b * 128 + tid];
        bias_s[tid] = bq[tid];
        bias_s[128 + tid] = bo[tid];
    }
    float sn[4][2], cs[4][2];
    load_rope(t0, r0, qid, tg, sn, cs);

    float acc[2][4][4];

    // ---- Q GEMM ----
    gemm_go(aT, wB, acc, r0, c0, lane);
    __syncthreads();                        // all Wbuf reads done
    issue_w2(g_wt[3], wB, tid);             // Wo in flight under apply
    rope_elu_acc(acc, bias_s, c0, tg, sn, cs);
    acc_storeH(qH, acc, r0, c0, qid, tg);
    __syncthreads();                        // qH visible to apply

    // ---- attention apply (fp16 q, fp32 ctx/z math) ----
    {
        int r = tid >> 2, hg = tid & 3, swr = r & 7;
        #pragma unroll
        for (int hh = 0; hh < 2; hh++) {
            int h = hg * 2 + hh;
            float qv[16];
            #pragma unroll
            for (int u = 0; u < 2; u++) {
                uint4 raw = *(const uint4*)(qH + r * 256 + (((2 * h + u) ^ swr) << 4));
                const __half2* hp = (const __half2*)&raw;
                #pragma unroll
                for (int p = 0; p < 4; p++) {
                    float2 f = __half22float2(hp[p]);
                    qv[u * 8 + p * 2] = f.x;
                    qv[u * 8 + p * 2 + 1] = f.y;
                }
            }
            float zz = 1e-6f;
            #pragma unroll
            for (int d = 0; d < 16; d++) zz = fmaf(qv[d], ksum_s[h * 16 + d], zz);
            float4 oo[4];
            #pragma unroll
            for (int e4 = 0; e4 < 4; e4++) oo[e4] = make_float4(0.f, 0.f, 0.f, 0.f);
            #pragma unroll
            for (int d = 0; d < 16; d++) {
                const float4* cr = (const float4*)&ctx_s[h * CTXP + d * 16];
                float q = qv[d];
                #pragma unroll
                for (int e4 = 0; e4 < 4; e4++) {
                    float4 c = cr[e4];
                    oo[e4].x = fmaf(q, c.x, oo[e4].x);
                    oo[e4].y = fmaf(q, c.y, oo[e4].y);
                    oo[e4].z = fmaf(q, c.z, oo[e4].z);
                    oo[e4].w = fmaf(q, c.w, oo[e4].w);
                }
            }
            float zi = 1.f / zz;
            #pragma unroll
            for (int e4 = 0; e4 < 4; e4++) {
                int kcol = h * 16 + e4 * 4;
                a_store4(A_t, r, kcol >> 2,
                         make_float4(oo[e4].x * zi, oo[e4].y * zi,
                                     oo[e4].z * zi, oo[e4].w * zi));
            }
        }
    }

    // ---- O GEMM (first sync inside gemm_go publishes attn A-tile writes) ----
    gemm_go(aT, wB, acc, r0, c0, lane);

    // direct global store with bias
    {
        float* op = out + ((size_t)(b * NT + t0)) * ND;
        #pragma unroll
        for (int mt = 0; mt < 2; mt++)
            #pragma unroll
            for (int nt = 0; nt < 4; nt++)
                #pragma unroll
                for (int h2 = 0; h2 < 2; h2++) {
                    int row = r0 + mt * 16 + h2 * 8 + qid;
                    int col = c0 + nt * 8 + tg * 2;
                    *(float2*)(op + (size_t)row * ND + col) =
                        make_float2(acc[mt][nt][h2 * 2] + bias_s[128 + col],
                                    acc[mt][nt][h2 * 2 + 1] + bias_s[128 + col + 1]);
                }
    }
}

// ---------------------------------------------------------------------------
extern "C" void kernel_launch(void* const* d_in, const int* in_sizes, int n_in,
                              void* d_out, int out_size)
{
    const float* x  = (const float*)d_in[0];
    const float* Wq = (const float*)d_in[1];
    const float* bq = (const float*)d_in[2];
    const float* Wk = (const float*)d_in[3];
    const float* bk = (const float*)d_in[4];
    const float* Wv = (const float*)d_in[5];
    const float* bv = (const float*)d_in[6];
    const float* Wo = (const float*)d_in[7];
    const float* bo = (const float*)d_in[8];
    float* out = (float*)d_out;

    cudaFuncSetAttribute(la_kv,   cudaFuncAttributeMaxDynamicSharedMemorySize, KV_SMEM);
    cudaFuncSetAttribute(la_qout, cudaFuncAttributeMaxDynamicSharedMemorySize, QO_SMEM);

    la_setup<<<36, 256>>>(Wq, Wk, Wv, Wo);

    dim3 grid(NT / TILE, NB);
    la_kv<<<grid, 256, KV_SMEM>>>(x, bk, bv);
    la_red<<<NB * 8, 256>>>();
    la_qout<<<grid, 256, QO_SMEM>>>(x, bq, bo, out);
}

// round 13
// speedup vs baseline: 3.9636x; 1.1379x over previous
#include <cuda_runtime.h>
#include <cuda_fp16.h>
#include <math.h>
#include <stdint.h>

#define NB 8
#define NT 8192
#define ND 128
#define NH 8
#define TILE 64
#define NTILES 128             // NT / TILE
#define NGRP 2                 // partial groups per block

// ---------------- scratch (device globals; no allocs allowed) ---------------
static __device__ float g_part[NB * NTILES * NGRP * 2048];  // ctx partials
static __device__ float g_partk[NB * NTILES * NGRP * 128];  // ksum partials
static __device__ float g_ctx[NB * 2048];                   // [b][h][d][e]
static __device__ float g_ksum[NB * 128];                   // [b][h*16+d]
static __device__ __half g_wt[4][16384];                    // W tiles (fp16, swizzled)
static __device__ float g_rope[NT * 16];                    // [t][j*2]=sin, [j*2+1]=cos

// ---------------------------------------------------------------------------
__device__ __forceinline__ void mma16816(float c[4], const uint32_t a[4],
                                         uint32_t b0, uint32_t b1) {
    asm volatile(
        "mma.sync.aligned.m16n8k16.row.col.f32.f16.f16.f32 "
        "{%0,%1,%2,%3}, {%4,%5,%6,%7}, {%8,%9}, {%0,%1,%2,%3};"
        : "+f"(c[0]), "+f"(c[1]), "+f"(c[2]), "+f"(c[3])
        : "r"(a[0]), "r"(a[1]), "r"(a[2]), "r"(a[3]), "r"(b0), "r"(b1));
}
__device__ __forceinline__ void ldsm4(uint32_t r[4], uint32_t addr) {
    asm volatile("ldmatrix.sync.aligned.m8n8.x4.shared.b16 {%0,%1,%2,%3}, [%4];"
                 : "=r"(r[0]), "=r"(r[1]), "=r"(r[2]), "=r"(r[3]) : "r"(addr));
}
__device__ __forceinline__ uint32_t smem_u32(const void* p) {
    return (uint32_t)__cvta_generic_to_shared(p);
}
__device__ __forceinline__ void cp_async16(uint32_t dst, const void* src) {
    asm volatile("cp.async.cg.shared.global [%0], [%1], 16;" :: "r"(dst), "l"(src));
}
#define CP_COMMIT() asm volatile("cp.async.commit_group;" ::: "memory")
#define CP_WAIT(n)  asm volatile("cp.async.wait_group %0;" :: "n"(n) : "memory")

// A tile layout: [rows][128 fp16 = 256B], 16B-granule XOR swizzle:
// phys_byte = row*256 + (((k>>3) ^ (row&7))<<4) + (k&7)*2.

// Stage one granule (8 consecutive k) of x: 2 float4 -> 8 fp16 (one 16B store).
__device__ __forceinline__ void x_store8(char* a, int row, int k8, float4 v0, float4 v1) {
    uint32_t off = (uint32_t)(row * 256 + ((k8 ^ (row & 7)) << 4));
    __half2 h[4];
    h[0] = __floats2half2_rn(v0.x, v0.y);
    h[1] = __floats2half2_rn(v0.z, v0.w);
    h[2] = __floats2half2_rn(v1.x, v1.y);
    h[3] = __floats2half2_rn(v1.z, v1.w);
    *(uint4*)(a + off) = *(const uint4*)h;
}
__device__ __forceinline__ void a_store4(char* a, int row, int k4, float4 v) {
    uint32_t off = (uint32_t)(row * 256 + ((((k4 >> 1) ^ (row & 7)) << 4) | ((k4 & 1) << 3)));
    *(__half2*)(a + off)     = __floats2half2_rn(v.x, v.y);
    *(__half2*)(a + off + 4) = __floats2half2_rn(v.z, v.w);
}

// Issue both 16KB W chunks of one W tile (two commit groups).
__device__ __forceinline__ void issue_w2(const __half* __restrict__ wsrc,
                                         uint32_t wB, int tid) {
    #pragma unroll
    for (int half = 0; half < 2; half++) {
        const char* src = (const char*)wsrc + half * 128;
        uint32_t buf = wB + (uint32_t)half * 16384;
        #pragma unroll
        for (int l = 0; l < 4; l++) {
            int i = tid + l * 256;
            int n = i >> 3, j = i & 7;
            cp_async16(buf + (uint32_t)i * 16, src + n * 256 + j * 16);
        }
        CP_COMMIT();
    }
}

// Compute 4 global ksteps (ks = half*4 + ksl): acc += A @ Wchunk.
__device__ __forceinline__ void gemm_chunk(uint32_t aT, uint32_t wbuf, int half,
                                           float acc[2][4][4], int r0, int c0, int lane) {
    const int l7 = lane & 7;
    const int am8 = ((lane >> 3) & 1) << 3;
    const int akh = lane >> 4;
    const int bm8 = ((lane >> 4) & 1) << 3;
    const int bpar = (lane >> 3) & 1;
    uint32_t arow[2], brow[2];
    int arow7[2], brow7[2];
    #pragma unroll
    for (int mt = 0; mt < 2; mt++) {
        int r = r0 + mt * 16 + am8 + l7;
        arow[mt] = (uint32_t)(r * 256); arow7[mt] = r & 7;
    }
    #pragma unroll
    for (int n2 = 0; n2 < 2; n2++) {
        int r = c0 + n2 * 16 + bm8 + l7;
        brow[n2] = (uint32_t)(r * 128); brow7[n2] = r & 7;
    }
    #pragma unroll
    for (int ksl = 0; ksl < 4; ksl++) {
        int ks = half * 4 + ksl;
        uint32_t Af[2][4], Bf[2][4];
        #pragma unroll
        for (int mt = 0; mt < 2; mt++) {
            uint32_t g = (uint32_t)(((2 * ks + akh) ^ arow7[mt]) << 4);
            ldsm4(Af[mt], aT + arow[mt] + g);
        }
        #pragma unroll
        for (int n2 = 0; n2 < 2; n2++) {
            uint32_t g = (uint32_t)(((2 * ksl + bpar) ^ brow7[n2]) << 4);
            ldsm4(Bf[n2], wbuf + brow[n2] + g);
        }
        #pragma unroll
        for (int n2 = 0; n2 < 2; n2++)
            #pragma unroll
            for (int j = 0; j < 2; j++) {
                int nt = n2 * 2 + j;
                uint32_t b0 = Bf[n2][j * 2], b1 = Bf[n2][j * 2 + 1];
                #pragma unroll
                for (int mt = 0; mt < 2; mt++)
                    mma16816(acc[mt][nt], Af[mt], b0, b1);
            }
    }
}

// Full GEMM from pre-issued chunks: waits chunk-by-chunk, computes.
__device__ __forceinline__ void gemm_go(uint32_t aT, uint32_t wB, float acc[2][4][4],
                                        int r0, int c0, int lane) {
    #pragma unroll
    for (int mt = 0; mt < 2; mt++)
        #pragma unroll
        for (int nt = 0; nt < 4; nt++)
            #pragma unroll
            for (int i = 0; i < 4; i++) acc[mt][nt][i] = 0.f;
    CP_WAIT(1);
    __syncthreads();
    gemm_chunk(aT, wB, 0, acc, r0, c0, lane);
    CP_WAIT(0);
    __syncthreads();
    gemm_chunk(aT, wB + 16384, 1, acc, r0, c0, lane);
}

// bias + RoPE + elu+1 on accumulators.
__device__ __forceinline__ void rope_elu_acc(float acc[2][4][4],
                                             const float* bias_s, int c0, int tg,
                                             const float sn[4][2], const float cs[4][2]) {
    #pragma unroll
    for (int mt = 0; mt < 2; mt++)
        #pragma unroll
        for (int t = 0; t < 2; t++)
            #pragma unroll
            for (int i = 0; i < 4; i++) {
                int ridx = mt * 2 + (i >> 1);
                int jj = i & 1;
                float x1 = acc[mt][2 * t][i]     + bias_s[c0 + t * 16 + tg * 2 + jj];
                float x2 = acc[mt][2 * t + 1][i] + bias_s[c0 + t * 16 + 8 + tg * 2 + jj];
                float s = sn[ridx][jj], c = cs[ridx][jj];
                float y1 = x1 * c - x2 * s;
                float y2 = x1 * s + x2 * c;
                acc[mt][2 * t][i]     = y1 > 0.f ? y1 + 1.f : __expf(y1);
                acc[mt][2 * t + 1][i] = y2 > 0.f ? y2 + 1.f : __expf(y2);
            }
}

// Store accumulators as fp16 tile [rows][128 fp16], 16B-granule swizzle.
__device__ __forceinline__ void acc_storeH(char* dstH, const float acc[2][4][4],
                                           int r0, int c0, int qid, int tg) {
    #pragma unroll
    for (int mt = 0; mt < 2; mt++)
        #pragma unroll
        for (int nt = 0; nt < 4; nt++)
            #pragma unroll
            for (int h2 = 0; h2 < 2; h2++) {
                int row = r0 + mt * 16 + h2 * 8 + qid;
                int col = c0 + nt * 8 + tg * 2;
                uint32_t off = (uint32_t)(row * 256 +
                    (((col >> 3) ^ (row & 7)) << 4) + (col & 7) * 2);
                *(__half2*)(dstH + off) =
                    __floats2half2_rn(acc[mt][nt][h2 * 2], acc[mt][nt][h2 * 2 + 1]);
            }
}

// Store accumulators TRANSPOSED as fp16: dstT[feature][t], rows 128B,
// phys = f*128 + (((t>>3) ^ (f&7))<<4) + (t&7)*2.
__device__ __forceinline__ void acc_storeT(char* dstT, const float acc[2][4][4],
                                           const float* bias_s, bool add_bias,
                                           int r0, int c0, int qid, int tg) {
    #pragma unroll
    for (int mt = 0; mt < 2; mt++)
        #pragma unroll
        for (int nt = 0; nt < 4; nt++)
            #pragma unroll
            for (int i = 0; i < 4; i++) {
                int t = r0 + mt * 16 + (i >> 1) * 8 + qid;
                int f = c0 + nt * 8 + tg * 2 + (i & 1);
                float v = acc[mt][nt][i];
                if (add_bias) v += bias_s[f];
                uint32_t off = (uint32_t)(f * 128 + (((t >> 3) ^ (f & 7)) << 4) + (t & 7) * 2);
                *(__half*)(dstT + off) = __float2half_rn(v);
            }
}

// Load rope tables from global.
__device__ __forceinline__ void load_rope(int t0, int r0, int qid, int tg,
                                          float sn[4][2], float cs[4][2]) {
    #pragma unroll
    for (int ridx = 0; ridx < 4; ridx++) {
        int mt = ridx >> 1, half = ridx & 1;
        int t = t0 + r0 + mt * 16 + half * 8 + qid;
        float4 v = *(const float4*)&g_rope[t * 16 + tg * 4];
        sn[ridx][0] = v.x; cs[ridx][0] = v.y;
        sn[ridx][1] = v.z; cs[ridx][1] = v.w;
    }
}

// ---------------------------------------------------------------------------
// Kernel 0: setup. Blocks 0-3: W->fp16 swizzled; blocks 4-35: rope tables.
// ---------------------------------------------------------------------------
extern "C" __global__ void __launch_bounds__(256)
la_setup(const float* __restrict__ Wq, const float* __restrict__ Wk,
         const float* __restrict__ Wv, const float* __restrict__ Wo)
{
    if (blockIdx.x < 4) {
        const float* W = (blockIdx.x == 0) ? Wk : (blockIdx.x == 1) ? Wq
                       : (blockIdx.x == 2) ? Wv : Wo;
        __half* wh = g_wt[blockIdx.x];
        const float4* Wp = (const float4*)W;
        for (int i = threadIdx.x; i < 4096; i += 256) {
            int k = i >> 5, n4 = i & 31;
            float4 w = Wp[i];
            float vv[4] = {w.x, w.y, w.z, w.w};
            #pragma unroll
            for (int u = 0; u < 4; u++) {
                int n = n4 * 4 + u;
                uint32_t e = (uint32_t)(n * 128 + ((((k >> 3) ^ (n & 7)) << 3) | (k & 7)));
                wh[e] = __float2half_rn(vv[u]);
            }
        }
    } else {
        const float invf[8] = {1.0f, 0.31622776601683794f, 0.1f, 0.03162277660168379f,
                               0.01f, 0.0031622776601683794f, 0.001f, 0.00031622776601683794f};
        int t = (blockIdx.x - 4) * 256 + threadIdx.x;     // 32 blocks x 256 = 8192
        float tf = (float)t;
        #pragma unroll
        for (int j = 0; j < 8; j++) {
            float s, c;
            sincosf(tf * invf[j], &s, &c);
            g_rope[t * 16 + j * 2] = s;
            g_rope[t * 16 + j * 2 + 1] = c;
        }
    }
}

// ---------------------------------------------------------------------------
// Kernel 1: K, V GEMMs; transposed fp16 k/v tiles; ctx via diagonal MMA.
// smem: A/vT 16K | Wbuf 32K | kT 16K | bias 1K  (~65.5K -> 3 blocks/SM)
// ---------------------------------------------------------------------------
#define KV_WB    16384
#define KV_KT    49152
#define KV_BIAS  65536
#define KV_SMEM  66560

extern "C" __global__ void __launch_bounds__(256, 3)
la_kv(const float* __restrict__ x,
      const float* __restrict__ bk, const float* __restrict__ bv)
{
    extern __shared__ char sm[];
    char* A_t = sm;
    char* kT  = sm + KV_KT;
    char* vT  = sm;                         // alias A (A dead after V GEMM)
    float* bias_s = (float*)(sm + KV_BIAS); // [2][128]: k, v

    const int tid = threadIdx.x;
    const int lane = tid & 31;
    const int wid = tid >> 5;
    const int qid = lane >> 2, tg = lane & 3;
    const int r0 = (wid & 1) * 32;
    const int c0 = (wid >> 1) * 32;
    const int b  = blockIdx.y;
    const int t0 = blockIdx.x * TILE;

    const uint32_t aT  = smem_u32(A_t);
    const uint32_t wB  = smem_u32(sm + KV_WB);
    const uint32_t kTa = smem_u32(kT);
    const uint32_t vTa = aT;

    issue_w2(g_wt[0], wB, tid);             // Wk in flight under x load

    const float4* xp = (const float4*)(x + ((size_t)(b * NT + t0)) * ND);
    for (int i = tid; i < 1024; i += 256) {
        int row = i >> 4, k8 = i & 15;
        x_store8(A_t, row, k8, xp[row * 32 + k8 * 2], xp[row * 32 + k8 * 2 + 1]);
    }
    if (tid < 128) {
        bias_s[tid]       = bk[tid];
        bias_s[128 + tid] = bv[tid];
    }
    float sn[4][2], cs[4][2];
    load_rope(t0, r0, qid, tg, sn, cs);

    float acc[2][4][4];

    // ---- K GEMM (first sync inside gemm_go also publishes A stores) ----
    gemm_go(aT, wB, acc, r0, c0, lane);
    __syncthreads();                        // all Wbuf reads done
    issue_w2(g_wt[2], wB, tid);             // Wv in flight under K epilogue
    rope_elu_acc(acc, bias_s, c0, tg, sn, cs);

    // ksum partials via register shuffles (rows r0..r0+31 per warp)
    {
        float s[8];
        #pragma unroll
        for (int nt = 0; nt < 4; nt++)
            #pragma unroll
            for (int j = 0; j < 2; j++) {
                float v = 0.f;
                #pragma unroll
                for (int mt = 0; mt < 2; mt++)
                    #pragma unroll
                    for (int h2 = 0; h2 < 2; h2++)
                        v += acc[mt][nt][h2 * 2 + j];
                s[nt * 2 + j] = v;
            }
        #pragma unroll
        for (int off = 4; off <= 16; off <<= 1)
            #pragma unroll
            for (int u = 0; u < 8; u++)
                s[u] += __shfl_xor_sync(0xffffffffu, s[u], off);
        if (qid == 0) {
            size_t slot = ((size_t)(b * NTILES + blockIdx.x) * NGRP + (wid & 1));
            #pragma unroll
            for (int nt = 0; nt < 4; nt++)
                #pragma unroll
                for (int j = 0; j < 2; j++)
                    g_partk[slot * 128 + c0 + nt * 8 + tg * 2 + j] = s[nt * 2 + j];
        }
    }
    acc_storeT(kT, acc, bias_s, false, r0, c0, qid, tg);

    // ---- V GEMM ----
    gemm_go(aT, wB, acc, r0, c0, lane);
    __syncthreads();                        // all A reads done before vT overwrite
    acc_storeT(vT, acc, bias_s + 128, true, r0, c0, qid, tg);
    __syncthreads();                        // kT + vT visible

    // ---- ctx via diagonal MMA: warp = (tile = wid&3, tgrp = wid>>2) ----
    {
        const int tile = wid & 3, tgrp = wid >> 2;
        const int base = tile * 32;
        const int l7 = lane & 7;
        const int am8 = ((lane >> 3) & 1) << 3;
        const int akh = lane >> 4;
        const int bm8 = ((lane >> 4) & 1) << 3;
        const int bpar = (lane >> 3) & 1;
        float c2[2][4][4];
        #pragma unroll
        for (int mt = 0; mt < 2; mt++)
            #pragma unroll
            for (int nt = 0; nt < 4; nt++)
                #pragma unroll
                for (int i = 0; i < 4; i++) c2[mt][nt][i] = 0.f;

        #pragma unroll
        for (int ksl = 0; ksl < 2; ksl++) {
            uint32_t Af[2][4], Bf[2][4];
            #pragma unroll
            for (int mt = 0; mt < 2; mt++) {
                int r = base + mt * 16 + am8 + l7;
                uint32_t g = (uint32_t)(((tgrp * 4 + 2 * ksl + akh) ^ (r & 7)) << 4);
                ldsm4(Af[mt], kTa + (uint32_t)(r * 128) + g);
            }
            #pragma unroll
            for (int n2 = 0; n2 < 2; n2++) {
                int r = base + n2 * 16 + bm8 + l7;
                uint32_t g = (uint32_t)(((tgrp * 4 + 2 * ksl + bpar) ^ (r & 7)) << 4);
                ldsm4(Bf[n2], vTa + (uint32_t)(r * 128) + g);
            }
            #pragma unroll
            for (int n2 = 0; n2 < 2; n2++)
                #pragma unroll
                for (int j = 0; j < 2; j++) {
                    int nt = n2 * 2 + j;
                    uint32_t b0 = Bf[n2][j * 2], b1 = Bf[n2][j * 2 + 1];
                    #pragma unroll
                    for (int mt = 0; mt < 2; mt++)
                        mma16816(c2[mt][nt], Af[mt], b0, b1);
                }
        }

        // keep diagonal blocks: mt == nt>>1
        size_t slot = ((size_t)(b * NTILES + blockIdx.x) * NGRP + tgrp);
        float* pp = g_part + slot * 2048;
        #pragma unroll
        for (int mt = 0; mt < 2; mt++)
            #pragma unroll
            for (int n1 = 0; n1 < 2; n1++) {
                int nt = mt * 2 + n1;
                #pragma unroll
                for (int i = 0; i < 4; i++) {
                    int head = tile * 2 + mt;
                    int d = (i >> 1) * 8 + qid;
                    int e = n1 * 8 + tg * 2 + (i & 1);
                    pp[head * 256 + d * 16 + e] = c2[mt][nt][i];
                }
            }
    }
}

// ---------------------------------------------------------------------------
// Kernel 2: reduce partials. grid = NB*8 blocks, 256 threads.
// ---------------------------------------------------------------------------
extern "C" __global__ void __launch_bounds__(256)
la_red()
{
    int b = blockIdx.x >> 3, ch = blockIdx.x & 7;
    int e = ch * 256 + threadIdx.x;
    const float* pc = g_part + (size_t)b * NTILES * NGRP * 2048;
    float s = 0.f;
    for (int j = 0; j < NTILES * NGRP; j++) s += pc[(size_t)j * 2048 + e];
    g_ctx[b * 2048 + e] = s;
    if (ch == 0 && threadIdx.x < 128) {
        const float* pk = g_partk + (size_t)b * NTILES * NGRP * 128;
        float sk = 0.f;
        for (int j = 0; j < NTILES * NGRP; j++) sk += pk[(size_t)j * 128 + threadIdx.x];
        g_ksum[b * 128 + threadIdx.x] = sk;
    }
}

// ---------------------------------------------------------------------------
// Kernel 3: q = rope_elu(x@Wq+bq); attn = (q@ctx)*z; out = attn@Wo + bo.
// smem: A 16K | Wbuf 32K | qH 16K | ctx 8.3K | ksum .5K | bias 1K (~73.6K)
// ---------------------------------------------------------------------------
#define QO_WB    16384
#define QO_QH    49152
#define QO_CTX   65536
#define QO_KSUM  73856
#define QO_BIAS  74368
#define QO_SMEM  75392
#define CTXP 260               // padded floats per head (bank shift 4)

extern "C" __global__ void __launch_bounds__(256, 3)
la_qout(const float* __restrict__ x,
        const float* __restrict__ bq, const float* __restrict__ bo,
        float* __restrict__ out)
{
    extern __shared__ char sm[];
    char* A_t = sm;
    char* qH  = sm + QO_QH;                  // fp16 q staging [64][128]
    float* ctx_s  = (float*)(sm + QO_CTX);   // [8][CTXP]
    float* ksum_s = (float*)(sm + QO_KSUM);
    float* bias_s = (float*)(sm + QO_BIAS);  // [2][128]: q, o

    const int tid = threadIdx.x;
    const int lane = tid & 31;
    const int wid = tid >> 5;
    const int qid = lane >> 2, tg = lane & 3;
    const int r0 = (wid & 1) * 32;
    const int c0 = (wid >> 1) * 32;
    const int b  = blockIdx.y;
    const int t0 = blockIdx.x * TILE;

    const uint32_t aT = smem_u32(A_t);
    const uint32_t wB = smem_u32(sm + QO_WB);

    issue_w2(g_wt[1], wB, tid);             // Wq in flight under x/ctx load

    const float4* xp = (const float4*)(x + ((size_t)(b * NT + t0)) * ND);
    for (int i = tid; i < 1024; i += 256) {
        int row = i >> 4, k8 = i & 15;
        x_store8(A_t, row, k8, xp[row * 32 + k8 * 2], xp[row * 32 + k8 * 2 + 1]);
    }
    for (int i = tid; i < 2048; i += 256)
        ctx_s[(i >> 8) * CTXP + (i & 255)] = g_ctx[b * 2048 + i];
    if (tid < 128) {
        ksum_s[tid] = g_ksum[b * 128 + tid];
        bias_s[tid] = bq[tid];
        bias_s[128 + tid] = bo[tid];
    }
    float sn[4][2], cs[4][2];
    load_rope(t0, r0, qid, tg, sn, cs);

    float acc[2][4][4];

    // ---- Q GEMM ----
    gemm_go(aT, wB, acc, r0, c0, lane);
    __syncthreads();                        // all Wbuf reads done
    issue_w2(g_wt[3], wB, tid);             // Wo in flight under apply
    rope_elu_acc(acc, bias_s, c0, tg, sn, cs);
    acc_storeH(qH, acc, r0, c0, qid, tg);
    __syncthreads();                        // qH visible to apply

    // ---- attention apply: warp-uniform head, thread = (h = tid>>5, row pair) ----
    {
        int h = tid >> 5;                   // warp-uniform -> ctx broadcasts
        int rp = tid & 31;
        #pragma unroll
        for (int rr = 0; rr < 2; rr++) {
            int r = rp * 2 + rr;
            int swr = r & 7;
            float qv[16];
            #pragma unroll
            for (int u = 0; u < 2; u++) {
                uint4 raw = *(const uint4*)(qH + r * 256 + (((2 * h + u) ^ swr) << 4));
                const __half2* hp = (const __half2*)&raw;
                #pragma unroll
                for (int p = 0; p < 4; p++) {
                    float2 f = __half22float2(hp[p]);
                    qv[u * 8 + p * 2] = f.x;
                    qv[u * 8 + p * 2 + 1] = f.y;
                }
            }
            float zz = 1e-6f;
            #pragma unroll
            for (int d = 0; d < 16; d++) zz = fmaf(qv[d], ksum_s[h * 16 + d], zz);
            float4 oo[4];
            #pragma unroll
            for (int e4 = 0; e4 < 4; e4++) oo[e4] = make_float4(0.f, 0.f, 0.f, 0.f);
            #pragma unroll
            for (int d = 0; d < 16; d++) {
                const float4* cr = (const float4*)&ctx_s[h * CTXP + d * 16];
                float q = qv[d];
                #pragma unroll
                for (int e4 = 0; e4 < 4; e4++) {
                    float4 c = cr[e4];
                    oo[e4].x = fmaf(q, c.x, oo[e4].x);
                    oo[e4].y = fmaf(q, c.y, oo[e4].y);
                    oo[e4].z = fmaf(q, c.z, oo[e4].z);
                    oo[e4].w = fmaf(q, c.w, oo[e4].w);
                }
            }
            float zi = 1.f / zz;
            #pragma unroll
            for (int e4 = 0; e4 < 4; e4++) {
                int kcol = h * 16 + e4 * 4;
                a_store4(A_t, r, kcol >> 2,
                         make_float4(oo[e4].x * zi, oo[e4].y * zi,
                                     oo[e4].z * zi, oo[e4].w * zi));
            }
        }
    }

    // ---- O GEMM (first sync inside gemm_go publishes attn A-tile writes) ----
    gemm_go(aT, wB, acc, r0, c0, lane);

    // direct global store with bias
    {
        float* op = out + ((size_t)(b * NT + t0)) * ND;
        #pragma unroll
        for (int mt = 0; mt < 2; mt++)
            #pragma unroll
            for (int nt = 0; nt < 4; nt++)
                #pragma unroll
                for (int h2 = 0; h2 < 2; h2++) {
                    int row = r0 + mt * 16 + h2 * 8 + qid;
                    int col = c0 + nt * 8 + tg * 2;
                    *(float2*)(op + (size_t)row * ND + col) =
                        make_float2(acc[mt][nt][h2 * 2] + bias_s[128 + col],
                                    acc[mt][nt][h2 * 2 + 1] + bias_s[128 + col + 1]);
                }
    }
}

// ---------------------------------------------------------------------------
extern "C" void kernel_launch(void* const* d_in, const int* in_sizes, int n_in,
                              void* d_out, int out_size)
{
    const float* x  = (const float*)d_in[0];
    const float* Wq = (const float*)d_in[1];
    const float* bq = (const float*)d_in[2];
    const float* Wk = (const float*)d_in[3];
    const float* bk = (const float*)d_in[4];
    const float* Wv = (const float*)d_in[5];
    const float* bv = (const float*)d_in[6];
    const float* Wo = (const float*)d_in[7];
    const float* bo = (const float*)d_in[8];
    float* out = (float*)d_out;

    cudaFuncSetAttribute(la_kv,   cudaFuncAttributeMaxDynamicSharedMemorySize, KV_SMEM);
    cudaFuncSetAttribute(la_qout, cudaFuncAttributeMaxDynamicSharedMemorySize, QO_SMEM);

    la_setup<<<36, 256>>>(Wq, Wk, Wv, Wo);

    dim3 grid(NT / TILE, NB);
    la_kv<<<grid, 256, KV_SMEM>>>(x, bk, bv);
    la_red<<<NB * 8, 256>>>();
    la_qout<<<grid, 256, QO_SMEM>>>(x, bq, bo, out);
}